// round 1
// baseline (speedup 1.0000x reference)
#include <cuda_runtime.h>
#include <cuda_bf16.h>
#include <math.h>

// ---------------------------------------------------------------------------
// Problem constants
// ---------------------------------------------------------------------------
#define BATCH 8
#define SEQ   512
#define DMODEL 512
#define NHEAD 8
#define DHEAD 64
#define NLAYER 4
#define DFF   2048
#define VOCAB 32000
#define MROWS (BATCH*SEQ)   // 4096

// ---------------------------------------------------------------------------
// Scratch (device globals; no allocation allowed)
// ---------------------------------------------------------------------------
__device__ __align__(16) float g_x  [MROWS*DMODEL];
__device__ __align__(16) float g_x2 [MROWS*DMODEL];
__device__ __align__(16) float g_q  [MROWS*DMODEL];
__device__ __align__(16) float g_k  [MROWS*DMODEL];
__device__ __align__(16) float g_v  [MROWS*DMODEL];
__device__ __align__(16) float g_ctx[MROWS*DMODEL];
__device__ __align__(16) float g_enc[MROWS*DMODEL];
__device__ __align__(16) float g_h  [MROWS*DFF];

// ---------------------------------------------------------------------------
// Embedding + sinusoidal positional encoding
// out[b,s,:] = emb[tok]*sqrt(D) + pe(s,:)
// ---------------------------------------------------------------------------
__global__ void embed_kernel(const int* __restrict__ tok,
                             const float* __restrict__ emb,
                             float* __restrict__ y) {
    int row = blockIdx.x;            // b*SEQ + s
    int s   = row % SEQ;
    int t   = tok[row];
    const float scale = 22.62741699796952f;       // sqrt(512)
    const float c0 = -9.210340371976184f / (float)DMODEL;  // -ln(10000)/D
    int tid = threadIdx.x;           // 128 threads, 4 elems each
    #pragma unroll
    for (int i = 0; i < 4; i++) {
        int d = tid + i*128;
        float e = (t == 0) ? 0.f : emb[(size_t)t*DMODEL + d];
        int half = d >> 1;
        float div = expf((float)(2*half) * c0);
        float ang = (float)s * div;
        float pe = (d & 1) ? cosf(ang) : sinf(ang);
        y[(size_t)row*DMODEL + d] = e*scale + pe;
    }
}

// ---------------------------------------------------------------------------
// LayerNorm over last dim (D=512). One block / row, 128 threads x 4 elems.
// ---------------------------------------------------------------------------
__global__ void ln_kernel(const float* __restrict__ x,
                          const float* __restrict__ g,
                          const float* __restrict__ b,
                          float* __restrict__ y) {
    int row = blockIdx.x;
    const float* xr = x + (size_t)row*DMODEL;
    int t = threadIdx.x;
    float v[4];
    float s = 0.f;
    #pragma unroll
    for (int i = 0; i < 4; i++) { v[i] = xr[t + i*128]; s += v[i]; }
    __shared__ float red[4];
    #pragma unroll
    for (int o = 16; o > 0; o >>= 1) s += __shfl_xor_sync(0xffffffffu, s, o);
    if ((t & 31) == 0) red[t >> 5] = s;
    __syncthreads();
    float mean = (red[0]+red[1]+red[2]+red[3]) * (1.f/(float)DMODEL);
    float vs = 0.f;
    #pragma unroll
    for (int i = 0; i < 4; i++) { float d = v[i]-mean; vs += d*d; }
    #pragma unroll
    for (int o = 16; o > 0; o >>= 1) vs += __shfl_xor_sync(0xffffffffu, vs, o);
    __syncthreads();
    if ((t & 31) == 0) red[t >> 5] = vs;
    __syncthreads();
    float var = (red[0]+red[1]+red[2]+red[3]) * (1.f/(float)DMODEL);
    float inv = rsqrtf(var + 1e-5f);
    #pragma unroll
    for (int i = 0; i < 4; i++) {
        int d = t + i*128;
        y[(size_t)row*DMODEL + d] = (v[i]-mean)*inv*g[d] + b[d];
    }
}

// ---------------------------------------------------------------------------
// SGEMM:  C[M,N] = A[M,K] * W[N,K]^T  (+bias) (+relu) (+residual)
// 128x128 tile, BK=16, 256 threads, 8x8 microtile. All dims divide tiles.
// ---------------------------------------------------------------------------
#define GBM 128
#define GBN 128
#define GBK 16
template<bool RELU, bool RES, bool BIAS>
__global__ __launch_bounds__(256)
void gemm_nt(const float* __restrict__ A, const float* __restrict__ W,
             const float* __restrict__ bias, const float* __restrict__ res,
             float* __restrict__ C, int M, int N, int K) {
    __shared__ float As[GBK][GBM];
    __shared__ float Ws[GBK][GBN];
    int t = threadIdx.x;
    int tx = t % 16, ty = t / 16;
    const float* Ab = A + (size_t)blockIdx.y*GBM*K;
    const float* Wb = W + (size_t)blockIdx.x*GBN*K;
    float acc[8][8] = {};
    for (int k0 = 0; k0 < K; k0 += GBK) {
        #pragma unroll
        for (int r = 0; r < 2; r++) {
            int idx = t + r*256;
            int ar = idx >> 2;
            int ac = (idx & 3) << 2;
            float4 av = *reinterpret_cast<const float4*>(Ab + (size_t)ar*K + k0 + ac);
            As[ac+0][ar]=av.x; As[ac+1][ar]=av.y; As[ac+2][ar]=av.z; As[ac+3][ar]=av.w;
            float4 wv = *reinterpret_cast<const float4*>(Wb + (size_t)ar*K + k0 + ac);
            Ws[ac+0][ar]=wv.x; Ws[ac+1][ar]=wv.y; Ws[ac+2][ar]=wv.z; Ws[ac+3][ar]=wv.w;
        }
        __syncthreads();
        #pragma unroll
        for (int k = 0; k < GBK; k++) {
            float a[8], b[8];
            #pragma unroll
            for (int i = 0; i < 8; i++) a[i] = As[k][ty*8+i];
            #pragma unroll
            for (int j = 0; j < 8; j++) b[j] = Ws[k][tx*8+j];
            #pragma unroll
            for (int i = 0; i < 8; i++)
                #pragma unroll
                for (int j = 0; j < 8; j++)
                    acc[i][j] = fmaf(a[i], b[j], acc[i][j]);
        }
        __syncthreads();
    }
    #pragma unroll
    for (int i = 0; i < 8; i++) {
        size_t m = (size_t)blockIdx.y*GBM + ty*8 + i;
        #pragma unroll
        for (int j = 0; j < 8; j++) {
            size_t n = (size_t)blockIdx.x*GBN + tx*8 + j;
            float c = acc[i][j];
            if (BIAS) c += bias[n];
            if (RELU) c = fmaxf(c, 0.f);
            if (RES)  c += res[m*N + n];
            C[m*N + n] = c;
        }
    }
}

static inline void launch_gemm(const float* A, const float* W, const float* bias,
                               const float* res, float* C, int M, int N, int K,
                               bool relu) {
    dim3 grid(N/GBN, M/GBM), block(256);
    if (res)        gemm_nt<false,true ,true ><<<grid,block>>>(A,W,bias,res,C,M,N,K);
    else if (relu)  gemm_nt<true ,false,true ><<<grid,block>>>(A,W,bias,nullptr,C,M,N,K);
    else if (bias)  gemm_nt<false,false,true ><<<grid,block>>>(A,W,bias,nullptr,C,M,N,K);
    else            gemm_nt<false,false,false><<<grid,block>>>(A,W,nullptr,nullptr,C,M,N,K);
}

// ---------------------------------------------------------------------------
// Fused attention: one block per (b, h, q).  Q/K/V in [b, s, h*64+d] layout.
// scores -> mask -> softmax -> ctx, all in-block. causal: k<=q; pad: mtok!=0
// ---------------------------------------------------------------------------
__global__ __launch_bounds__(128)
void attn_kernel(const float* __restrict__ Q, const float* __restrict__ Kt,
                 const float* __restrict__ Vt, float* __restrict__ O,
                 const int* __restrict__ mtok, int causal) {
    int qpos = blockIdx.x;
    int h = blockIdx.y;
    int b = blockIdx.z;
    int t = threadIdx.x;
    __shared__ float qs[DHEAD];
    __shared__ float sc[SEQ];
    __shared__ float red[4];
    __shared__ float ctxp[DHEAD];
    const size_t base = (size_t)b*SEQ*DMODEL + h*DHEAD;
    const float* qrow = Q + base + (size_t)qpos*DMODEL;
    if (t < DHEAD) qs[t] = qrow[t];
    __syncthreads();
    // scores (4 keys / thread)
    float lmax = -INFINITY;
    #pragma unroll
    for (int r = 0; r < 4; r++) {
        int j = t + r*128;
        const float* krow = Kt + base + (size_t)j*DMODEL;
        float s = 0.f;
        #pragma unroll
        for (int d = 0; d < DHEAD; d += 4) {
            float4 kv = *reinterpret_cast<const float4*>(krow + d);
            s = fmaf(qs[d],kv.x, fmaf(qs[d+1],kv.y, fmaf(qs[d+2],kv.z, fmaf(qs[d+3],kv.w, s))));
        }
        s *= 0.125f;  // 1/sqrt(64)
        bool valid = (mtok[b*SEQ + j] != 0) && (!causal || j <= qpos);
        s = valid ? s : -1e9f;
        sc[j] = s;
        lmax = fmaxf(lmax, s);
    }
    #pragma unroll
    for (int o = 16; o > 0; o >>= 1) lmax = fmaxf(lmax, __shfl_xor_sync(0xffffffffu, lmax, o));
    if ((t & 31) == 0) red[t >> 5] = lmax;
    __syncthreads();
    float mx = fmaxf(fmaxf(red[0], red[1]), fmaxf(red[2], red[3]));
    float lsum = 0.f;
    #pragma unroll
    for (int r = 0; r < 4; r++) {
        int j = t + r*128;
        float e = expf(sc[j] - mx);
        sc[j] = e;
        lsum += e;
    }
    #pragma unroll
    for (int o = 16; o > 0; o >>= 1) lsum += __shfl_xor_sync(0xffffffffu, lsum, o);
    __syncthreads();
    if ((t & 31) == 0) red[t >> 5] = lsum;
    __syncthreads();
    float inv = 1.f / (red[0]+red[1]+red[2]+red[3]);
    // ctx: thread = d + 64*g ; each half sums 256 keys
    int d = t & 63, g = t >> 6;
    const float* vb = Vt + base + d;
    float a0=0.f, a1=0.f, a2=0.f, a3=0.f;
    int j0 = g*256;
    for (int j = j0; j < j0+256; j += 4) {
        a0 = fmaf(sc[j+0], vb[(size_t)(j+0)*DMODEL], a0);
        a1 = fmaf(sc[j+1], vb[(size_t)(j+1)*DMODEL], a1);
        a2 = fmaf(sc[j+2], vb[(size_t)(j+2)*DMODEL], a2);
        a3 = fmaf(sc[j+3], vb[(size_t)(j+3)*DMODEL], a3);
    }
    float acc = (a0+a1)+(a2+a3);
    if (g == 1) ctxp[d] = acc;
    __syncthreads();
    if (g == 0) O[base + (size_t)qpos*DMODEL + d] = (acc + ctxp[d]) * inv;
}

// ---------------------------------------------------------------------------
// Orchestration
// ---------------------------------------------------------------------------
extern "C" void kernel_launch(void* const* d_in, const int* in_sizes, int n_in,
                              void* d_out, int out_size) {
    const int*   src        = (const int*)  d_in[0];
    const int*   tgt        = (const int*)  d_in[1];
    const float* emb        = (const float*)d_in[2];
    const float* enc_attn_w = (const float*)d_in[3];
    const float* enc_attn_b = (const float*)d_in[4];
    const float* enc_ln_g   = (const float*)d_in[5];
    const float* enc_ln_b   = (const float*)d_in[6];
    const float* enc_w1     = (const float*)d_in[7];
    const float* enc_b1     = (const float*)d_in[8];
    const float* enc_w2     = (const float*)d_in[9];
    const float* enc_b2     = (const float*)d_in[10];
    const float* dec_attn_w = (const float*)d_in[11];
    const float* dec_attn_b = (const float*)d_in[12];
    const float* dec_ln_g   = (const float*)d_in[13];
    const float* dec_ln_b   = (const float*)d_in[14];
    const float* dec_w1     = (const float*)d_in[15];
    const float* dec_b1     = (const float*)d_in[16];
    const float* dec_w2     = (const float*)d_in[17];
    const float* dec_b2     = (const float*)d_in[18];
    const float* enc_norm_g = (const float*)d_in[19];
    const float* enc_norm_b = (const float*)d_in[20];
    const float* dec_norm_g = (const float*)d_in[21];
    const float* dec_norm_b = (const float*)d_in[22];

    float *x, *x2, *q, *k, *v, *ctx, *enc, *hbuf;
    cudaGetSymbolAddress((void**)&x,   g_x);
    cudaGetSymbolAddress((void**)&x2,  g_x2);
    cudaGetSymbolAddress((void**)&q,   g_q);
    cudaGetSymbolAddress((void**)&k,   g_k);
    cudaGetSymbolAddress((void**)&v,   g_v);
    cudaGetSymbolAddress((void**)&ctx, g_ctx);
    cudaGetSymbolAddress((void**)&enc, g_enc);
    cudaGetSymbolAddress((void**)&hbuf,g_h);

    const int D = DMODEL, M = MROWS;
    const size_t WSZ = (size_t)D*D;   // one attn weight matrix
    dim3 attnGrid(SEQ, NHEAD, BATCH);

    // ===================== ENCODER =====================
    embed_kernel<<<M, 128>>>(src, emb, x);
    for (int l = 0; l < NLAYER; l++) {
        const float* w  = enc_attn_w + (size_t)l*4*WSZ;
        const float* bb = enc_attn_b + (size_t)l*4*D;
        ln_kernel<<<M, 128>>>(x, enc_ln_g + (size_t)(l*2+0)*D, enc_ln_b + (size_t)(l*2+0)*D, x2);
        launch_gemm(x2, w + 0*WSZ, bb + 0*D, nullptr, q, M, D, D, false);
        launch_gemm(x2, w + 1*WSZ, bb + 1*D, nullptr, k, M, D, D, false);
        launch_gemm(x2, w + 2*WSZ, bb + 2*D, nullptr, v, M, D, D, false);
        attn_kernel<<<attnGrid, 128>>>(q, k, v, ctx, src, 0);
        launch_gemm(ctx, w + 3*WSZ, bb + 3*D, x, x, M, D, D, false);
        ln_kernel<<<M, 128>>>(x, enc_ln_g + (size_t)(l*2+1)*D, enc_ln_b + (size_t)(l*2+1)*D, x2);
        launch_gemm(x2, enc_w1 + (size_t)l*DFF*D, enc_b1 + (size_t)l*DFF, nullptr, hbuf, M, DFF, D, true);
        launch_gemm(hbuf, enc_w2 + (size_t)l*D*DFF, enc_b2 + (size_t)l*D, x, x, M, D, DFF, false);
    }
    ln_kernel<<<M, 128>>>(x, enc_norm_g, enc_norm_b, enc);

    // ===================== DECODER =====================
    embed_kernel<<<M, 128>>>(tgt, emb, x);
    for (int l = 0; l < NLAYER; l++) {
        const float* w  = dec_attn_w + (size_t)l*8*WSZ;
        const float* bb = dec_attn_b + (size_t)l*8*D;
        // self-attention (causal + pad mask on tgt)
        ln_kernel<<<M, 128>>>(x, dec_ln_g + (size_t)(l*3+0)*D, dec_ln_b + (size_t)(l*3+0)*D, x2);
        launch_gemm(x2, w + 0*WSZ, bb + 0*D, nullptr, q, M, D, D, false);
        launch_gemm(x2, w + 1*WSZ, bb + 1*D, nullptr, k, M, D, D, false);
        launch_gemm(x2, w + 2*WSZ, bb + 2*D, nullptr, v, M, D, D, false);
        attn_kernel<<<attnGrid, 128>>>(q, k, v, ctx, tgt, 1);
        launch_gemm(ctx, w + 3*WSZ, bb + 3*D, x, x, M, D, D, false);
        // cross-attention (pad mask on src, K/V from encoder output)
        ln_kernel<<<M, 128>>>(x, dec_ln_g + (size_t)(l*3+1)*D, dec_ln_b + (size_t)(l*3+1)*D, x2);
        launch_gemm(x2,  w + 4*WSZ, bb + 4*D, nullptr, q, M, D, D, false);
        launch_gemm(enc, w + 5*WSZ, bb + 5*D, nullptr, k, M, D, D, false);
        launch_gemm(enc, w + 6*WSZ, bb + 6*D, nullptr, v, M, D, D, false);
        attn_kernel<<<attnGrid, 128>>>(q, k, v, ctx, src, 0);
        launch_gemm(ctx, w + 7*WSZ, bb + 7*D, x, x, M, D, D, false);
        // FFN
        ln_kernel<<<M, 128>>>(x, dec_ln_g + (size_t)(l*3+2)*D, dec_ln_b + (size_t)(l*3+2)*D, x2);
        launch_gemm(x2, dec_w1 + (size_t)l*DFF*D, dec_b1 + (size_t)l*DFF, nullptr, hbuf, M, DFF, D, true);
        launch_gemm(hbuf, dec_w2 + (size_t)l*D*DFF, dec_b2 + (size_t)l*D, x, x, M, D, DFF, false);
    }
    ln_kernel<<<M, 128>>>(x, dec_norm_g, dec_norm_b, x2);

    // ===================== tied output projection =====================
    launch_gemm(x2, emb, nullptr, nullptr, (float*)d_out, M, VOCAB, D, false);
}

// round 3
// speedup vs baseline: 3.2431x; 3.2431x over previous
#include <cuda_runtime.h>
#include <cuda_bf16.h>
#include <cstdint>
#include <math.h>

// ---------------------------------------------------------------------------
// Problem constants
// ---------------------------------------------------------------------------
#define BATCH 8
#define SEQ   512
#define DMODEL 512
#define NHEAD 8
#define DHEAD 64
#define NLAYER 4
#define DFF   2048
#define VOCAB 32000
#define MROWS (BATCH*SEQ)   // 4096

__device__ __forceinline__ uint32_t f2tf32(float x) {
    uint32_t r; asm("cvt.rna.tf32.f32 %0, %1;" : "=r"(r) : "f"(x)); return r;
}

__device__ __forceinline__ void mma_tf32(float* c, const uint32_t* a, const uint32_t* b) {
    asm volatile(
        "mma.sync.aligned.m16n8k8.row.col.f32.tf32.tf32.f32 "
        "{%0,%1,%2,%3}, {%4,%5,%6,%7}, {%8,%9}, {%0,%1,%2,%3};"
        : "+f"(c[0]), "+f"(c[1]), "+f"(c[2]), "+f"(c[3])
        : "r"(a[0]), "r"(a[1]), "r"(a[2]), "r"(a[3]), "r"(b[0]), "r"(b[1]));
}

// ---------------------------------------------------------------------------
// Scratch (device globals; no allocation allowed)
// ---------------------------------------------------------------------------
__device__ __align__(16) float g_x  [MROWS*DMODEL];
__device__ __align__(16) float g_x2 [MROWS*DMODEL];
__device__ __align__(16) float g_q  [MROWS*DMODEL];
__device__ __align__(16) float g_ctx[MROWS*DMODEL];
__device__ __align__(16) float g_enc[MROWS*DMODEL];
__device__ __align__(16) float g_h  [MROWS*DFF];
__device__ __align__(16) float g_qkv[MROWS*3*DMODEL];
__device__ __align__(16) float g_kv [MROWS*2*DMODEL];

// ---------------------------------------------------------------------------
// Embedding + sinusoidal positional encoding
// ---------------------------------------------------------------------------
__global__ void embed_kernel(const int* __restrict__ tok,
                             const float* __restrict__ emb,
                             float* __restrict__ y) {
    int row = blockIdx.x;
    int s   = row % SEQ;
    int t   = tok[row];
    const float scale = 22.62741699796952f;
    const float c0 = -9.210340371976184f / (float)DMODEL;
    int tid = threadIdx.x;
    #pragma unroll
    for (int i = 0; i < 4; i++) {
        int d = tid + i*128;
        float e = (t == 0) ? 0.f : emb[(size_t)t*DMODEL + d];
        int half = d >> 1;
        float div = expf((float)(2*half) * c0);
        float ang = (float)s * div;
        float pe = (d & 1) ? cosf(ang) : sinf(ang);
        y[(size_t)row*DMODEL + d] = e*scale + pe;
    }
}

// ---------------------------------------------------------------------------
// LayerNorm over last dim (D=512)
// ---------------------------------------------------------------------------
__global__ void ln_kernel(const float* __restrict__ x,
                          const float* __restrict__ g,
                          const float* __restrict__ b,
                          float* __restrict__ y) {
    int row = blockIdx.x;
    const float* xr = x + (size_t)row*DMODEL;
    int t = threadIdx.x;
    float v[4];
    float s = 0.f;
    #pragma unroll
    for (int i = 0; i < 4; i++) { v[i] = xr[t + i*128]; s += v[i]; }
    __shared__ float red[4];
    #pragma unroll
    for (int o = 16; o > 0; o >>= 1) s += __shfl_xor_sync(0xffffffffu, s, o);
    if ((t & 31) == 0) red[t >> 5] = s;
    __syncthreads();
    float mean = (red[0]+red[1]+red[2]+red[3]) * (1.f/(float)DMODEL);
    float vs = 0.f;
    #pragma unroll
    for (int i = 0; i < 4; i++) { float d = v[i]-mean; vs += d*d; }
    #pragma unroll
    for (int o = 16; o > 0; o >>= 1) vs += __shfl_xor_sync(0xffffffffu, vs, o);
    __syncthreads();
    if ((t & 31) == 0) red[t >> 5] = vs;
    __syncthreads();
    float var = (red[0]+red[1]+red[2]+red[3]) * (1.f/(float)DMODEL);
    float inv = rsqrtf(var + 1e-5f);
    #pragma unroll
    for (int i = 0; i < 4; i++) {
        int d = t + i*128;
        y[(size_t)row*DMODEL + d] = (v[i]-mean)*inv*g[d] + b[d];
    }
}

// ---------------------------------------------------------------------------
// tf32 mma.sync GEMM:  C[M,N] = A[M,K] * W[N,K]^T (+bias)(+relu)(+res)
// CTA 128x128x32, 256 thr, 8 warps (2 along M x 4 along N), warp tile 64x32.
// Double-buffered smem, register-prefetched global loads, cvt.rna.tf32 fill.
// ---------------------------------------------------------------------------
#define SSTR 132                 // smem row stride (words)
#define ABUF (32*SSTR)           // one A (or B) buffer, words
#define GEMM_SMEM (4*ABUF*4)     // 67584 bytes

template<bool RELU, bool RES, bool BIAS>
__global__ __launch_bounds__(256)
void gemm_mma(const float* __restrict__ A, const float* __restrict__ W,
              const float* __restrict__ bias, const float* __restrict__ res,
              float* __restrict__ C, int M, int N, int K) {
    extern __shared__ uint32_t sm[];
    int t = threadIdx.x, lane = t & 31, wid = t >> 5;
    int wm = (wid & 1) * 64;        // warp M offset in tile
    int wn = (wid >> 1) * 32;       // warp N offset in tile
    int r4 = lane >> 2, l4 = lane & 3;

    const float* Ab = A + (size_t)blockIdx.y*128*K;
    const float* Wb = W + (size_t)blockIdx.x*128*K;
    int row0 = t >> 3;              // 0..31
    int qc   = t & 7;               // float4 column group within BK=32

    float acc[4][4][4];
    #pragma unroll
    for (int i = 0; i < 4; i++)
        #pragma unroll
        for (int j = 0; j < 4; j++)
            #pragma unroll
            for (int c = 0; c < 4; c++) acc[i][j][c] = 0.f;

    int NK = K >> 5;
    float4 pa[4], pb[4];
    // prologue: load tile 0
    #pragma unroll
    for (int i = 0; i < 4; i++) {
        pa[i] = *(const float4*)(Ab + (size_t)(row0 + 32*i)*K + qc*4);
        pb[i] = *(const float4*)(Wb + (size_t)(row0 + 32*i)*K + qc*4);
    }
    {
        uint32_t* sA = sm; uint32_t* sB = sm + ABUF;
        #pragma unroll
        for (int i = 0; i < 4; i++) {
            int rr = row0 + 32*i, kc = qc*4;
            sA[(kc+0)*SSTR+rr]=f2tf32(pa[i].x); sA[(kc+1)*SSTR+rr]=f2tf32(pa[i].y);
            sA[(kc+2)*SSTR+rr]=f2tf32(pa[i].z); sA[(kc+3)*SSTR+rr]=f2tf32(pa[i].w);
            sB[(kc+0)*SSTR+rr]=f2tf32(pb[i].x); sB[(kc+1)*SSTR+rr]=f2tf32(pb[i].y);
            sB[(kc+2)*SSTR+rr]=f2tf32(pb[i].z); sB[(kc+3)*SSTR+rr]=f2tf32(pb[i].w);
        }
    }
    __syncthreads();

    for (int it = 0; it < NK; it++) {
        int cur = it & 1;
        if (it + 1 < NK) {
            int k0 = (it+1)*32;
            #pragma unroll
            for (int i = 0; i < 4; i++) {
                pa[i] = *(const float4*)(Ab + (size_t)(row0 + 32*i)*K + k0 + qc*4);
                pb[i] = *(const float4*)(Wb + (size_t)(row0 + 32*i)*K + k0 + qc*4);
            }
        }
        const uint32_t* sA = sm + cur*2*ABUF;
        const uint32_t* sB = sA + ABUF;
        #pragma unroll
        for (int ks = 0; ks < 4; ks++) {
            int kb = ks*8 + l4;
            uint32_t af[4][4], bf[4][2];
            #pragma unroll
            for (int mi = 0; mi < 4; mi++) {
                int m = wm + mi*16 + r4;
                af[mi][0] = sA[kb*SSTR + m];
                af[mi][1] = sA[kb*SSTR + m + 8];
                af[mi][2] = sA[(kb+4)*SSTR + m];
                af[mi][3] = sA[(kb+4)*SSTR + m + 8];
            }
            #pragma unroll
            for (int ni = 0; ni < 4; ni++) {
                int n = wn + ni*8 + r4;
                bf[ni][0] = sB[kb*SSTR + n];
                bf[ni][1] = sB[(kb+4)*SSTR + n];
            }
            #pragma unroll
            for (int mi = 0; mi < 4; mi++)
                #pragma unroll
                for (int ni = 0; ni < 4; ni++)
                    mma_tf32(acc[mi][ni], af[mi], bf[ni]);
        }
        __syncthreads();
        if (it + 1 < NK) {
            uint32_t* dA = sm + (1-cur)*2*ABUF;
            uint32_t* dB = dA + ABUF;
            #pragma unroll
            for (int i = 0; i < 4; i++) {
                int rr = row0 + 32*i, kc = qc*4;
                dA[(kc+0)*SSTR+rr]=f2tf32(pa[i].x); dA[(kc+1)*SSTR+rr]=f2tf32(pa[i].y);
                dA[(kc+2)*SSTR+rr]=f2tf32(pa[i].z); dA[(kc+3)*SSTR+rr]=f2tf32(pa[i].w);
                dB[(kc+0)*SSTR+rr]=f2tf32(pb[i].x); dB[(kc+1)*SSTR+rr]=f2tf32(pb[i].y);
                dB[(kc+2)*SSTR+rr]=f2tf32(pb[i].z); dB[(kc+3)*SSTR+rr]=f2tf32(pb[i].w);
            }
            __syncthreads();
        }
    }

    // epilogue
    int gm = blockIdx.y*128 + wm;
    int gn = blockIdx.x*128 + wn;
    #pragma unroll
    for (int mi = 0; mi < 4; mi++) {
        #pragma unroll
        for (int ni = 0; ni < 4; ni++) {
            int row = gm + mi*16 + r4;
            int col = gn + ni*8 + l4*2;
            float2 v0 = make_float2(acc[mi][ni][0], acc[mi][ni][1]);
            float2 v1 = make_float2(acc[mi][ni][2], acc[mi][ni][3]);
            if (BIAS) {
                float2 bv = *(const float2*)(bias + col);
                v0.x += bv.x; v0.y += bv.y; v1.x += bv.x; v1.y += bv.y;
            }
            if (RELU) {
                v0.x = fmaxf(v0.x, 0.f); v0.y = fmaxf(v0.y, 0.f);
                v1.x = fmaxf(v1.x, 0.f); v1.y = fmaxf(v1.y, 0.f);
            }
            if (RES) {
                float2 r0 = *(const float2*)(res + (size_t)row*N + col);
                float2 r1 = *(const float2*)(res + (size_t)(row+8)*N + col);
                v0.x += r0.x; v0.y += r0.y; v1.x += r1.x; v1.y += r1.y;
            }
            *(float2*)(C + (size_t)row*N + col)     = v0;
            *(float2*)(C + (size_t)(row+8)*N + col) = v1;
        }
    }
}

// ---------------------------------------------------------------------------
// Tiled attention: block = 32 q-rows of one (b,h). K/V staged in smem,
// two-pass softmax with scores tile in smem. 128 threads.
// ---------------------------------------------------------------------------
#define QT 32
#define SCS 516
#define ATTN_SMEM 92928

__global__ __launch_bounds__(128)
void attn_tiled(const float* __restrict__ Qp, int qstride,
                const float* __restrict__ Kp, const float* __restrict__ Vp, int kvstride,
                float* __restrict__ Op,
                const int* __restrict__ mtok, int causal) {
    extern __shared__ float smf[];
    float* Qs   = smf;
    float* Ks   = smf + 2176;
    float* sc   = smf + 6528;
    float* red  = smf + 23040;
    float* invr = smf + 23168;

    int t = threadIdx.x;
    int q0 = blockIdx.x * QT;
    int h = blockIdx.y, b = blockIdx.z;
    const float* Qb = Qp + (size_t)b*SEQ*qstride  + h*DHEAD;
    const float* Kb = Kp + (size_t)b*SEQ*kvstride + h*DHEAD;
    const float* Vb = Vp + (size_t)b*SEQ*kvstride + h*DHEAD;

    #pragma unroll
    for (int i = 0; i < 4; i++) {
        int idx = t + i*128; int r = idx >> 4, c4 = idx & 15;
        float4 v = *(const float4*)(Qb + (size_t)(q0 + r)*qstride + c4*4);
        *(float4*)(Qs + r*68 + c4*4) = v;
    }

    int tq = t >> 4, tk = t & 15;
    for (int kt = 0; kt < 8; kt++) {
        __syncthreads();
        #pragma unroll
        for (int i = 0; i < 8; i++) {
            int idx = t + i*128; int r = idx >> 4, c4 = idx & 15;
            float4 v = *(const float4*)(Kb + (size_t)(kt*64 + r)*kvstride + c4*4);
            *(float4*)(Ks + r*68 + c4*4) = v;
        }
        __syncthreads();
        float acc[4][4] = {};
        const float4* Qs4 = (const float4*)Qs;
        const float4* Ks4 = (const float4*)Ks;
        #pragma unroll
        for (int dc = 0; dc < 16; dc++) {
            float4 a[4], bb[4];
            #pragma unroll
            for (int i = 0; i < 4; i++) a[i]  = Qs4[(4*tq + i)*17 + dc];
            #pragma unroll
            for (int j = 0; j < 4; j++) bb[j] = Ks4[(4*tk + j)*17 + dc];
            #pragma unroll
            for (int i = 0; i < 4; i++)
                #pragma unroll
                for (int j = 0; j < 4; j++)
                    acc[i][j] = fmaf(a[i].x, bb[j].x, fmaf(a[i].y, bb[j].y,
                                fmaf(a[i].z, bb[j].z, fmaf(a[i].w, bb[j].w, acc[i][j]))));
        }
        #pragma unroll
        for (int i = 0; i < 4; i++) {
            int q = q0 + 4*tq + i;
            #pragma unroll
            for (int j = 0; j < 4; j++) {
                int k = kt*64 + 4*tk + j;
                bool valid = (mtok[b*SEQ + k] != 0) && (!causal || k <= q);
                sc[(4*tq + i)*SCS + k] = valid ? acc[i][j]*0.125f : -1e9f;
            }
        }
    }
    __syncthreads();
    {
        int r = t & 31, p = t >> 5;
        float4* row4 = (float4*)(sc + r*SCS + p*128);
        float m = -1e30f;
        #pragma unroll 8
        for (int j = 0; j < 32; j++) {
            float4 v = row4[j];
            m = fmaxf(m, fmaxf(fmaxf(v.x, v.y), fmaxf(v.z, v.w)));
        }
        red[r*4 + p] = m;
        __syncthreads();
        m = fmaxf(fmaxf(red[r*4], red[r*4+1]), fmaxf(red[r*4+2], red[r*4+3]));
        __syncthreads();
        float s = 0.f;
        #pragma unroll 8
        for (int j = 0; j < 32; j++) {
            float4 v = row4[j];
            v.x = __expf(v.x - m); v.y = __expf(v.y - m);
            v.z = __expf(v.z - m); v.w = __expf(v.w - m);
            row4[j] = v;
            s += (v.x + v.y) + (v.z + v.w);
        }
        red[r*4 + p] = s;
        __syncthreads();
        if (p == 0) invr[r] = 1.f / (red[r*4] + red[r*4+1] + red[r*4+2] + red[r*4+3]);
    }
    int tq2 = t >> 4, td = t & 15;
    float4 cacc[4];
    #pragma unroll
    for (int i = 0; i < 4; i++) cacc[i] = make_float4(0.f, 0.f, 0.f, 0.f);
    for (int kt = 0; kt < 8; kt++) {
        __syncthreads();
        #pragma unroll
        for (int i = 0; i < 8; i++) {
            int idx = t + i*128; int r = idx >> 4, c4 = idx & 15;
            float4 v = *(const float4*)(Vb + (size_t)(kt*64 + r)*kvstride + c4*4);
            *(float4*)(Ks + r*68 + c4*4) = v;
        }
        __syncthreads();
        const float4* sc4 = (const float4*)sc;
        const float4* Vs4 = (const float4*)Ks;
        #pragma unroll
        for (int kk = 0; kk < 16; kk++) {
            float4 s4[4], v4[4];
            #pragma unroll
            for (int i = 0; i < 4; i++) s4[i] = sc4[(4*tq2 + i)*129 + kt*16 + kk];
            #pragma unroll
            for (int j = 0; j < 4; j++) v4[j] = Vs4[(kk*4 + j)*17 + td];
            #pragma unroll
            for (int i = 0; i < 4; i++) {
                cacc[i].x = fmaf(s4[i].x, v4[0].x, fmaf(s4[i].y, v4[1].x,
                            fmaf(s4[i].z, v4[2].x, fmaf(s4[i].w, v4[3].x, cacc[i].x))));
                cacc[i].y = fmaf(s4[i].x, v4[0].y, fmaf(s4[i].y, v4[1].y,
                            fmaf(s4[i].z, v4[2].y, fmaf(s4[i].w, v4[3].y, cacc[i].y))));
                cacc[i].z = fmaf(s4[i].x, v4[0].z, fmaf(s4[i].y, v4[1].z,
                            fmaf(s4[i].z, v4[2].z, fmaf(s4[i].w, v4[3].z, cacc[i].z))));
                cacc[i].w = fmaf(s4[i].x, v4[0].w, fmaf(s4[i].y, v4[1].w,
                            fmaf(s4[i].z, v4[2].w, fmaf(s4[i].w, v4[3].w, cacc[i].w))));
            }
        }
    }
    #pragma unroll
    for (int i = 0; i < 4; i++) {
        int q = q0 + 4*tq2 + i;
        float inv = invr[4*tq2 + i];
        float4 o = make_float4(cacc[i].x*inv, cacc[i].y*inv, cacc[i].z*inv, cacc[i].w*inv);
        *(float4*)(Op + ((size_t)b*SEQ + q)*DMODEL + h*DHEAD + td*4) = o;
    }
}

// ---------------------------------------------------------------------------
// Orchestration
// ---------------------------------------------------------------------------
static inline void launch_gemm(const float* A, const float* W, const float* bias,
                               const float* res, float* C, int M, int N, int K,
                               bool relu) {
    dim3 grid(N/128, M/128), block(256);
    if (res) {
        cudaFuncSetAttribute(gemm_mma<false,true,true>, cudaFuncAttributeMaxDynamicSharedMemorySize, GEMM_SMEM);
        gemm_mma<false,true,true><<<grid, block, GEMM_SMEM>>>(A, W, bias, res, C, M, N, K);
    } else if (relu) {
        cudaFuncSetAttribute(gemm_mma<true,false,true>, cudaFuncAttributeMaxDynamicSharedMemorySize, GEMM_SMEM);
        gemm_mma<true,false,true><<<grid, block, GEMM_SMEM>>>(A, W, bias, nullptr, C, M, N, K);
    } else if (bias) {
        cudaFuncSetAttribute(gemm_mma<false,false,true>, cudaFuncAttributeMaxDynamicSharedMemorySize, GEMM_SMEM);
        gemm_mma<false,false,true><<<grid, block, GEMM_SMEM>>>(A, W, bias, nullptr, C, M, N, K);
    } else {
        cudaFuncSetAttribute(gemm_mma<false,false,false>, cudaFuncAttributeMaxDynamicSharedMemorySize, GEMM_SMEM);
        gemm_mma<false,false,false><<<grid, block, GEMM_SMEM>>>(A, W, nullptr, nullptr, C, M, N, K);
    }
}

extern "C" void kernel_launch(void* const* d_in, const int* in_sizes, int n_in,
                              void* d_out, int out_size) {
    const int*   src        = (const int*)  d_in[0];
    const int*   tgt        = (const int*)  d_in[1];
    const float* emb        = (const float*)d_in[2];
    const float* enc_attn_w = (const float*)d_in[3];
    const float* enc_attn_b = (const float*)d_in[4];
    const float* enc_ln_g   = (const float*)d_in[5];
    const float* enc_ln_b   = (const float*)d_in[6];
    const float* enc_w1     = (const float*)d_in[7];
    const float* enc_b1     = (const float*)d_in[8];
    const float* enc_w2     = (const float*)d_in[9];
    const float* enc_b2     = (const float*)d_in[10];
    const float* dec_attn_w = (const float*)d_in[11];
    const float* dec_attn_b = (const float*)d_in[12];
    const float* dec_ln_g   = (const float*)d_in[13];
    const float* dec_ln_b   = (const float*)d_in[14];
    const float* dec_w1     = (const float*)d_in[15];
    const float* dec_b1     = (const float*)d_in[16];
    const float* dec_w2     = (const float*)d_in[17];
    const float* dec_b2     = (const float*)d_in[18];
    const float* enc_norm_g = (const float*)d_in[19];
    const float* enc_norm_b = (const float*)d_in[20];
    const float* dec_norm_g = (const float*)d_in[21];
    const float* dec_norm_b = (const float*)d_in[22];

    float *x, *x2, *qb, *ctx, *enc, *hbuf, *qkv, *kv;
    cudaGetSymbolAddress((void**)&x,    g_x);
    cudaGetSymbolAddress((void**)&x2,   g_x2);
    cudaGetSymbolAddress((void**)&qb,   g_q);
    cudaGetSymbolAddress((void**)&ctx,  g_ctx);
    cudaGetSymbolAddress((void**)&enc,  g_enc);
    cudaGetSymbolAddress((void**)&hbuf, g_h);
    cudaGetSymbolAddress((void**)&qkv,  g_qkv);
    cudaGetSymbolAddress((void**)&kv,   g_kv);

    cudaFuncSetAttribute(attn_tiled, cudaFuncAttributeMaxDynamicSharedMemorySize, ATTN_SMEM);

    const int D = DMODEL, M = MROWS;
    const size_t WSZ = (size_t)D*D;
    dim3 attnGrid(SEQ/QT, NHEAD, BATCH);

    // ===================== ENCODER =====================
    embed_kernel<<<M, 128>>>(src, emb, x);
    for (int l = 0; l < NLAYER; l++) {
        const float* w  = enc_attn_w + (size_t)l*4*WSZ;
        const float* bb = enc_attn_b + (size_t)l*4*D;
        ln_kernel<<<M, 128>>>(x, enc_ln_g + (size_t)(l*2+0)*D, enc_ln_b + (size_t)(l*2+0)*D, x2);
        launch_gemm(x2, w, bb, nullptr, qkv, M, 3*D, D, false);          // fused QKV
        attn_tiled<<<attnGrid, 128, ATTN_SMEM>>>(qkv, 3*D, qkv + D, qkv + 2*D, 3*D, ctx, src, 0);
        launch_gemm(ctx, w + 3*WSZ, bb + 3*D, x, x, M, D, D, false);
        ln_kernel<<<M, 128>>>(x, enc_ln_g + (size_t)(l*2+1)*D, enc_ln_b + (size_t)(l*2+1)*D, x2);
        launch_gemm(x2, enc_w1 + (size_t)l*DFF*D, enc_b1 + (size_t)l*DFF, nullptr, hbuf, M, DFF, D, true);
        launch_gemm(hbuf, enc_w2 + (size_t)l*D*DFF, enc_b2 + (size_t)l*D, x, x, M, D, DFF, false);
    }
    ln_kernel<<<M, 128>>>(x, enc_norm_g, enc_norm_b, enc);

    // ===================== DECODER =====================
    embed_kernel<<<M, 128>>>(tgt, emb, x);
    for (int l = 0; l < NLAYER; l++) {
        const float* w  = dec_attn_w + (size_t)l*8*WSZ;
        const float* bb = dec_attn_b + (size_t)l*8*D;
        // self-attention (causal + pad mask on tgt)
        ln_kernel<<<M, 128>>>(x, dec_ln_g + (size_t)(l*3+0)*D, dec_ln_b + (size_t)(l*3+0)*D, x2);
        launch_gemm(x2, w, bb, nullptr, qkv, M, 3*D, D, false);
        attn_tiled<<<attnGrid, 128, ATTN_SMEM>>>(qkv, 3*D, qkv + D, qkv + 2*D, 3*D, ctx, tgt, 1);
        launch_gemm(ctx, w + 3*WSZ, bb + 3*D, x, x, M, D, D, false);
        // cross-attention (pad mask on src, K/V from encoder output)
        ln_kernel<<<M, 128>>>(x, dec_ln_g + (size_t)(l*3+1)*D, dec_ln_b + (size_t)(l*3+1)*D, x2);
        launch_gemm(x2,  w + 4*WSZ, bb + 4*D, nullptr, qb, M, D, D, false);
        launch_gemm(enc, w + 5*WSZ, bb + 5*D, nullptr, kv, M, 2*D, D, false);  // fused K,V
        attn_tiled<<<attnGrid, 128, ATTN_SMEM>>>(qb, D, kv, kv + D, 2*D, ctx, src, 0);
        launch_gemm(ctx, w + 7*WSZ, bb + 7*D, x, x, M, D, D, false);
        // FFN
        ln_kernel<<<M, 128>>>(x, dec_ln_g + (size_t)(l*3+2)*D, dec_ln_b + (size_t)(l*3+2)*D, x2);
        launch_gemm(x2, dec_w1 + (size_t)l*DFF*D, dec_b1 + (size_t)l*DFF, nullptr, hbuf, M, DFF, D, true);
        launch_gemm(hbuf, dec_w2 + (size_t)l*D*DFF, dec_b2 + (size_t)l*D, x, x, M, D, DFF, false);
    }
    ln_kernel<<<M, 128>>>(x, dec_norm_g, dec_norm_b, x2);

    // ===================== tied output projection =====================
    launch_gemm(x2, emb, nullptr, nullptr, (float*)d_out, M, VOCAB, D, false);
}

// round 4
// speedup vs baseline: 4.6101x; 1.4215x over previous
#include <cuda_runtime.h>
#include <cuda_bf16.h>
#include <cstdint>
#include <math.h>

// ---------------------------------------------------------------------------
// Problem constants
// ---------------------------------------------------------------------------
#define BATCH 8
#define SEQ   512
#define DMODEL 512
#define NHEAD 8
#define DHEAD 64
#define NLAYER 4
#define DFF   2048
#define VOCAB 32000
#define MROWS (BATCH*SEQ)   // 4096

__device__ __forceinline__ uint32_t f2tf32(float x) {
    uint32_t r; asm("cvt.rna.tf32.f32 %0, %1;" : "=r"(r) : "f"(x)); return r;
}

__device__ __forceinline__ void mma_tf32(float* c, const uint32_t* a, const uint32_t* b) {
    asm volatile(
        "mma.sync.aligned.m16n8k8.row.col.f32.tf32.tf32.f32 "
        "{%0,%1,%2,%3}, {%4,%5,%6,%7}, {%8,%9}, {%0,%1,%2,%3};"
        : "+f"(c[0]), "+f"(c[1]), "+f"(c[2]), "+f"(c[3])
        : "r"(a[0]), "r"(a[1]), "r"(a[2]), "r"(a[3]), "r"(b[0]), "r"(b[1]));
}

// ---------------------------------------------------------------------------
// Scratch (device globals; no allocation allowed)
// ---------------------------------------------------------------------------
__device__ __align__(16) float g_x  [MROWS*DMODEL];
__device__ __align__(16) float g_x2 [MROWS*DMODEL];
__device__ __align__(16) float g_q  [MROWS*DMODEL];
__device__ __align__(16) float g_ctx[MROWS*DMODEL];
__device__ __align__(16) float g_enc[MROWS*DMODEL];
__device__ __align__(16) float g_h  [MROWS*DFF];
__device__ __align__(16) float g_qkv[MROWS*3*DMODEL];
__device__ __align__(16) float g_kv [MROWS*2*DMODEL];

// ---------------------------------------------------------------------------
// Embedding + sinusoidal positional encoding
// ---------------------------------------------------------------------------
__global__ void embed_kernel(const int* __restrict__ tok,
                             const float* __restrict__ emb,
                             float* __restrict__ y) {
    int row = blockIdx.x;
    int s   = row % SEQ;
    int t   = tok[row];
    const float scale = 22.62741699796952f;
    const float c0 = -9.210340371976184f / (float)DMODEL;
    int tid = threadIdx.x;
    #pragma unroll
    for (int i = 0; i < 4; i++) {
        int d = tid + i*128;
        float e = (t == 0) ? 0.f : emb[(size_t)t*DMODEL + d];
        int half = d >> 1;
        float div = expf((float)(2*half) * c0);
        float ang = (float)s * div;
        float pe = (d & 1) ? cosf(ang) : sinf(ang);
        y[(size_t)row*DMODEL + d] = e*scale + pe;
    }
}

// ---------------------------------------------------------------------------
// LayerNorm over last dim (D=512)
// ---------------------------------------------------------------------------
__global__ void ln_kernel(const float* __restrict__ x,
                          const float* __restrict__ g,
                          const float* __restrict__ b,
                          float* __restrict__ y) {
    int row = blockIdx.x;
    const float* xr = x + (size_t)row*DMODEL;
    int t = threadIdx.x;
    float v[4];
    float s = 0.f;
    #pragma unroll
    for (int i = 0; i < 4; i++) { v[i] = xr[t + i*128]; s += v[i]; }
    __shared__ float red[4];
    #pragma unroll
    for (int o = 16; o > 0; o >>= 1) s += __shfl_xor_sync(0xffffffffu, s, o);
    if ((t & 31) == 0) red[t >> 5] = s;
    __syncthreads();
    float mean = (red[0]+red[1]+red[2]+red[3]) * (1.f/(float)DMODEL);
    float vs = 0.f;
    #pragma unroll
    for (int i = 0; i < 4; i++) { float d = v[i]-mean; vs += d*d; }
    #pragma unroll
    for (int o = 16; o > 0; o >>= 1) vs += __shfl_xor_sync(0xffffffffu, vs, o);
    __syncthreads();
    if ((t & 31) == 0) red[t >> 5] = vs;
    __syncthreads();
    float var = (red[0]+red[1]+red[2]+red[3]) * (1.f/(float)DMODEL);
    float inv = rsqrtf(var + 1e-5f);
    #pragma unroll
    for (int i = 0; i < 4; i++) {
        int d = t + i*128;
        y[(size_t)row*DMODEL + d] = (v[i]-mean)*inv*g[d] + b[d];
    }
}

// ---------------------------------------------------------------------------
// tf32 mma.sync GEMM:  C[M,N] = A[M,K] * W[N,K]^T (+bias)(+relu)(+res)
// CTA 128x128x32, 256 thr, 8 warps, warp tile 64x32. (unchanged from R3)
// ---------------------------------------------------------------------------
#define SSTR 132
#define ABUF (32*SSTR)
#define GEMM_SMEM (4*ABUF*4)

template<bool RELU, bool RES, bool BIAS>
__global__ __launch_bounds__(256)
void gemm_mma(const float* __restrict__ A, const float* __restrict__ W,
              const float* __restrict__ bias, const float* __restrict__ res,
              float* __restrict__ C, int M, int N, int K) {
    extern __shared__ uint32_t sm[];
    int t = threadIdx.x, lane = t & 31, wid = t >> 5;
    int wm = (wid & 1) * 64;
    int wn = (wid >> 1) * 32;
    int r4 = lane >> 2, l4 = lane & 3;

    const float* Ab = A + (size_t)blockIdx.y*128*K;
    const float* Wb = W + (size_t)blockIdx.x*128*K;
    int row0 = t >> 3;
    int qc   = t & 7;

    float acc[4][4][4];
    #pragma unroll
    for (int i = 0; i < 4; i++)
        #pragma unroll
        for (int j = 0; j < 4; j++)
            #pragma unroll
            for (int c = 0; c < 4; c++) acc[i][j][c] = 0.f;

    int NK = K >> 5;
    float4 pa[4], pb[4];
    #pragma unroll
    for (int i = 0; i < 4; i++) {
        pa[i] = *(const float4*)(Ab + (size_t)(row0 + 32*i)*K + qc*4);
        pb[i] = *(const float4*)(Wb + (size_t)(row0 + 32*i)*K + qc*4);
    }
    {
        uint32_t* sA = sm; uint32_t* sB = sm + ABUF;
        #pragma unroll
        for (int i = 0; i < 4; i++) {
            int rr = row0 + 32*i, kc = qc*4;
            sA[(kc+0)*SSTR+rr]=f2tf32(pa[i].x); sA[(kc+1)*SSTR+rr]=f2tf32(pa[i].y);
            sA[(kc+2)*SSTR+rr]=f2tf32(pa[i].z); sA[(kc+3)*SSTR+rr]=f2tf32(pa[i].w);
            sB[(kc+0)*SSTR+rr]=f2tf32(pb[i].x); sB[(kc+1)*SSTR+rr]=f2tf32(pb[i].y);
            sB[(kc+2)*SSTR+rr]=f2tf32(pb[i].z); sB[(kc+3)*SSTR+rr]=f2tf32(pb[i].w);
        }
    }
    __syncthreads();

    for (int it = 0; it < NK; it++) {
        int cur = it & 1;
        if (it + 1 < NK) {
            int k0 = (it+1)*32;
            #pragma unroll
            for (int i = 0; i < 4; i++) {
                pa[i] = *(const float4*)(Ab + (size_t)(row0 + 32*i)*K + k0 + qc*4);
                pb[i] = *(const float4*)(Wb + (size_t)(row0 + 32*i)*K + k0 + qc*4);
            }
        }
        const uint32_t* sA = sm + cur*2*ABUF;
        const uint32_t* sB = sA + ABUF;
        #pragma unroll
        for (int ks = 0; ks < 4; ks++) {
            int kb = ks*8 + l4;
            uint32_t af[4][4], bf[4][2];
            #pragma unroll
            for (int mi = 0; mi < 4; mi++) {
                int m = wm + mi*16 + r4;
                af[mi][0] = sA[kb*SSTR + m];
                af[mi][1] = sA[kb*SSTR + m + 8];
                af[mi][2] = sA[(kb+4)*SSTR + m];
                af[mi][3] = sA[(kb+4)*SSTR + m + 8];
            }
            #pragma unroll
            for (int ni = 0; ni < 4; ni++) {
                int n = wn + ni*8 + r4;
                bf[ni][0] = sB[kb*SSTR + n];
                bf[ni][1] = sB[(kb+4)*SSTR + n];
            }
            #pragma unroll
            for (int mi = 0; mi < 4; mi++)
                #pragma unroll
                for (int ni = 0; ni < 4; ni++)
                    mma_tf32(acc[mi][ni], af[mi], bf[ni]);
        }
        __syncthreads();
        if (it + 1 < NK) {
            uint32_t* dA = sm + (1-cur)*2*ABUF;
            uint32_t* dB = dA + ABUF;
            #pragma unroll
            for (int i = 0; i < 4; i++) {
                int rr = row0 + 32*i, kc = qc*4;
                dA[(kc+0)*SSTR+rr]=f2tf32(pa[i].x); dA[(kc+1)*SSTR+rr]=f2tf32(pa[i].y);
                dA[(kc+2)*SSTR+rr]=f2tf32(pa[i].z); dA[(kc+3)*SSTR+rr]=f2tf32(pa[i].w);
                dB[(kc+0)*SSTR+rr]=f2tf32(pb[i].x); dB[(kc+1)*SSTR+rr]=f2tf32(pb[i].y);
                dB[(kc+2)*SSTR+rr]=f2tf32(pb[i].z); dB[(kc+3)*SSTR+rr]=f2tf32(pb[i].w);
            }
            __syncthreads();
        }
    }

    int gm = blockIdx.y*128 + wm;
    int gn = blockIdx.x*128 + wn;
    #pragma unroll
    for (int mi = 0; mi < 4; mi++) {
        #pragma unroll
        for (int ni = 0; ni < 4; ni++) {
            int row = gm + mi*16 + r4;
            int col = gn + ni*8 + l4*2;
            float2 v0 = make_float2(acc[mi][ni][0], acc[mi][ni][1]);
            float2 v1 = make_float2(acc[mi][ni][2], acc[mi][ni][3]);
            if (BIAS) {
                float2 bv = *(const float2*)(bias + col);
                v0.x += bv.x; v0.y += bv.y; v1.x += bv.x; v1.y += bv.y;
            }
            if (RELU) {
                v0.x = fmaxf(v0.x, 0.f); v0.y = fmaxf(v0.y, 0.f);
                v1.x = fmaxf(v1.x, 0.f); v1.y = fmaxf(v1.y, 0.f);
            }
            if (RES) {
                float2 r0 = *(const float2*)(res + (size_t)row*N + col);
                float2 r1 = *(const float2*)(res + (size_t)(row+8)*N + col);
                v0.x += r0.x; v0.y += r0.y; v1.x += r1.x; v1.y += r1.y;
            }
            *(float2*)(C + (size_t)row*N + col)     = v0;
            *(float2*)(C + (size_t)(row+8)*N + col) = v1;
        }
    }
}

// ---------------------------------------------------------------------------
// Flash-style mma attention.
// Block = 64 q-rows of one (b,h), 128 threads (4 warps).
// S-phase: warp w owns q rows [w*16, w*16+16) (stats warp-local).
// PV-phase: O^T = V^T @ P^T; warp w owns d rows [w*16, w*16+16).
// KV chunks of 64; causal blocks skip chunks above the diagonal.
// ---------------------------------------------------------------------------
#define KSS 68                       // K/V smem row stride (words)
#define PSS 76                       // P smem row stride (words)
#define KS_OFF 0
#define VS_OFF (64*KSS)              // 4352
#define PS_OFF (2*64*KSS)            // 8704
#define AL_OFF (PS_OFF + 64*PSS)     // 13568
#define LI_OFF (AL_OFF + 64)
#define MK_OFF (LI_OFF + 64)
#define ATTN_SMEM ((MK_OFF + 64)*4)  // 55040 bytes

__global__ __launch_bounds__(128)
void attn_mma(const float* __restrict__ Qp, int qstride,
              const float* __restrict__ Kp, const float* __restrict__ Vp, int kvstride,
              float* __restrict__ Op,
              const int* __restrict__ mtok, int causal) {
    extern __shared__ uint32_t smu[];
    uint32_t* Ks = smu + KS_OFF;
    uint32_t* Vs = smu + VS_OFF;
    uint32_t* Ps = smu + PS_OFF;
    float* alphas = (float*)(smu + AL_OFF);
    float* linv   = (float*)(smu + LI_OFF);
    uint32_t* maskv = smu + MK_OFF;

    int t = threadIdx.x, lane = t & 31, w = t >> 5;
    int r4 = lane >> 2, l4 = lane & 3;
    int q0 = blockIdx.x * 64, h = blockIdx.y, b = blockIdx.z;
    const float* Qb = Qp + (size_t)b*SEQ*qstride  + h*DHEAD;
    const float* Kb = Kp + (size_t)b*SEQ*kvstride + h*DHEAD;
    const float* Vb = Vp + (size_t)b*SEQ*kvstride + h*DHEAD;

    // stage Q (fp32 bits) into Ps
    #pragma unroll
    for (int i = 0; i < 8; i++) {
        int idx = t + i*128, s = idx >> 4, dg = idx & 15;
        float4 v = *(const float4*)(Qb + (size_t)(q0+s)*qstride + dg*4);
        uint32_t* dst = Ps + s*PSS + dg*4;
        dst[0]=__float_as_uint(v.x); dst[1]=__float_as_uint(v.y);
        dst[2]=__float_as_uint(v.z); dst[3]=__float_as_uint(v.w);
    }
    __syncthreads();
    int m0 = w*16;
    uint32_t qf[8][4];
    #pragma unroll
    for (int ks = 0; ks < 8; ks++) {
        qf[ks][0] = f2tf32(__uint_as_float(Ps[(m0+r4)*PSS   + ks*8 + l4]));
        qf[ks][1] = f2tf32(__uint_as_float(Ps[(m0+r4+8)*PSS + ks*8 + l4]));
        qf[ks][2] = f2tf32(__uint_as_float(Ps[(m0+r4)*PSS   + ks*8 + 4 + l4]));
        qf[ks][3] = f2tf32(__uint_as_float(Ps[(m0+r4+8)*PSS + ks*8 + 4 + l4]));
    }

    float oacc[8][4];
    #pragma unroll
    for (int j = 0; j < 8; j++)
        #pragma unroll
        for (int c = 0; c < 4; c++) oacc[j][c] = 0.f;
    float mrA = -1e30f, mrB = -1e30f, lrA = 0.f, lrB = 0.f;

    int qcnk = q0 >> 6;
    int nchunks = causal ? (qcnk + 1) : (SEQ/64);
    int qA = q0 + m0 + r4, qB = qA + 8;

    for (int kt = 0; kt < nchunks; kt++) {
        __syncthreads();   // prior-iteration readers done before overwrite
        #pragma unroll
        for (int i = 0; i < 8; i++) {
            int idx = t + i*128, s = idx >> 4, dg = idx & 15;
            float4 kv = *(const float4*)(Kb + (size_t)(kt*64+s)*kvstride + dg*4);
            uint32_t* kd = Ks + s*KSS + dg*4;
            kd[0]=f2tf32(kv.x); kd[1]=f2tf32(kv.y); kd[2]=f2tf32(kv.z); kd[3]=f2tf32(kv.w);
            float4 vv = *(const float4*)(Vb + (size_t)(kt*64+s)*kvstride + dg*4);
            uint32_t* vd = Vs + s*KSS + dg*4;
            vd[0]=f2tf32(vv.x); vd[1]=f2tf32(vv.y); vd[2]=f2tf32(vv.z); vd[3]=f2tf32(vv.w);
        }
        if (t < 64) maskv[t] = (mtok[b*SEQ + kt*64 + t] != 0);
        __syncthreads();

        // ---- S = Q K^T for warp's 16 q rows x 64 k cols ----
        float sacc[8][4];
        #pragma unroll
        for (int j = 0; j < 8; j++)
            #pragma unroll
            for (int c = 0; c < 4; c++) sacc[j][c] = 0.f;
        #pragma unroll
        for (int j = 0; j < 8; j++) {
            #pragma unroll
            for (int ks = 0; ks < 8; ks++) {
                uint32_t bf[2];
                bf[0] = Ks[(j*8 + r4)*KSS + ks*8 + l4];
                bf[1] = Ks[(j*8 + r4)*KSS + ks*8 + 4 + l4];
                mma_tf32(sacc[j], qf[ks], bf);
            }
        }
        // ---- mask + scale + row max ----
        bool diag = causal && (kt == qcnk);
        float mA = -1e30f, mB = -1e30f;
        #pragma unroll
        for (int j = 0; j < 8; j++) {
            int kl = j*8 + 2*l4;
            int kg = kt*64 + kl;
            bool pv0 = maskv[kl] != 0, pv1 = maskv[kl+1] != 0;
            bool a0 = pv0 && (!diag || kg   <= qA);
            bool a1 = pv1 && (!diag || kg+1 <= qA);
            bool b0 = pv0 && (!diag || kg   <= qB);
            bool b1 = pv1 && (!diag || kg+1 <= qB);
            sacc[j][0] = a0 ? sacc[j][0]*0.125f : -1e9f;
            sacc[j][1] = a1 ? sacc[j][1]*0.125f : -1e9f;
            sacc[j][2] = b0 ? sacc[j][2]*0.125f : -1e9f;
            sacc[j][3] = b1 ? sacc[j][3]*0.125f : -1e9f;
            mA = fmaxf(mA, fmaxf(sacc[j][0], sacc[j][1]));
            mB = fmaxf(mB, fmaxf(sacc[j][2], sacc[j][3]));
        }
        mA = fmaxf(mA, __shfl_xor_sync(0xffffffffu, mA, 1));
        mA = fmaxf(mA, __shfl_xor_sync(0xffffffffu, mA, 2));
        mB = fmaxf(mB, __shfl_xor_sync(0xffffffffu, mB, 1));
        mB = fmaxf(mB, __shfl_xor_sync(0xffffffffu, mB, 2));
        float mnA = fmaxf(mrA, mA), mnB = fmaxf(mrB, mB);
        float aA = __expf(mrA - mnA), aB = __expf(mrB - mnB);
        mrA = mnA; mrB = mnB;
        // ---- exp + write P + row sums ----
        float lA = 0.f, lB = 0.f;
        #pragma unroll
        for (int j = 0; j < 8; j++) {
            float p0 = __expf(sacc[j][0] - mnA);
            float p1 = __expf(sacc[j][1] - mnA);
            float p2 = __expf(sacc[j][2] - mnB);
            float p3 = __expf(sacc[j][3] - mnB);
            lA += p0 + p1; lB += p2 + p3;
            uint32_t* pr0 = Ps + (m0 + r4)*PSS + j*8 + 2*l4;
            pr0[0] = f2tf32(p0); pr0[1] = f2tf32(p1);
            uint32_t* pr1 = Ps + (m0 + r4 + 8)*PSS + j*8 + 2*l4;
            pr1[0] = f2tf32(p2); pr1[1] = f2tf32(p3);
        }
        lA += __shfl_xor_sync(0xffffffffu, lA, 1);
        lA += __shfl_xor_sync(0xffffffffu, lA, 2);
        lB += __shfl_xor_sync(0xffffffffu, lB, 1);
        lB += __shfl_xor_sync(0xffffffffu, lB, 2);
        lrA = lrA*aA + lA;
        lrB = lrB*aB + lB;
        if (l4 == 0) {
            alphas[m0 + r4]     = aA;
            alphas[m0 + r4 + 8] = aB;
            if (kt == nchunks - 1) {
                linv[m0 + r4]     = 1.f / lrA;
                linv[m0 + r4 + 8] = 1.f / lrB;
            }
        }
        __syncthreads();

        // ---- PV: O^T[d,q] += V^T[d,s] P^T[s,q]; warp d-tile [m0, m0+16) ----
        #pragma unroll
        for (int j = 0; j < 8; j++) {
            float a0 = alphas[j*8 + 2*l4];
            float a1 = alphas[j*8 + 2*l4 + 1];
            oacc[j][0] *= a0; oacc[j][1] *= a1;
            oacc[j][2] *= a0; oacc[j][3] *= a1;
        }
        #pragma unroll
        for (int ks2 = 0; ks2 < 8; ks2++) {
            uint32_t af[4];
            af[0] = Vs[(ks2*8 + l4)*KSS     + m0 + r4];
            af[1] = Vs[(ks2*8 + l4)*KSS     + m0 + r4 + 8];
            af[2] = Vs[(ks2*8 + l4 + 4)*KSS + m0 + r4];
            af[3] = Vs[(ks2*8 + l4 + 4)*KSS + m0 + r4 + 8];
            #pragma unroll
            for (int j = 0; j < 8; j++) {
                uint32_t bf[2];
                bf[0] = Ps[(j*8 + r4)*PSS + ks2*8 + l4];
                bf[1] = Ps[(j*8 + r4)*PSS + ks2*8 + 4 + l4];
                mma_tf32(oacc[j], af, bf);
            }
        }
    }

    // ---- output: O[b, q, h*64 + d] = O^T[d,q] * linv[q] ----
    #pragma unroll
    for (int j = 0; j < 8; j++) {
        int qc2 = j*8 + 2*l4;
        float i0 = linv[qc2], i1 = linv[qc2 + 1];
        int d0 = m0 + r4;
        size_t ro0 = ((size_t)b*SEQ + q0 + qc2)*DMODEL + h*DHEAD;
        size_t ro1 = ro0 + DMODEL;
        Op[ro0 + d0]     = oacc[j][0]*i0;
        Op[ro1 + d0]     = oacc[j][1]*i1;
        Op[ro0 + d0 + 8] = oacc[j][2]*i0;
        Op[ro1 + d0 + 8] = oacc[j][3]*i1;
    }
}

// ---------------------------------------------------------------------------
// Orchestration
// ---------------------------------------------------------------------------
static inline void launch_gemm(const float* A, const float* W, const float* bias,
                               const float* res, float* C, int M, int N, int K,
                               bool relu) {
    dim3 grid(N/128, M/128), block(256);
    if (res) {
        cudaFuncSetAttribute(gemm_mma<false,true,true>, cudaFuncAttributeMaxDynamicSharedMemorySize, GEMM_SMEM);
        gemm_mma<false,true,true><<<grid, block, GEMM_SMEM>>>(A, W, bias, res, C, M, N, K);
    } else if (relu) {
        cudaFuncSetAttribute(gemm_mma<true,false,true>, cudaFuncAttributeMaxDynamicSharedMemorySize, GEMM_SMEM);
        gemm_mma<true,false,true><<<grid, block, GEMM_SMEM>>>(A, W, bias, nullptr, C, M, N, K);
    } else if (bias) {
        cudaFuncSetAttribute(gemm_mma<false,false,true>, cudaFuncAttributeMaxDynamicSharedMemorySize, GEMM_SMEM);
        gemm_mma<false,false,true><<<grid, block, GEMM_SMEM>>>(A, W, bias, nullptr, C, M, N, K);
    } else {
        cudaFuncSetAttribute(gemm_mma<false,false,false>, cudaFuncAttributeMaxDynamicSharedMemorySize, GEMM_SMEM);
        gemm_mma<false,false,false><<<grid, block, GEMM_SMEM>>>(A, W, nullptr, nullptr, C, M, N, K);
    }
}

extern "C" void kernel_launch(void* const* d_in, const int* in_sizes, int n_in,
                              void* d_out, int out_size) {
    const int*   src        = (const int*)  d_in[0];
    const int*   tgt        = (const int*)  d_in[1];
    const float* emb        = (const float*)d_in[2];
    const float* enc_attn_w = (const float*)d_in[3];
    const float* enc_attn_b = (const float*)d_in[4];
    const float* enc_ln_g   = (const float*)d_in[5];
    const float* enc_ln_b   = (const float*)d_in[6];
    const float* enc_w1     = (const float*)d_in[7];
    const float* enc_b1     = (const float*)d_in[8];
    const float* enc_w2     = (const float*)d_in[9];
    const float* enc_b2     = (const float*)d_in[10];
    const float* dec_attn_w = (const float*)d_in[11];
    const float* dec_attn_b = (const float*)d_in[12];
    const float* dec_ln_g   = (const float*)d_in[13];
    const float* dec_ln_b   = (const float*)d_in[14];
    const float* dec_w1     = (const float*)d_in[15];
    const float* dec_b1     = (const float*)d_in[16];
    const float* dec_w2     = (const float*)d_in[17];
    const float* dec_b2     = (const float*)d_in[18];
    const float* enc_norm_g = (const float*)d_in[19];
    const float* enc_norm_b = (const float*)d_in[20];
    const float* dec_norm_g = (const float*)d_in[21];
    const float* dec_norm_b = (const float*)d_in[22];

    float *x, *x2, *qb, *ctx, *enc, *hbuf, *qkv, *kv;
    cudaGetSymbolAddress((void**)&x,    g_x);
    cudaGetSymbolAddress((void**)&x2,   g_x2);
    cudaGetSymbolAddress((void**)&qb,   g_q);
    cudaGetSymbolAddress((void**)&ctx,  g_ctx);
    cudaGetSymbolAddress((void**)&enc,  g_enc);
    cudaGetSymbolAddress((void**)&hbuf, g_h);
    cudaGetSymbolAddress((void**)&qkv,  g_qkv);
    cudaGetSymbolAddress((void**)&kv,   g_kv);

    cudaFuncSetAttribute(attn_mma, cudaFuncAttributeMaxDynamicSharedMemorySize, ATTN_SMEM);

    const int D = DMODEL, M = MROWS;
    const size_t WSZ = (size_t)D*D;
    dim3 attnGrid(SEQ/64, NHEAD, BATCH);

    // ===================== ENCODER =====================
    embed_kernel<<<M, 128>>>(src, emb, x);
    for (int l = 0; l < NLAYER; l++) {
        const float* w  = enc_attn_w + (size_t)l*4*WSZ;
        const float* bb = enc_attn_b + (size_t)l*4*D;
        ln_kernel<<<M, 128>>>(x, enc_ln_g + (size_t)(l*2+0)*D, enc_ln_b + (size_t)(l*2+0)*D, x2);
        launch_gemm(x2, w, bb, nullptr, qkv, M, 3*D, D, false);
        attn_mma<<<attnGrid, 128, ATTN_SMEM>>>(qkv, 3*D, qkv + D, qkv + 2*D, 3*D, ctx, src, 0);
        launch_gemm(ctx, w + 3*WSZ, bb + 3*D, x, x, M, D, D, false);
        ln_kernel<<<M, 128>>>(x, enc_ln_g + (size_t)(l*2+1)*D, enc_ln_b + (size_t)(l*2+1)*D, x2);
        launch_gemm(x2, enc_w1 + (size_t)l*DFF*D, enc_b1 + (size_t)l*DFF, nullptr, hbuf, M, DFF, D, true);
        launch_gemm(hbuf, enc_w2 + (size_t)l*D*DFF, enc_b2 + (size_t)l*D, x, x, M, D, DFF, false);
    }
    ln_kernel<<<M, 128>>>(x, enc_norm_g, enc_norm_b, enc);

    // ===================== DECODER =====================
    embed_kernel<<<M, 128>>>(tgt, emb, x);
    for (int l = 0; l < NLAYER; l++) {
        const float* w  = dec_attn_w + (size_t)l*8*WSZ;
        const float* bb = dec_attn_b + (size_t)l*8*D;
        ln_kernel<<<M, 128>>>(x, dec_ln_g + (size_t)(l*3+0)*D, dec_ln_b + (size_t)(l*3+0)*D, x2);
        launch_gemm(x2, w, bb, nullptr, qkv, M, 3*D, D, false);
        attn_mma<<<attnGrid, 128, ATTN_SMEM>>>(qkv, 3*D, qkv + D, qkv + 2*D, 3*D, ctx, tgt, 1);
        launch_gemm(ctx, w + 3*WSZ, bb + 3*D, x, x, M, D, D, false);
        ln_kernel<<<M, 128>>>(x, dec_ln_g + (size_t)(l*3+1)*D, dec_ln_b + (size_t)(l*3+1)*D, x2);
        launch_gemm(x2,  w + 4*WSZ, bb + 4*D, nullptr, qb, M, D, D, false);
        launch_gemm(enc, w + 5*WSZ, bb + 5*D, nullptr, kv, M, 2*D, D, false);
        attn_mma<<<attnGrid, 128, ATTN_SMEM>>>(qb, D, kv, kv + D, 2*D, ctx, src, 0);
        launch_gemm(ctx, w + 7*WSZ, bb + 7*D, x, x, M, D, D, false);
        ln_kernel<<<M, 128>>>(x, dec_ln_g + (size_t)(l*3+2)*D, dec_ln_b + (size_t)(l*3+2)*D, x2);
        launch_gemm(x2, dec_w1 + (size_t)l*DFF*D, dec_b1 + (size_t)l*DFF, nullptr, hbuf, M, DFF, D, true);
        launch_gemm(hbuf, dec_w2 + (size_t)l*D*DFF, dec_b2 + (size_t)l*D, x, x, M, D, DFF, false);
    }
    ln_kernel<<<M, 128>>>(x, dec_norm_g, dec_norm_b, x2);

    // ===================== tied output projection =====================
    launch_gemm(x2, emb, nullptr, nullptr, (float*)d_out, M, VOCAB, D, false);
}

// round 5
// speedup vs baseline: 7.2203x; 1.5662x over previous
#include <cuda_runtime.h>
#include <cuda_bf16.h>
#include <cstdint>
#include <math.h>

// ---------------------------------------------------------------------------
// Problem constants
// ---------------------------------------------------------------------------
#define BATCH 8
#define SEQ   512
#define DMODEL 512
#define NHEAD 8
#define DHEAD 64
#define NLAYER 4
#define DFF   2048
#define VOCAB 32000
#define MROWS (BATCH*SEQ)   // 4096

__device__ __forceinline__ uint32_t f2tf32(float x) {
    uint32_t r; asm("cvt.rna.tf32.f32 %0, %1;" : "=r"(r) : "f"(x)); return r;
}
__device__ __forceinline__ uint32_t smem_u32(const void* p) {
    uint32_t a;
    asm("{ .reg .u64 t; cvta.to.shared.u64 t, %1; cvt.u32.u64 %0, t; }" : "=r"(a) : "l"(p));
    return a;
}
__device__ __forceinline__ void cp16(uint32_t s, const void* g) {
    asm volatile("cp.async.cg.shared.global [%0], [%1], 16;" :: "r"(s), "l"(g));
}
#define CP_COMMIT() asm volatile("cp.async.commit_group;" ::: "memory")
template<int N> __device__ __forceinline__ void cp_wait() {
    asm volatile("cp.async.wait_group %0;" :: "n"(N) : "memory");
}

__device__ __forceinline__ void mma_tf32(float* c, const uint32_t* a, const uint32_t* b) {
    asm volatile(
        "mma.sync.aligned.m16n8k8.row.col.f32.tf32.tf32.f32 "
        "{%0,%1,%2,%3}, {%4,%5,%6,%7}, {%8,%9}, {%0,%1,%2,%3};"
        : "+f"(c[0]), "+f"(c[1]), "+f"(c[2]), "+f"(c[3])
        : "r"(a[0]), "r"(a[1]), "r"(a[2]), "r"(a[3]), "r"(b[0]), "r"(b[1]));
}

// ---------------------------------------------------------------------------
// Scratch (device globals; no allocation allowed)
// ---------------------------------------------------------------------------
__device__ __align__(16) float g_x  [MROWS*DMODEL];
__device__ __align__(16) float g_x2 [MROWS*DMODEL];
__device__ __align__(16) float g_q  [MROWS*DMODEL];
__device__ __align__(16) float g_ctx[MROWS*DMODEL];
__device__ __align__(16) float g_enc[MROWS*DMODEL];
__device__ __align__(16) float g_h  [MROWS*DFF];
__device__ __align__(16) float g_qkv[MROWS*3*DMODEL];
__device__ __align__(16) float g_kv [MROWS*2*DMODEL];

// converted-weight arena (tf32 bits)
#define OFF_ENC_ATTN 0
#define OFF_ENC_W1   (OFF_ENC_ATTN + NLAYER*4*DMODEL*DMODEL)
#define OFF_ENC_W2   (OFF_ENC_W1   + NLAYER*DFF*DMODEL)
#define OFF_DEC_ATTN (OFF_ENC_W2   + NLAYER*DMODEL*DFF)
#define OFF_DEC_W1   (OFF_DEC_ATTN + NLAYER*8*DMODEL*DMODEL)
#define OFF_DEC_W2   (OFF_DEC_W1   + NLAYER*DFF*DMODEL)
#define OFF_EMB      (OFF_DEC_W2   + NLAYER*DMODEL*DFF)
#define W_TOTAL      (OFF_EMB      + VOCAB*DMODEL)
__device__ __align__(16) uint32_t g_w[W_TOTAL];

// ---------------------------------------------------------------------------
// fp32 -> tf32-bits conversion (vectorized)
// ---------------------------------------------------------------------------
__global__ void cvt_kernel(const float* __restrict__ in, uint32_t* __restrict__ out, int n) {
    int i = (blockIdx.x*blockDim.x + threadIdx.x)*4;
    if (i < n) {
        float4 v = *(const float4*)(in + i);
        uint4 o;
        o.x = f2tf32(v.x); o.y = f2tf32(v.y); o.z = f2tf32(v.z); o.w = f2tf32(v.w);
        *(uint4*)(out + i) = o;
    }
}

// ---------------------------------------------------------------------------
// Embedding + sinusoidal positional encoding (residual stream, fp32)
// ---------------------------------------------------------------------------
__global__ void embed_kernel(const int* __restrict__ tok,
                             const float* __restrict__ emb,
                             float* __restrict__ y) {
    int row = blockIdx.x;
    int s   = row % SEQ;
    int t   = tok[row];
    const float scale = 22.62741699796952f;
    const float c0 = -9.210340371976184f / (float)DMODEL;
    int tid = threadIdx.x;
    #pragma unroll
    for (int i = 0; i < 4; i++) {
        int d = tid + i*128;
        float e = (t == 0) ? 0.f : emb[(size_t)t*DMODEL + d];
        int half = d >> 1;
        float div = expf((float)(2*half) * c0);
        float ang = (float)s * div;
        float pe = (d & 1) ? cosf(ang) : sinf(ang);
        y[(size_t)row*DMODEL + d] = e*scale + pe;
    }
}

// ---------------------------------------------------------------------------
// LayerNorm over last dim (D=512). Output written as tf32 bits (feeds GEMM A).
// ---------------------------------------------------------------------------
__global__ void ln_kernel(const float* __restrict__ x,
                          const float* __restrict__ g,
                          const float* __restrict__ b,
                          float* __restrict__ y) {
    int row = blockIdx.x;
    const float* xr = x + (size_t)row*DMODEL;
    int t = threadIdx.x;
    float v[4];
    float s = 0.f;
    #pragma unroll
    for (int i = 0; i < 4; i++) { v[i] = xr[t + i*128]; s += v[i]; }
    __shared__ float red[4];
    #pragma unroll
    for (int o = 16; o > 0; o >>= 1) s += __shfl_xor_sync(0xffffffffu, s, o);
    if ((t & 31) == 0) red[t >> 5] = s;
    __syncthreads();
    float mean = (red[0]+red[1]+red[2]+red[3]) * (1.f/(float)DMODEL);
    float vs = 0.f;
    #pragma unroll
    for (int i = 0; i < 4; i++) { float d = v[i]-mean; vs += d*d; }
    #pragma unroll
    for (int o = 16; o > 0; o >>= 1) vs += __shfl_xor_sync(0xffffffffu, vs, o);
    __syncthreads();
    if ((t & 31) == 0) red[t >> 5] = vs;
    __syncthreads();
    float var = (red[0]+red[1]+red[2]+red[3]) * (1.f/(float)DMODEL);
    float inv = rsqrtf(var + 1e-5f);
    #pragma unroll
    for (int i = 0; i < 4; i++) {
        int d = t + i*128;
        float val = (v[i]-mean)*inv*g[d] + b[d];
        y[(size_t)row*DMODEL + d] = __uint_as_float(f2tf32(val));
    }
}

// ---------------------------------------------------------------------------
// tf32 mma.sync GEMM with cp.async 3-stage pipeline.
// A, W already tf32 bits. C[M,N] = A[M,K] W[N,K]^T (+bias)(+relu)(+res).
// CTA 128x128x32, 256 thr, 8 warps (2M x 4N), warp tile 64x32.
// smem per tile: [m][k] rows of 32 words padded to 36 (conflict-free frags).
// ---------------------------------------------------------------------------
#define TSTR 36
#define TILE_WORDS (128*TSTR)             // 4608
#define GEMM_SMEM (3*2*TILE_WORDS*4)      // 110592 bytes

template<bool RELU, bool RES, bool BIAS, bool OTF32>
__global__ __launch_bounds__(256)
void gemm_mma(const uint32_t* __restrict__ A, const uint32_t* __restrict__ W,
              const float* __restrict__ bias, const float* __restrict__ res,
              float* __restrict__ C, int M, int N, int K) {
    extern __shared__ uint32_t sm[];
    int t = threadIdx.x, lane = t & 31, wid = t >> 5;
    int wm = (wid & 1) * 64;
    int wn = (wid >> 1) * 32;
    int r4 = lane >> 2, l4 = lane & 3;

    const uint32_t* Ab = A + (size_t)blockIdx.y*128*K;
    const uint32_t* Wb = W + (size_t)blockIdx.x*128*K;
    uint32_t sbase = smem_u32(sm);

    float acc[4][4][4];
    #pragma unroll
    for (int i = 0; i < 4; i++)
        #pragma unroll
        for (int j = 0; j < 4; j++)
            #pragma unroll
            for (int c = 0; c < 4; c++) acc[i][j][c] = 0.f;

    int NK = K >> 5;

    // tile issue: 1024 16B-chunks per matrix, 4 per thread
    auto issue = [&](int it, int buf) {
        uint32_t base = sbase + (uint32_t)buf*2*TILE_WORDS*4;
        int k0 = it*32;
        #pragma unroll
        for (int i = 0; i < 4; i++) {
            int idx = t + i*256, r = idx >> 3, ch = idx & 7;
            uint32_t off = (uint32_t)(r*TSTR + ch*4)*4;
            cp16(base + off,                  Ab + (size_t)r*K + k0 + ch*4);
            cp16(base + TILE_WORDS*4 + off,   Wb + (size_t)r*K + k0 + ch*4);
        }
        CP_COMMIT();
    };

    issue(0, 0);
    issue(1, 1);

    for (int it = 0; it < NK; it++) {
        if (it + 1 < NK) cp_wait<1>(); else cp_wait<0>();
        __syncthreads();
        if (it + 2 < NK) issue(it + 2, (it + 2) % 3);
        const uint32_t* sA = sm + (it % 3)*2*TILE_WORDS;
        const uint32_t* sB = sA + TILE_WORDS;
        #pragma unroll
        for (int ks = 0; ks < 4; ks++) {
            int kb = ks*8 + l4;
            uint32_t af[4][4], bf[4][2];
            #pragma unroll
            for (int mi = 0; mi < 4; mi++) {
                int m = wm + mi*16 + r4;
                af[mi][0] = sA[m*TSTR + kb];
                af[mi][1] = sA[(m+8)*TSTR + kb];
                af[mi][2] = sA[m*TSTR + kb + 4];
                af[mi][3] = sA[(m+8)*TSTR + kb + 4];
            }
            #pragma unroll
            for (int ni = 0; ni < 4; ni++) {
                int n = wn + ni*8 + r4;
                bf[ni][0] = sB[n*TSTR + kb];
                bf[ni][1] = sB[n*TSTR + kb + 4];
            }
            #pragma unroll
            for (int mi = 0; mi < 4; mi++)
                #pragma unroll
                for (int ni = 0; ni < 4; ni++)
                    mma_tf32(acc[mi][ni], af[mi], bf[ni]);
        }
        __syncthreads();
    }

    // epilogue
    int gm = blockIdx.y*128 + wm;
    int gn = blockIdx.x*128 + wn;
    #pragma unroll
    for (int mi = 0; mi < 4; mi++) {
        #pragma unroll
        for (int ni = 0; ni < 4; ni++) {
            int row = gm + mi*16 + r4;
            int col = gn + ni*8 + l4*2;
            float2 v0 = make_float2(acc[mi][ni][0], acc[mi][ni][1]);
            float2 v1 = make_float2(acc[mi][ni][2], acc[mi][ni][3]);
            if (BIAS) {
                float2 bv = *(const float2*)(bias + col);
                v0.x += bv.x; v0.y += bv.y; v1.x += bv.x; v1.y += bv.y;
            }
            if (RELU) {
                v0.x = fmaxf(v0.x, 0.f); v0.y = fmaxf(v0.y, 0.f);
                v1.x = fmaxf(v1.x, 0.f); v1.y = fmaxf(v1.y, 0.f);
            }
            if (RES) {
                float2 r0 = *(const float2*)(res + (size_t)row*N + col);
                float2 r1 = *(const float2*)(res + (size_t)(row+8)*N + col);
                v0.x += r0.x; v0.y += r0.y; v1.x += r1.x; v1.y += r1.y;
            }
            if (OTF32) {
                v0.x = __uint_as_float(f2tf32(v0.x)); v0.y = __uint_as_float(f2tf32(v0.y));
                v1.x = __uint_as_float(f2tf32(v1.x)); v1.y = __uint_as_float(f2tf32(v1.y));
            }
            *(float2*)(C + (size_t)row*N + col)     = v0;
            *(float2*)(C + (size_t)(row+8)*N + col) = v1;
        }
    }
}

// ---------------------------------------------------------------------------
// Flash-style mma attention (unchanged from R4 except tf32-bit output store).
// ---------------------------------------------------------------------------
#define KSS 68
#define PSS 76
#define KS_OFF 0
#define VS_OFF (64*KSS)
#define PS_OFF (2*64*KSS)
#define AL_OFF (PS_OFF + 64*PSS)
#define LI_OFF (AL_OFF + 64)
#define MK_OFF (LI_OFF + 64)
#define ATTN_SMEM ((MK_OFF + 64)*4)

__global__ __launch_bounds__(128)
void attn_mma(const float* __restrict__ Qp, int qstride,
              const float* __restrict__ Kp, const float* __restrict__ Vp, int kvstride,
              float* __restrict__ Op,
              const int* __restrict__ mtok, int causal) {
    extern __shared__ uint32_t smu[];
    uint32_t* Ks = smu + KS_OFF;
    uint32_t* Vs = smu + VS_OFF;
    uint32_t* Ps = smu + PS_OFF;
    float* alphas = (float*)(smu + AL_OFF);
    float* linv   = (float*)(smu + LI_OFF);
    uint32_t* maskv = smu + MK_OFF;

    int t = threadIdx.x, lane = t & 31, w = t >> 5;
    int r4 = lane >> 2, l4 = lane & 3;
    int q0 = blockIdx.x * 64, h = blockIdx.y, b = blockIdx.z;
    const float* Qb = Qp + (size_t)b*SEQ*qstride  + h*DHEAD;
    const float* Kb = Kp + (size_t)b*SEQ*kvstride + h*DHEAD;
    const float* Vb = Vp + (size_t)b*SEQ*kvstride + h*DHEAD;

    #pragma unroll
    for (int i = 0; i < 8; i++) {
        int idx = t + i*128, s = idx >> 4, dg = idx & 15;
        float4 v = *(const float4*)(Qb + (size_t)(q0+s)*qstride + dg*4);
        uint32_t* dst = Ps + s*PSS + dg*4;
        dst[0]=__float_as_uint(v.x); dst[1]=__float_as_uint(v.y);
        dst[2]=__float_as_uint(v.z); dst[3]=__float_as_uint(v.w);
    }
    __syncthreads();
    int m0 = w*16;
    uint32_t qf[8][4];
    #pragma unroll
    for (int ks = 0; ks < 8; ks++) {
        qf[ks][0] = f2tf32(__uint_as_float(Ps[(m0+r4)*PSS   + ks*8 + l4]));
        qf[ks][1] = f2tf32(__uint_as_float(Ps[(m0+r4+8)*PSS + ks*8 + l4]));
        qf[ks][2] = f2tf32(__uint_as_float(Ps[(m0+r4)*PSS   + ks*8 + 4 + l4]));
        qf[ks][3] = f2tf32(__uint_as_float(Ps[(m0+r4+8)*PSS + ks*8 + 4 + l4]));
    }

    float oacc[8][4];
    #pragma unroll
    for (int j = 0; j < 8; j++)
        #pragma unroll
        for (int c = 0; c < 4; c++) oacc[j][c] = 0.f;
    float mrA = -1e30f, mrB = -1e30f, lrA = 0.f, lrB = 0.f;

    int qcnk = q0 >> 6;
    int nchunks = causal ? (qcnk + 1) : (SEQ/64);
    int qA = q0 + m0 + r4, qB = qA + 8;

    for (int kt = 0; kt < nchunks; kt++) {
        __syncthreads();
        #pragma unroll
        for (int i = 0; i < 8; i++) {
            int idx = t + i*128, s = idx >> 4, dg = idx & 15;
            float4 kv = *(const float4*)(Kb + (size_t)(kt*64+s)*kvstride + dg*4);
            uint32_t* kd = Ks + s*KSS + dg*4;
            kd[0]=f2tf32(kv.x); kd[1]=f2tf32(kv.y); kd[2]=f2tf32(kv.z); kd[3]=f2tf32(kv.w);
            float4 vv = *(const float4*)(Vb + (size_t)(kt*64+s)*kvstride + dg*4);
            uint32_t* vd = Vs + s*KSS + dg*4;
            vd[0]=f2tf32(vv.x); vd[1]=f2tf32(vv.y); vd[2]=f2tf32(vv.z); vd[3]=f2tf32(vv.w);
        }
        if (t < 64) maskv[t] = (mtok[b*SEQ + kt*64 + t] != 0);
        __syncthreads();

        float sacc[8][4];
        #pragma unroll
        for (int j = 0; j < 8; j++)
            #pragma unroll
            for (int c = 0; c < 4; c++) sacc[j][c] = 0.f;
        #pragma unroll
        for (int j = 0; j < 8; j++) {
            #pragma unroll
            for (int ks = 0; ks < 8; ks++) {
                uint32_t bf[2];
                bf[0] = Ks[(j*8 + r4)*KSS + ks*8 + l4];
                bf[1] = Ks[(j*8 + r4)*KSS + ks*8 + 4 + l4];
                mma_tf32(sacc[j], qf[ks], bf);
            }
        }
        bool diag = causal && (kt == qcnk);
        float mA = -1e30f, mB = -1e30f;
        #pragma unroll
        for (int j = 0; j < 8; j++) {
            int kl = j*8 + 2*l4;
            int kg = kt*64 + kl;
            bool pv0 = maskv[kl] != 0, pv1 = maskv[kl+1] != 0;
            bool a0 = pv0 && (!diag || kg   <= qA);
            bool a1 = pv1 && (!diag || kg+1 <= qA);
            bool b0 = pv0 && (!diag || kg   <= qB);
            bool b1 = pv1 && (!diag || kg+1 <= qB);
            sacc[j][0] = a0 ? sacc[j][0]*0.125f : -1e9f;
            sacc[j][1] = a1 ? sacc[j][1]*0.125f : -1e9f;
            sacc[j][2] = b0 ? sacc[j][2]*0.125f : -1e9f;
            sacc[j][3] = b1 ? sacc[j][3]*0.125f : -1e9f;
            mA = fmaxf(mA, fmaxf(sacc[j][0], sacc[j][1]));
            mB = fmaxf(mB, fmaxf(sacc[j][2], sacc[j][3]));
        }
        mA = fmaxf(mA, __shfl_xor_sync(0xffffffffu, mA, 1));
        mA = fmaxf(mA, __shfl_xor_sync(0xffffffffu, mA, 2));
        mB = fmaxf(mB, __shfl_xor_sync(0xffffffffu, mB, 1));
        mB = fmaxf(mB, __shfl_xor_sync(0xffffffffu, mB, 2));
        float mnA = fmaxf(mrA, mA), mnB = fmaxf(mrB, mB);
        float aA = __expf(mrA - mnA), aB = __expf(mrB - mnB);
        mrA = mnA; mrB = mnB;
        float lA = 0.f, lB = 0.f;
        #pragma unroll
        for (int j = 0; j < 8; j++) {
            float p0 = __expf(sacc[j][0] - mnA);
            float p1 = __expf(sacc[j][1] - mnA);
            float p2 = __expf(sacc[j][2] - mnB);
            float p3 = __expf(sacc[j][3] - mnB);
            lA += p0 + p1; lB += p2 + p3;
            uint32_t* pr0 = Ps + (m0 + r4)*PSS + j*8 + 2*l4;
            pr0[0] = f2tf32(p0); pr0[1] = f2tf32(p1);
            uint32_t* pr1 = Ps + (m0 + r4 + 8)*PSS + j*8 + 2*l4;
            pr1[0] = f2tf32(p2); pr1[1] = f2tf32(p3);
        }
        lA += __shfl_xor_sync(0xffffffffu, lA, 1);
        lA += __shfl_xor_sync(0xffffffffu, lA, 2);
        lB += __shfl_xor_sync(0xffffffffu, lB, 1);
        lB += __shfl_xor_sync(0xffffffffu, lB, 2);
        lrA = lrA*aA + lA;
        lrB = lrB*aB + lB;
        if (l4 == 0) {
            alphas[m0 + r4]     = aA;
            alphas[m0 + r4 + 8] = aB;
            if (kt == nchunks - 1) {
                linv[m0 + r4]     = 1.f / lrA;
                linv[m0 + r4 + 8] = 1.f / lrB;
            }
        }
        __syncthreads();

        #pragma unroll
        for (int j = 0; j < 8; j++) {
            float a0 = alphas[j*8 + 2*l4];
            float a1 = alphas[j*8 + 2*l4 + 1];
            oacc[j][0] *= a0; oacc[j][1] *= a1;
            oacc[j][2] *= a0; oacc[j][3] *= a1;
        }
        #pragma unroll
        for (int ks2 = 0; ks2 < 8; ks2++) {
            uint32_t af[4];
            af[0] = Vs[(ks2*8 + l4)*KSS     + m0 + r4];
            af[1] = Vs[(ks2*8 + l4)*KSS     + m0 + r4 + 8];
            af[2] = Vs[(ks2*8 + l4 + 4)*KSS + m0 + r4];
            af[3] = Vs[(ks2*8 + l4 + 4)*KSS + m0 + r4 + 8];
            #pragma unroll
            for (int j = 0; j < 8; j++) {
                uint32_t bf[2];
                bf[0] = Ps[(j*8 + r4)*PSS + ks2*8 + l4];
                bf[1] = Ps[(j*8 + r4)*PSS + ks2*8 + 4 + l4];
                mma_tf32(oacc[j], af, bf);
            }
        }
    }

    // output as tf32 bits (feeds out-projection GEMM A)
    #pragma unroll
    for (int j = 0; j < 8; j++) {
        int qc2 = j*8 + 2*l4;
        float i0 = linv[qc2], i1 = linv[qc2 + 1];
        int d0 = m0 + r4;
        size_t ro0 = ((size_t)b*SEQ + q0 + qc2)*DMODEL + h*DHEAD;
        size_t ro1 = ro0 + DMODEL;
        Op[ro0 + d0]     = __uint_as_float(f2tf32(oacc[j][0]*i0));
        Op[ro1 + d0]     = __uint_as_float(f2tf32(oacc[j][1]*i1));
        Op[ro0 + d0 + 8] = __uint_as_float(f2tf32(oacc[j][2]*i0));
        Op[ro1 + d0 + 8] = __uint_as_float(f2tf32(oacc[j][3]*i1));
    }
}

// ---------------------------------------------------------------------------
// Orchestration
// ---------------------------------------------------------------------------
static inline void launch_gemm(const void* A, const uint32_t* W, const float* bias,
                               const float* res, float* C, int M, int N, int K,
                               bool relu, bool otf32) {
    dim3 grid(N/128, M/128), block(256);
    const uint32_t* Au = (const uint32_t*)A;
    if (res) {
        cudaFuncSetAttribute(gemm_mma<false,true,true,false>, cudaFuncAttributeMaxDynamicSharedMemorySize, GEMM_SMEM);
        gemm_mma<false,true,true,false><<<grid, block, GEMM_SMEM>>>(Au, W, bias, res, C, M, N, K);
    } else if (relu) {
        cudaFuncSetAttribute(gemm_mma<true,false,true,true>, cudaFuncAttributeMaxDynamicSharedMemorySize, GEMM_SMEM);
        gemm_mma<true,false,true,true><<<grid, block, GEMM_SMEM>>>(Au, W, bias, nullptr, C, M, N, K);
    } else if (bias) {
        cudaFuncSetAttribute(gemm_mma<false,false,true,false>, cudaFuncAttributeMaxDynamicSharedMemorySize, GEMM_SMEM);
        gemm_mma<false,false,true,false><<<grid, block, GEMM_SMEM>>>(Au, W, bias, nullptr, C, M, N, K);
    } else {
        cudaFuncSetAttribute(gemm_mma<false,false,false,false>, cudaFuncAttributeMaxDynamicSharedMemorySize, GEMM_SMEM);
        gemm_mma<false,false,false,false><<<grid, block, GEMM_SMEM>>>(Au, W, nullptr, nullptr, C, M, N, K);
    }
}

extern "C" void kernel_launch(void* const* d_in, const int* in_sizes, int n_in,
                              void* d_out, int out_size) {
    const int*   src        = (const int*)  d_in[0];
    const int*   tgt        = (const int*)  d_in[1];
    const float* emb        = (const float*)d_in[2];
    const float* enc_attn_w = (const float*)d_in[3];
    const float* enc_attn_b = (const float*)d_in[4];
    const float* enc_ln_g   = (const float*)d_in[5];
    const float* enc_ln_b   = (const float*)d_in[6];
    const float* enc_w1     = (const float*)d_in[7];
    const float* enc_b1     = (const float*)d_in[8];
    const float* enc_w2     = (const float*)d_in[9];
    const float* enc_b2     = (const float*)d_in[10];
    const float* dec_attn_w = (const float*)d_in[11];
    const float* dec_attn_b = (const float*)d_in[12];
    const float* dec_ln_g   = (const float*)d_in[13];
    const float* dec_ln_b   = (const float*)d_in[14];
    const float* dec_w1     = (const float*)d_in[15];
    const float* dec_b1     = (const float*)d_in[16];
    const float* dec_w2     = (const float*)d_in[17];
    const float* dec_b2     = (const float*)d_in[18];
    const float* enc_norm_g = (const float*)d_in[19];
    const float* enc_norm_b = (const float*)d_in[20];
    const float* dec_norm_g = (const float*)d_in[21];
    const float* dec_norm_b = (const float*)d_in[22];

    float *x, *x2, *qb, *ctx, *enc, *hbuf, *qkv, *kv;
    uint32_t* wv;
    cudaGetSymbolAddress((void**)&x,    g_x);
    cudaGetSymbolAddress((void**)&x2,   g_x2);
    cudaGetSymbolAddress((void**)&qb,   g_q);
    cudaGetSymbolAddress((void**)&ctx,  g_ctx);
    cudaGetSymbolAddress((void**)&enc,  g_enc);
    cudaGetSymbolAddress((void**)&hbuf, g_h);
    cudaGetSymbolAddress((void**)&qkv,  g_qkv);
    cudaGetSymbolAddress((void**)&kv,   g_kv);
    cudaGetSymbolAddress((void**)&wv,   g_w);

    cudaFuncSetAttribute(attn_mma, cudaFuncAttributeMaxDynamicSharedMemorySize, ATTN_SMEM);

    // --------------- weight conversion (tf32 bits) ---------------
    {
        struct { const float* src; int off; int n; } cv[7] = {
            { enc_attn_w, OFF_ENC_ATTN, NLAYER*4*DMODEL*DMODEL },
            { enc_w1,     OFF_ENC_W1,   NLAYER*DFF*DMODEL },
            { enc_w2,     OFF_ENC_W2,   NLAYER*DMODEL*DFF },
            { dec_attn_w, OFF_DEC_ATTN, NLAYER*8*DMODEL*DMODEL },
            { dec_w1,     OFF_DEC_W1,   NLAYER*DFF*DMODEL },
            { dec_w2,     OFF_DEC_W2,   NLAYER*DMODEL*DFF },
            { emb,        OFF_EMB,      VOCAB*DMODEL },
        };
        for (int i = 0; i < 7; i++)
            cvt_kernel<<<cv[i].n/1024, 256>>>(cv[i].src, wv + cv[i].off, cv[i].n);
    }

    const int D = DMODEL, M = MROWS;
    const size_t WSZ = (size_t)D*D;
    dim3 attnGrid(SEQ/64, NHEAD, BATCH);
    const uint32_t* ew = wv + OFF_ENC_ATTN;
    const uint32_t* dw = wv + OFF_DEC_ATTN;

    // ===================== ENCODER =====================
    embed_kernel<<<M, 128>>>(src, emb, x);
    for (int l = 0; l < NLAYER; l++) {
        const uint32_t* w  = ew + (size_t)l*4*WSZ;
        const float*    bb = enc_attn_b + (size_t)l*4*D;
        ln_kernel<<<M, 128>>>(x, enc_ln_g + (size_t)(l*2+0)*D, enc_ln_b + (size_t)(l*2+0)*D, x2);
        launch_gemm(x2, w, bb, nullptr, qkv, M, 3*D, D, false, false);
        attn_mma<<<attnGrid, 128, ATTN_SMEM>>>(qkv, 3*D, qkv + D, qkv + 2*D, 3*D, ctx, src, 0);
        launch_gemm(ctx, w + 3*WSZ, bb + 3*D, x, x, M, D, D, false, false);
        ln_kernel<<<M, 128>>>(x, enc_ln_g + (size_t)(l*2+1)*D, enc_ln_b + (size_t)(l*2+1)*D, x2);
        launch_gemm(x2, wv + OFF_ENC_W1 + (size_t)l*DFF*D, enc_b1 + (size_t)l*DFF, nullptr, hbuf, M, DFF, D, true, false);
        launch_gemm(hbuf, wv + OFF_ENC_W2 + (size_t)l*D*DFF, enc_b2 + (size_t)l*D, x, x, M, D, DFF, false, false);
    }
    ln_kernel<<<M, 128>>>(x, enc_norm_g, enc_norm_b, enc);

    // ===================== DECODER =====================
    embed_kernel<<<M, 128>>>(tgt, emb, x);
    for (int l = 0; l < NLAYER; l++) {
        const uint32_t* w  = dw + (size_t)l*8*WSZ;
        const float*    bb = dec_attn_b + (size_t)l*8*D;
        ln_kernel<<<M, 128>>>(x, dec_ln_g + (size_t)(l*3+0)*D, dec_ln_b + (size_t)(l*3+0)*D, x2);
        launch_gemm(x2, w, bb, nullptr, qkv, M, 3*D, D, false, false);
        attn_mma<<<attnGrid, 128, ATTN_SMEM>>>(qkv, 3*D, qkv + D, qkv + 2*D, 3*D, ctx, tgt, 1);
        launch_gemm(ctx, w + 3*WSZ, bb + 3*D, x, x, M, D, D, false, false);
        ln_kernel<<<M, 128>>>(x, dec_ln_g + (size_t)(l*3+1)*D, dec_ln_b + (size_t)(l*3+1)*D, x2);
        launch_gemm(x2,  w + 4*WSZ, bb + 4*D, nullptr, qb, M, D, D, false, false);
        launch_gemm(enc, w + 5*WSZ, bb + 5*D, nullptr, kv, M, 2*D, D, false, false);
        attn_mma<<<attnGrid, 128, ATTN_SMEM>>>(qb, D, kv, kv + D, 2*D, ctx, src, 0);
        launch_gemm(ctx, w + 7*WSZ, bb + 7*D, x, x, M, D, D, false, false);
        ln_kernel<<<M, 128>>>(x, dec_ln_g + (size_t)(l*3+2)*D, dec_ln_b + (size_t)(l*3+2)*D, x2);
        launch_gemm(x2, wv + OFF_DEC_W1 + (size_t)l*DFF*D, dec_b1 + (size_t)l*DFF, nullptr, hbuf, M, DFF, D, true, false);
        launch_gemm(hbuf, wv + OFF_DEC_W2 + (size_t)l*D*DFF, dec_b2 + (size_t)l*D, x, x, M, D, DFF, false, false);
    }
    ln_kernel<<<M, 128>>>(x, dec_norm_g, dec_norm_b, x2);

    // ===================== tied output projection =====================
    launch_gemm(x2, wv + OFF_EMB, nullptr, nullptr, (float*)d_out, M, VOCAB, D, false, false);
}

// round 6
// speedup vs baseline: 10.5692x; 1.4638x over previous
#include <cuda_runtime.h>
#include <cuda_fp16.h>
#include <cstdint>
#include <math.h>

// ---------------------------------------------------------------------------
// Problem constants
// ---------------------------------------------------------------------------
#define BATCH 8
#define SEQ   512
#define DMODEL 512
#define NHEAD 8
#define DHEAD 64
#define NLAYER 4
#define DFF   2048
#define VOCAB 32000
#define MROWS (BATCH*SEQ)   // 4096

__device__ __forceinline__ uint32_t f2tf32(float x) {
    uint32_t r; asm("cvt.rna.tf32.f32 %0, %1;" : "=r"(r) : "f"(x)); return r;
}
__device__ __forceinline__ uint32_t smem_u32(const void* p) {
    uint32_t a;
    asm("{ .reg .u64 t; cvta.to.shared.u64 t, %1; cvt.u32.u64 %0, t; }" : "=r"(a) : "l"(p));
    return a;
}
__device__ __forceinline__ void cp16(uint32_t s, const void* g) {
    asm volatile("cp.async.cg.shared.global [%0], [%1], 16;" :: "r"(s), "l"(g));
}
#define CP_COMMIT() asm volatile("cp.async.commit_group;" ::: "memory")
template<int N> __device__ __forceinline__ void cp_wait() {
    asm volatile("cp.async.wait_group %0;" :: "n"(N) : "memory");
}
__device__ __forceinline__ void ldm_x4(uint32_t* r, uint32_t addr) {
    asm volatile("ldmatrix.sync.aligned.m8n8.x4.shared.b16 {%0,%1,%2,%3}, [%4];"
        : "=r"(r[0]), "=r"(r[1]), "=r"(r[2]), "=r"(r[3]) : "r"(addr));
}
__device__ __forceinline__ void mma_f16(float* c, const uint32_t* a, const uint32_t* b) {
    asm volatile(
        "mma.sync.aligned.m16n8k16.row.col.f32.f16.f16.f32 "
        "{%0,%1,%2,%3}, {%4,%5,%6,%7}, {%8,%9}, {%0,%1,%2,%3};"
        : "+f"(c[0]), "+f"(c[1]), "+f"(c[2]), "+f"(c[3])
        : "r"(a[0]), "r"(a[1]), "r"(a[2]), "r"(a[3]), "r"(b[0]), "r"(b[1]));
}
__device__ __forceinline__ void mma_tf32(float* c, const uint32_t* a, const uint32_t* b) {
    asm volatile(
        "mma.sync.aligned.m16n8k8.row.col.f32.tf32.tf32.f32 "
        "{%0,%1,%2,%3}, {%4,%5,%6,%7}, {%8,%9}, {%0,%1,%2,%3};"
        : "+f"(c[0]), "+f"(c[1]), "+f"(c[2]), "+f"(c[3])
        : "r"(a[0]), "r"(a[1]), "r"(a[2]), "r"(a[3]), "r"(b[0]), "r"(b[1]));
}

// ---------------------------------------------------------------------------
// Scratch (device globals; no allocation allowed)
// ---------------------------------------------------------------------------
__device__ __align__(16) float g_x  [MROWS*DMODEL];
__device__ __align__(16) __half g_x2 [MROWS*DMODEL];
__device__ __align__(16) float g_q  [MROWS*DMODEL];
__device__ __align__(16) __half g_ctx[MROWS*DMODEL];
__device__ __align__(16) __half g_enc[MROWS*DMODEL];
__device__ __align__(16) __half g_h  [MROWS*DFF];
__device__ __align__(16) float g_qkv[MROWS*3*DMODEL];
__device__ __align__(16) float g_kv [MROWS*2*DMODEL];

// converted-weight arena (fp16)
#define OFF_ENC_ATTN 0
#define OFF_ENC_W1   (OFF_ENC_ATTN + NLAYER*4*DMODEL*DMODEL)
#define OFF_ENC_W2   (OFF_ENC_W1   + NLAYER*DFF*DMODEL)
#define OFF_DEC_ATTN (OFF_ENC_W2   + NLAYER*DMODEL*DFF)
#define OFF_DEC_W1   (OFF_DEC_ATTN + NLAYER*8*DMODEL*DMODEL)
#define OFF_DEC_W2   (OFF_DEC_W1   + NLAYER*DFF*DMODEL)
#define OFF_EMB      (OFF_DEC_W2   + NLAYER*DMODEL*DFF)
#define W_TOTAL      (OFF_EMB      + VOCAB*DMODEL)
__device__ __align__(16) __half g_w[W_TOTAL];

// ---------------------------------------------------------------------------
// fp32 -> fp16 conversion (8 elems/thread, 16B stores)
// ---------------------------------------------------------------------------
__global__ void cvt_kernel(const float* __restrict__ in, __half* __restrict__ out, int n) {
    int i = (blockIdx.x*blockDim.x + threadIdx.x)*8;
    if (i < n) {
        float4 a = *(const float4*)(in + i);
        float4 b = *(const float4*)(in + i + 4);
        __half2 h0 = __floats2half2_rn(a.x, a.y);
        __half2 h1 = __floats2half2_rn(a.z, a.w);
        __half2 h2 = __floats2half2_rn(b.x, b.y);
        __half2 h3 = __floats2half2_rn(b.z, b.w);
        uint4 o;
        o.x = *(uint32_t*)&h0; o.y = *(uint32_t*)&h1;
        o.z = *(uint32_t*)&h2; o.w = *(uint32_t*)&h3;
        *(uint4*)(out + i) = o;
    }
}

// ---------------------------------------------------------------------------
// Embedding + sinusoidal positional encoding (residual stream, fp32)
// ---------------------------------------------------------------------------
__global__ void embed_kernel(const int* __restrict__ tok,
                             const float* __restrict__ emb,
                             float* __restrict__ y) {
    int row = blockIdx.x;
    int s   = row % SEQ;
    int t   = tok[row];
    const float scale = 22.62741699796952f;
    const float c0 = -9.210340371976184f / (float)DMODEL;
    int tid = threadIdx.x;
    #pragma unroll
    for (int i = 0; i < 4; i++) {
        int d = tid + i*128;
        float e = (t == 0) ? 0.f : emb[(size_t)t*DMODEL + d];
        int half = d >> 1;
        float div = expf((float)(2*half) * c0);
        float ang = (float)s * div;
        float pe = (d & 1) ? cosf(ang) : sinf(ang);
        y[(size_t)row*DMODEL + d] = e*scale + pe;
    }
}

// ---------------------------------------------------------------------------
// LayerNorm over last dim (D=512). Output fp16 (feeds GEMM A).
// ---------------------------------------------------------------------------
__global__ void ln_kernel(const float* __restrict__ x,
                          const float* __restrict__ g,
                          const float* __restrict__ b,
                          __half* __restrict__ y) {
    int row = blockIdx.x;
    const float* xr = x + (size_t)row*DMODEL;
    int t = threadIdx.x;
    float v[4];
    float s = 0.f;
    #pragma unroll
    for (int i = 0; i < 4; i++) { v[i] = xr[t + i*128]; s += v[i]; }
    __shared__ float red[4];
    #pragma unroll
    for (int o = 16; o > 0; o >>= 1) s += __shfl_xor_sync(0xffffffffu, s, o);
    if ((t & 31) == 0) red[t >> 5] = s;
    __syncthreads();
    float mean = (red[0]+red[1]+red[2]+red[3]) * (1.f/(float)DMODEL);
    float vs = 0.f;
    #pragma unroll
    for (int i = 0; i < 4; i++) { float d = v[i]-mean; vs += d*d; }
    #pragma unroll
    for (int o = 16; o > 0; o >>= 1) vs += __shfl_xor_sync(0xffffffffu, vs, o);
    __syncthreads();
    if ((t & 31) == 0) red[t >> 5] = vs;
    __syncthreads();
    float var = (red[0]+red[1]+red[2]+red[3]) * (1.f/(float)DMODEL);
    float inv = rsqrtf(var + 1e-5f);
    #pragma unroll
    for (int i = 0; i < 4; i++) {
        int d = t + i*128;
        float val = (v[i]-mean)*inv*g[d] + b[d];
        y[(size_t)row*DMODEL + d] = __float2half_rn(val);
    }
}

// ---------------------------------------------------------------------------
// fp16 mma.sync GEMM (m16n8k16, ldmatrix, cp.async 3-stage).
// A[M,K] half, W[N,K] half.  C = A W^T (+bias)(+relu)(+res), out fp32 or fp16.
// CTA 128x128x32, 256 thr, 8 warps (2M x 4N), warp tile 64x32.
// smem rows padded to 40 halfs (80B) -> conflict-free ldmatrix phases.
// ---------------------------------------------------------------------------
#define TSTR 40
#define TILE_HALFS (128*TSTR)             // 5120
#define STAGE_HALFS (2*TILE_HALFS)
#define GEMM_SMEM (3*STAGE_HALFS*2)       // 61440 bytes

template<bool RELU, bool RES, bool BIAS, bool OHALF>
__global__ __launch_bounds__(256, 2)
void gemm_mma(const __half* __restrict__ A, const __half* __restrict__ W,
              const float* __restrict__ bias, const float* __restrict__ res,
              void* __restrict__ Cv, int M, int N, int K) {
    extern __shared__ __half smh[];
    int t = threadIdx.x, lane = t & 31, wid = t >> 5;
    int wm = (wid & 1) * 64;
    int wn = (wid >> 1) * 32;
    int r4 = lane >> 2, l4 = lane & 3;

    const __half* Ab = A + (size_t)blockIdx.y*128*K;
    const __half* Wb = W + (size_t)blockIdx.x*128*K;
    uint32_t sbase = smem_u32(smh);

    float acc[4][4][4];
    #pragma unroll
    for (int i = 0; i < 4; i++)
        #pragma unroll
        for (int j = 0; j < 4; j++)
            #pragma unroll
            for (int c = 0; c < 4; c++) acc[i][j][c] = 0.f;

    int NK = K >> 5;

    auto issue = [&](int it, int buf) {
        uint32_t base = sbase + (uint32_t)buf*STAGE_HALFS*2;
        int k0 = it*32;
        #pragma unroll
        for (int i = 0; i < 2; i++) {
            int idx = t + i*256, r = idx >> 2, ch = idx & 3;
            uint32_t off = (uint32_t)(r*TSTR + ch*8)*2;
            cp16(base + off,                  Ab + (size_t)r*K + k0 + ch*8);
            cp16(base + TILE_HALFS*2 + off,   Wb + (size_t)r*K + k0 + ch*8);
        }
        CP_COMMIT();
    };

    issue(0, 0);
    issue(1, 1);

    // ldmatrix lane address components
    int a_row = (lane & 15);            // within 16-row block
    int a_kh8 = (lane >> 4) * 8;        // +8 halfs for k upper half
    int b_row = (lane & 7) + ((lane >> 4) & 1) * 8;  // n row within 16
    int b_kh8 = ((lane >> 3) & 1) * 8;

    for (int it = 0; it < NK; it++) {
        if (it + 1 < NK) cp_wait<1>(); else cp_wait<0>();
        __syncthreads();
        if (it + 2 < NK) issue(it + 2, (it + 2) % 3);
        uint32_t sA = sbase + (uint32_t)(it % 3)*STAGE_HALFS*2;
        uint32_t sB = sA + TILE_HALFS*2;
        #pragma unroll
        for (int kh = 0; kh < 2; kh++) {
            uint32_t af[4][4], bf[2][4];
            #pragma unroll
            for (int mi = 0; mi < 4; mi++)
                ldm_x4(af[mi], sA + (uint32_t)((wm + mi*16 + a_row)*TSTR + kh*16 + a_kh8)*2);
            #pragma unroll
            for (int nb = 0; nb < 2; nb++)
                ldm_x4(bf[nb], sB + (uint32_t)((wn + nb*16 + b_row)*TSTR + kh*16 + b_kh8)*2);
            #pragma unroll
            for (int mi = 0; mi < 4; mi++) {
                #pragma unroll
                for (int ni = 0; ni < 4; ni++)
                    mma_f16(acc[mi][ni], af[mi], bf[ni >> 1] + (ni & 1)*2);
            }
        }
    }

    // epilogue
    int gm = blockIdx.y*128 + wm;
    int gn = blockIdx.x*128 + wn;
    #pragma unroll
    for (int mi = 0; mi < 4; mi++) {
        #pragma unroll
        for (int ni = 0; ni < 4; ni++) {
            int row = gm + mi*16 + r4;
            int col = gn + ni*8 + l4*2;
            float2 v0 = make_float2(acc[mi][ni][0], acc[mi][ni][1]);
            float2 v1 = make_float2(acc[mi][ni][2], acc[mi][ni][3]);
            if (BIAS) {
                float2 bv = *(const float2*)(bias + col);
                v0.x += bv.x; v0.y += bv.y; v1.x += bv.x; v1.y += bv.y;
            }
            if (RELU) {
                v0.x = fmaxf(v0.x, 0.f); v0.y = fmaxf(v0.y, 0.f);
                v1.x = fmaxf(v1.x, 0.f); v1.y = fmaxf(v1.y, 0.f);
            }
            if (RES) {
                float2 r0 = *(const float2*)(res + (size_t)row*N + col);
                float2 r1 = *(const float2*)(res + (size_t)(row+8)*N + col);
                v0.x += r0.x; v0.y += r0.y; v1.x += r1.x; v1.y += r1.y;
            }
            if (OHALF) {
                __half* C = (__half*)Cv;
                __half2 h0 = __floats2half2_rn(v0.x, v0.y);
                __half2 h1 = __floats2half2_rn(v1.x, v1.y);
                *(__half2*)(C + (size_t)row*N + col)     = h0;
                *(__half2*)(C + (size_t)(row+8)*N + col) = h1;
            } else {
                float* C = (float*)Cv;
                *(float2*)(C + (size_t)row*N + col)     = v0;
                *(float2*)(C + (size_t)(row+8)*N + col) = v1;
            }
        }
    }
}

// ---------------------------------------------------------------------------
// Flash-style tf32 mma attention (R4 design); output stored fp16.
// ---------------------------------------------------------------------------
#define KSS 68
#define PSS 76
#define KS_OFF 0
#define VS_OFF (64*KSS)
#define PS_OFF (2*64*KSS)
#define AL_OFF (PS_OFF + 64*PSS)
#define LI_OFF (AL_OFF + 64)
#define MK_OFF (LI_OFF + 64)
#define ATTN_SMEM ((MK_OFF + 64)*4)

__global__ __launch_bounds__(128)
void attn_mma(const float* __restrict__ Qp, int qstride,
              const float* __restrict__ Kp, const float* __restrict__ Vp, int kvstride,
              __half* __restrict__ Op,
              const int* __restrict__ mtok, int causal) {
    extern __shared__ uint32_t smu[];
    uint32_t* Ks = smu + KS_OFF;
    uint32_t* Vs = smu + VS_OFF;
    uint32_t* Ps = smu + PS_OFF;
    float* alphas = (float*)(smu + AL_OFF);
    float* linv   = (float*)(smu + LI_OFF);
    uint32_t* maskv = smu + MK_OFF;

    int t = threadIdx.x, lane = t & 31, w = t >> 5;
    int r4 = lane >> 2, l4 = lane & 3;
    int q0 = blockIdx.x * 64, h = blockIdx.y, b = blockIdx.z;
    const float* Qb = Qp + (size_t)b*SEQ*qstride  + h*DHEAD;
    const float* Kb = Kp + (size_t)b*SEQ*kvstride + h*DHEAD;
    const float* Vb = Vp + (size_t)b*SEQ*kvstride + h*DHEAD;

    #pragma unroll
    for (int i = 0; i < 8; i++) {
        int idx = t + i*128, s = idx >> 4, dg = idx & 15;
        float4 v = *(const float4*)(Qb + (size_t)(q0+s)*qstride + dg*4);
        uint32_t* dst = Ps + s*PSS + dg*4;
        dst[0]=__float_as_uint(v.x); dst[1]=__float_as_uint(v.y);
        dst[2]=__float_as_uint(v.z); dst[3]=__float_as_uint(v.w);
    }
    __syncthreads();
    int m0 = w*16;
    uint32_t qf[8][4];
    #pragma unroll
    for (int ks = 0; ks < 8; ks++) {
        qf[ks][0] = f2tf32(__uint_as_float(Ps[(m0+r4)*PSS   + ks*8 + l4]));
        qf[ks][1] = f2tf32(__uint_as_float(Ps[(m0+r4+8)*PSS + ks*8 + l4]));
        qf[ks][2] = f2tf32(__uint_as_float(Ps[(m0+r4)*PSS   + ks*8 + 4 + l4]));
        qf[ks][3] = f2tf32(__uint_as_float(Ps[(m0+r4+8)*PSS + ks*8 + 4 + l4]));
    }

    float oacc[8][4];
    #pragma unroll
    for (int j = 0; j < 8; j++)
        #pragma unroll
        for (int c = 0; c < 4; c++) oacc[j][c] = 0.f;
    float mrA = -1e30f, mrB = -1e30f, lrA = 0.f, lrB = 0.f;

    int qcnk = q0 >> 6;
    int nchunks = causal ? (qcnk + 1) : (SEQ/64);
    int qA = q0 + m0 + r4, qB = qA + 8;

    for (int kt = 0; kt < nchunks; kt++) {
        __syncthreads();
        #pragma unroll
        for (int i = 0; i < 8; i++) {
            int idx = t + i*128, s = idx >> 4, dg = idx & 15;
            float4 kv = *(const float4*)(Kb + (size_t)(kt*64+s)*kvstride + dg*4);
            uint32_t* kd = Ks + s*KSS + dg*4;
            kd[0]=f2tf32(kv.x); kd[1]=f2tf32(kv.y); kd[2]=f2tf32(kv.z); kd[3]=f2tf32(kv.w);
            float4 vv = *(const float4*)(Vb + (size_t)(kt*64+s)*kvstride + dg*4);
            uint32_t* vd = Vs + s*KSS + dg*4;
            vd[0]=f2tf32(vv.x); vd[1]=f2tf32(vv.y); vd[2]=f2tf32(vv.z); vd[3]=f2tf32(vv.w);
        }
        if (t < 64) maskv[t] = (mtok[b*SEQ + kt*64 + t] != 0);
        __syncthreads();

        float sacc[8][4];
        #pragma unroll
        for (int j = 0; j < 8; j++)
            #pragma unroll
            for (int c = 0; c < 4; c++) sacc[j][c] = 0.f;
        #pragma unroll
        for (int j = 0; j < 8; j++) {
            #pragma unroll
            for (int ks = 0; ks < 8; ks++) {
                uint32_t bf[2];
                bf[0] = Ks[(j*8 + r4)*KSS + ks*8 + l4];
                bf[1] = Ks[(j*8 + r4)*KSS + ks*8 + 4 + l4];
                mma_tf32(sacc[j], qf[ks], bf);
            }
        }
        bool diag = causal && (kt == qcnk);
        float mA = -1e30f, mB = -1e30f;
        #pragma unroll
        for (int j = 0; j < 8; j++) {
            int kl = j*8 + 2*l4;
            int kg = kt*64 + kl;
            bool pv0 = maskv[kl] != 0, pv1 = maskv[kl+1] != 0;
            bool a0 = pv0 && (!diag || kg   <= qA);
            bool a1 = pv1 && (!diag || kg+1 <= qA);
            bool b0 = pv0 && (!diag || kg   <= qB);
            bool b1 = pv1 && (!diag || kg+1 <= qB);
            sacc[j][0] = a0 ? sacc[j][0]*0.125f : -1e9f;
            sacc[j][1] = a1 ? sacc[j][1]*0.125f : -1e9f;
            sacc[j][2] = b0 ? sacc[j][2]*0.125f : -1e9f;
            sacc[j][3] = b1 ? sacc[j][3]*0.125f : -1e9f;
            mA = fmaxf(mA, fmaxf(sacc[j][0], sacc[j][1]));
            mB = fmaxf(mB, fmaxf(sacc[j][2], sacc[j][3]));
        }
        mA = fmaxf(mA, __shfl_xor_sync(0xffffffffu, mA, 1));
        mA = fmaxf(mA, __shfl_xor_sync(0xffffffffu, mA, 2));
        mB = fmaxf(mB, __shfl_xor_sync(0xffffffffu, mB, 1));
        mB = fmaxf(mB, __shfl_xor_sync(0xffffffffu, mB, 2));
        float mnA = fmaxf(mrA, mA), mnB = fmaxf(mrB, mB);
        float aA = __expf(mrA - mnA), aB = __expf(mrB - mnB);
        mrA = mnA; mrB = mnB;
        float lA = 0.f, lB = 0.f;
        #pragma unroll
        for (int j = 0; j < 8; j++) {
            float p0 = __expf(sacc[j][0] - mnA);
            float p1 = __expf(sacc[j][1] - mnA);
            float p2 = __expf(sacc[j][2] - mnB);
            float p3 = __expf(sacc[j][3] - mnB);
            lA += p0 + p1; lB += p2 + p3;
            uint32_t* pr0 = Ps + (m0 + r4)*PSS + j*8 + 2*l4;
            pr0[0] = f2tf32(p0); pr0[1] = f2tf32(p1);
            uint32_t* pr1 = Ps + (m0 + r4 + 8)*PSS + j*8 + 2*l4;
            pr1[0] = f2tf32(p2); pr1[1] = f2tf32(p3);
        }
        lA += __shfl_xor_sync(0xffffffffu, lA, 1);
        lA += __shfl_xor_sync(0xffffffffu, lA, 2);
        lB += __shfl_xor_sync(0xffffffffu, lB, 1);
        lB += __shfl_xor_sync(0xffffffffu, lB, 2);
        lrA = lrA*aA + lA;
        lrB = lrB*aB + lB;
        if (l4 == 0) {
            alphas[m0 + r4]     = aA;
            alphas[m0 + r4 + 8] = aB;
            if (kt == nchunks - 1) {
                linv[m0 + r4]     = 1.f / lrA;
                linv[m0 + r4 + 8] = 1.f / lrB;
            }
        }
        __syncthreads();

        #pragma unroll
        for (int j = 0; j < 8; j++) {
            float a0 = alphas[j*8 + 2*l4];
            float a1 = alphas[j*8 + 2*l4 + 1];
            oacc[j][0] *= a0; oacc[j][1] *= a1;
            oacc[j][2] *= a0; oacc[j][3] *= a1;
        }
        #pragma unroll
        for (int ks2 = 0; ks2 < 8; ks2++) {
            uint32_t af[4];
            af[0] = Vs[(ks2*8 + l4)*KSS     + m0 + r4];
            af[1] = Vs[(ks2*8 + l4)*KSS     + m0 + r4 + 8];
            af[2] = Vs[(ks2*8 + l4 + 4)*KSS + m0 + r4];
            af[3] = Vs[(ks2*8 + l4 + 4)*KSS + m0 + r4 + 8];
            #pragma unroll
            for (int j = 0; j < 8; j++) {
                uint32_t bf[2];
                bf[0] = Ps[(j*8 + r4)*PSS + ks2*8 + l4];
                bf[1] = Ps[(j*8 + r4)*PSS + ks2*8 + 4 + l4];
                mma_tf32(oacc[j], af, bf);
            }
        }
    }

    // output fp16 (feeds out-projection GEMM A)
    #pragma unroll
    for (int j = 0; j < 8; j++) {
        int qc2 = j*8 + 2*l4;
        float i0 = linv[qc2], i1 = linv[qc2 + 1];
        int d0 = m0 + r4;
        size_t ro0 = ((size_t)b*SEQ + q0 + qc2)*DMODEL + h*DHEAD;
        size_t ro1 = ro0 + DMODEL;
        Op[ro0 + d0]     = __float2half_rn(oacc[j][0]*i0);
        Op[ro1 + d0]     = __float2half_rn(oacc[j][1]*i1);
        Op[ro0 + d0 + 8] = __float2half_rn(oacc[j][2]*i0);
        Op[ro1 + d0 + 8] = __float2half_rn(oacc[j][3]*i1);
    }
}

// ---------------------------------------------------------------------------
// Orchestration
// ---------------------------------------------------------------------------
static inline void launch_gemm(const __half* A, const __half* W, const float* bias,
                               const float* res, void* C, int M, int N, int K,
                               bool relu, bool ohalf) {
    dim3 grid(N/128, M/128), block(256);
    if (res) {
        cudaFuncSetAttribute(gemm_mma<false,true,true,false>, cudaFuncAttributeMaxDynamicSharedMemorySize, GEMM_SMEM);
        gemm_mma<false,true,true,false><<<grid, block, GEMM_SMEM>>>(A, W, bias, res, C, M, N, K);
    } else if (relu) {
        cudaFuncSetAttribute(gemm_mma<true,false,true,true>, cudaFuncAttributeMaxDynamicSharedMemorySize, GEMM_SMEM);
        gemm_mma<true,false,true,true><<<grid, block, GEMM_SMEM>>>(A, W, bias, nullptr, C, M, N, K);
    } else if (bias) {
        cudaFuncSetAttribute(gemm_mma<false,false,true,false>, cudaFuncAttributeMaxDynamicSharedMemorySize, GEMM_SMEM);
        gemm_mma<false,false,true,false><<<grid, block, GEMM_SMEM>>>(A, W, bias, nullptr, C, M, N, K);
    } else {
        cudaFuncSetAttribute(gemm_mma<false,false,false,false>, cudaFuncAttributeMaxDynamicSharedMemorySize, GEMM_SMEM);
        gemm_mma<false,false,false,false><<<grid, block, GEMM_SMEM>>>(A, W, nullptr, nullptr, C, M, N, K);
    }
}

extern "C" void kernel_launch(void* const* d_in, const int* in_sizes, int n_in,
                              void* d_out, int out_size) {
    const int*   src        = (const int*)  d_in[0];
    const int*   tgt        = (const int*)  d_in[1];
    const float* emb        = (const float*)d_in[2];
    const float* enc_attn_w = (const float*)d_in[3];
    const float* enc_attn_b = (const float*)d_in[4];
    const float* enc_ln_g   = (const float*)d_in[5];
    const float* enc_ln_b   = (const float*)d_in[6];
    const float* enc_w1     = (const float*)d_in[7];
    const float* enc_b1     = (const float*)d_in[8];
    const float* enc_w2     = (const float*)d_in[9];
    const float* enc_b2     = (const float*)d_in[10];
    const float* dec_attn_w = (const float*)d_in[11];
    const float* dec_attn_b = (const float*)d_in[12];
    const float* dec_ln_g   = (const float*)d_in[13];
    const float* dec_ln_b   = (const float*)d_in[14];
    const float* dec_w1     = (const float*)d_in[15];
    const float* dec_b1     = (const float*)d_in[16];
    const float* dec_w2     = (const float*)d_in[17];
    const float* dec_b2     = (const float*)d_in[18];
    const float* enc_norm_g = (const float*)d_in[19];
    const float* enc_norm_b = (const float*)d_in[20];
    const float* dec_norm_g = (const float*)d_in[21];
    const float* dec_norm_b = (const float*)d_in[22];

    float *x, *qb, *qkv, *kv;
    __half *x2, *ctx, *enc, *hbuf, *wv;
    cudaGetSymbolAddress((void**)&x,    g_x);
    cudaGetSymbolAddress((void**)&x2,   g_x2);
    cudaGetSymbolAddress((void**)&qb,   g_q);
    cudaGetSymbolAddress((void**)&ctx,  g_ctx);
    cudaGetSymbolAddress((void**)&enc,  g_enc);
    cudaGetSymbolAddress((void**)&hbuf, g_h);
    cudaGetSymbolAddress((void**)&qkv,  g_qkv);
    cudaGetSymbolAddress((void**)&kv,   g_kv);
    cudaGetSymbolAddress((void**)&wv,   g_w);

    cudaFuncSetAttribute(attn_mma, cudaFuncAttributeMaxDynamicSharedMemorySize, ATTN_SMEM);

    // --------------- weight conversion (fp16) ---------------
    {
        struct { const float* src; int off; int n; } cv[7] = {
            { enc_attn_w, OFF_ENC_ATTN, NLAYER*4*DMODEL*DMODEL },
            { enc_w1,     OFF_ENC_W1,   NLAYER*DFF*DMODEL },
            { enc_w2,     OFF_ENC_W2,   NLAYER*DMODEL*DFF },
            { dec_attn_w, OFF_DEC_ATTN, NLAYER*8*DMODEL*DMODEL },
            { dec_w1,     OFF_DEC_W1,   NLAYER*DFF*DMODEL },
            { dec_w2,     OFF_DEC_W2,   NLAYER*DMODEL*DFF },
            { emb,        OFF_EMB,      VOCAB*DMODEL },
        };
        for (int i = 0; i < 7; i++)
            cvt_kernel<<<cv[i].n/2048, 256>>>(cv[i].src, wv + cv[i].off, cv[i].n);
    }

    const int D = DMODEL, M = MROWS;
    const size_t WSZ = (size_t)D*D;
    dim3 attnGrid(SEQ/64, NHEAD, BATCH);
    const __half* ew = wv + OFF_ENC_ATTN;
    const __half* dw = wv + OFF_DEC_ATTN;

    // ===================== ENCODER =====================
    embed_kernel<<<M, 128>>>(src, emb, x);
    for (int l = 0; l < NLAYER; l++) {
        const __half* w  = ew + (size_t)l*4*WSZ;
        const float*  bb = enc_attn_b + (size_t)l*4*D;
        ln_kernel<<<M, 128>>>(x, enc_ln_g + (size_t)(l*2+0)*D, enc_ln_b + (size_t)(l*2+0)*D, x2);
        launch_gemm(x2, w, bb, nullptr, qkv, M, 3*D, D, false, false);
        attn_mma<<<attnGrid, 128, ATTN_SMEM>>>(qkv, 3*D, qkv + D, qkv + 2*D, 3*D, ctx, src, 0);
        launch_gemm(ctx, w + 3*WSZ, bb + 3*D, x, x, M, D, D, false, false);
        ln_kernel<<<M, 128>>>(x, enc_ln_g + (size_t)(l*2+1)*D, enc_ln_b + (size_t)(l*2+1)*D, x2);
        launch_gemm(x2, wv + OFF_ENC_W1 + (size_t)l*DFF*D, enc_b1 + (size_t)l*DFF, nullptr, hbuf, M, DFF, D, true, true);
        launch_gemm(hbuf, wv + OFF_ENC_W2 + (size_t)l*D*DFF, enc_b2 + (size_t)l*D, x, x, M, D, DFF, false, false);
    }
    ln_kernel<<<M, 128>>>(x, enc_norm_g, enc_norm_b, enc);

    // ===================== DECODER =====================
    embed_kernel<<<M, 128>>>(tgt, emb, x);
    for (int l = 0; l < NLAYER; l++) {
        const __half* w  = dw + (size_t)l*8*WSZ;
        const float*  bb = dec_attn_b + (size_t)l*8*D;
        ln_kernel<<<M, 128>>>(x, dec_ln_g + (size_t)(l*3+0)*D, dec_ln_b + (size_t)(l*3+0)*D, x2);
        launch_gemm(x2, w, bb, nullptr, qkv, M, 3*D, D, false, false);
        attn_mma<<<attnGrid, 128, ATTN_SMEM>>>(qkv, 3*D, qkv + D, qkv + 2*D, 3*D, ctx, tgt, 1);
        launch_gemm(ctx, w + 3*WSZ, bb + 3*D, x, x, M, D, D, false, false);
        ln_kernel<<<M, 128>>>(x, dec_ln_g + (size_t)(l*3+1)*D, dec_ln_b + (size_t)(l*3+1)*D, x2);
        launch_gemm(x2,  w + 4*WSZ, bb + 4*D, nullptr, qb, M, D, D, false, false);
        launch_gemm(enc, w + 5*WSZ, bb + 5*D, nullptr, kv, M, 2*D, D, false, false);
        attn_mma<<<attnGrid, 128, ATTN_SMEM>>>(qb, D, kv, kv + D, 2*D, ctx, src, 0);
        launch_gemm(ctx, w + 7*WSZ, bb + 7*D, x, x, M, D, D, false, false);
        ln_kernel<<<M, 128>>>(x, dec_ln_g + (size_t)(l*3+2)*D, dec_ln_b + (size_t)(l*3+2)*D, x2);
        launch_gemm(x2, wv + OFF_DEC_W1 + (size_t)l*DFF*D, dec_b1 + (size_t)l*DFF, nullptr, hbuf, M, DFF, D, true, true);
        launch_gemm(hbuf, wv + OFF_DEC_W2 + (size_t)l*D*DFF, dec_b2 + (size_t)l*D, x, x, M, D, DFF, false, false);
    }
    ln_kernel<<<M, 128>>>(x, dec_norm_g, dec_norm_b, x2);

    // ===================== tied output projection =====================
    launch_gemm(x2, wv + OFF_EMB, nullptr, nullptr, (float*)d_out, M, VOCAB, D, false, false);
}

// round 7
// speedup vs baseline: 11.4285x; 1.0813x over previous
#include <cuda_runtime.h>
#include <cuda_fp16.h>
#include <cstdint>
#include <math.h>

// ---------------------------------------------------------------------------
// Problem constants
// ---------------------------------------------------------------------------
#define BATCH 8
#define SEQ   512
#define DMODEL 512
#define NHEAD 8
#define DHEAD 64
#define NLAYER 4
#define DFF   2048
#define VOCAB 32000
#define MROWS (BATCH*SEQ)   // 4096

__device__ __forceinline__ uint32_t smem_u32(const void* p) {
    uint32_t a;
    asm("{ .reg .u64 t; cvta.to.shared.u64 t, %1; cvt.u32.u64 %0, t; }" : "=r"(a) : "l"(p));
    return a;
}
__device__ __forceinline__ void cp16(uint32_t s, const void* g) {
    asm volatile("cp.async.cg.shared.global [%0], [%1], 16;" :: "r"(s), "l"(g));
}
#define CP_COMMIT() asm volatile("cp.async.commit_group;" ::: "memory")
template<int N> __device__ __forceinline__ void cp_wait() {
    asm volatile("cp.async.wait_group %0;" :: "n"(N) : "memory");
}
__device__ __forceinline__ void ldm_x4(uint32_t* r, uint32_t addr) {
    asm volatile("ldmatrix.sync.aligned.m8n8.x4.shared.b16 {%0,%1,%2,%3}, [%4];"
        : "=r"(r[0]), "=r"(r[1]), "=r"(r[2]), "=r"(r[3]) : "r"(addr));
}
__device__ __forceinline__ void ldm_x4_t(uint32_t* r, uint32_t addr) {
    asm volatile("ldmatrix.sync.aligned.m8n8.x4.trans.shared.b16 {%0,%1,%2,%3}, [%4];"
        : "=r"(r[0]), "=r"(r[1]), "=r"(r[2]), "=r"(r[3]) : "r"(addr));
}
__device__ __forceinline__ void mma_f16(float* c, const uint32_t* a, const uint32_t* b) {
    asm volatile(
        "mma.sync.aligned.m16n8k16.row.col.f32.f16.f16.f32 "
        "{%0,%1,%2,%3}, {%4,%5,%6,%7}, {%8,%9}, {%0,%1,%2,%3};"
        : "+f"(c[0]), "+f"(c[1]), "+f"(c[2]), "+f"(c[3])
        : "r"(a[0]), "r"(a[1]), "r"(a[2]), "r"(a[3]), "r"(b[0]), "r"(b[1]));
}

// ---------------------------------------------------------------------------
// Scratch (device globals; no allocation allowed)
// ---------------------------------------------------------------------------
__device__ __align__(16) float g_x  [MROWS*DMODEL];
__device__ __align__(16) __half g_x2 [MROWS*DMODEL];
__device__ __align__(16) float g_q  [MROWS*DMODEL];
__device__ __align__(16) __half g_ctx[MROWS*DMODEL];
__device__ __align__(16) __half g_enc[MROWS*DMODEL];
__device__ __align__(16) __half g_h  [MROWS*DFF];
__device__ __align__(16) float g_qkv[MROWS*3*DMODEL];
__device__ __align__(16) float g_kv [MROWS*2*DMODEL];

// converted-weight arena (fp16)
#define OFF_ENC_ATTN 0
#define OFF_ENC_W1   (OFF_ENC_ATTN + NLAYER*4*DMODEL*DMODEL)
#define OFF_ENC_W2   (OFF_ENC_W1   + NLAYER*DFF*DMODEL)
#define OFF_DEC_ATTN (OFF_ENC_W2   + NLAYER*DMODEL*DFF)
#define OFF_DEC_W1   (OFF_DEC_ATTN + NLAYER*8*DMODEL*DMODEL)
#define OFF_DEC_W2   (OFF_DEC_W1   + NLAYER*DFF*DMODEL)
#define OFF_EMB      (OFF_DEC_W2   + NLAYER*DMODEL*DFF)
#define W_TOTAL      (OFF_EMB      + VOCAB*DMODEL)
__device__ __align__(16) __half g_w[W_TOTAL];

// ---------------------------------------------------------------------------
// fp32 -> fp16 conversion
// ---------------------------------------------------------------------------
__global__ void cvt_kernel(const float* __restrict__ in, __half* __restrict__ out, int n) {
    int i = (blockIdx.x*blockDim.x + threadIdx.x)*8;
    if (i < n) {
        float4 a = *(const float4*)(in + i);
        float4 b = *(const float4*)(in + i + 4);
        __half2 h0 = __floats2half2_rn(a.x, a.y);
        __half2 h1 = __floats2half2_rn(a.z, a.w);
        __half2 h2 = __floats2half2_rn(b.x, b.y);
        __half2 h3 = __floats2half2_rn(b.z, b.w);
        uint4 o;
        o.x = *(uint32_t*)&h0; o.y = *(uint32_t*)&h1;
        o.z = *(uint32_t*)&h2; o.w = *(uint32_t*)&h3;
        *(uint4*)(out + i) = o;
    }
}

// ---------------------------------------------------------------------------
// Embedding + sinusoidal positional encoding (residual stream, fp32)
// ---------------------------------------------------------------------------
__global__ void embed_kernel(const int* __restrict__ tok,
                             const float* __restrict__ emb,
                             float* __restrict__ y) {
    int row = blockIdx.x;
    int s   = row % SEQ;
    int t   = tok[row];
    const float scale = 22.62741699796952f;
    const float c0 = -9.210340371976184f / (float)DMODEL;
    int tid = threadIdx.x;
    #pragma unroll
    for (int i = 0; i < 4; i++) {
        int d = tid + i*128;
        float e = (t == 0) ? 0.f : emb[(size_t)t*DMODEL + d];
        int half = d >> 1;
        float div = expf((float)(2*half) * c0);
        float ang = (float)s * div;
        float pe = (d & 1) ? cosf(ang) : sinf(ang);
        y[(size_t)row*DMODEL + d] = e*scale + pe;
    }
}

// ---------------------------------------------------------------------------
// LayerNorm over last dim (D=512). Output fp16 (feeds GEMM A).
// ---------------------------------------------------------------------------
__global__ void ln_kernel(const float* __restrict__ x,
                          const float* __restrict__ g,
                          const float* __restrict__ b,
                          __half* __restrict__ y) {
    int row = blockIdx.x;
    const float* xr = x + (size_t)row*DMODEL;
    int t = threadIdx.x;
    float v[4];
    float s = 0.f;
    #pragma unroll
    for (int i = 0; i < 4; i++) { v[i] = xr[t + i*128]; s += v[i]; }
    __shared__ float red[4];
    #pragma unroll
    for (int o = 16; o > 0; o >>= 1) s += __shfl_xor_sync(0xffffffffu, s, o);
    if ((t & 31) == 0) red[t >> 5] = s;
    __syncthreads();
    float mean = (red[0]+red[1]+red[2]+red[3]) * (1.f/(float)DMODEL);
    float vs = 0.f;
    #pragma unroll
    for (int i = 0; i < 4; i++) { float d = v[i]-mean; vs += d*d; }
    #pragma unroll
    for (int o = 16; o > 0; o >>= 1) vs += __shfl_xor_sync(0xffffffffu, vs, o);
    __syncthreads();
    if ((t & 31) == 0) red[t >> 5] = vs;
    __syncthreads();
    float var = (red[0]+red[1]+red[2]+red[3]) * (1.f/(float)DMODEL);
    float inv = rsqrtf(var + 1e-5f);
    #pragma unroll
    for (int i = 0; i < 4; i++) {
        int d = t + i*128;
        float val = (v[i]-mean)*inv*g[d] + b[d];
        y[(size_t)row*DMODEL + d] = __float2half_rn(val);
    }
}

// ---------------------------------------------------------------------------
// fp16 mma.sync GEMM (m16n8k16, ldmatrix, cp.async 3-stage). (R6, unchanged)
// ---------------------------------------------------------------------------
#define TSTR 40
#define TILE_HALFS (128*TSTR)
#define STAGE_HALFS (2*TILE_HALFS)
#define GEMM_SMEM (3*STAGE_HALFS*2)

template<bool RELU, bool RES, bool BIAS, bool OHALF>
__global__ __launch_bounds__(256, 2)
void gemm_mma(const __half* __restrict__ A, const __half* __restrict__ W,
              const float* __restrict__ bias, const float* __restrict__ res,
              void* __restrict__ Cv, int M, int N, int K) {
    extern __shared__ __half smh[];
    int t = threadIdx.x, lane = t & 31, wid = t >> 5;
    int wm = (wid & 1) * 64;
    int wn = (wid >> 1) * 32;
    int r4 = lane >> 2, l4 = lane & 3;

    const __half* Ab = A + (size_t)blockIdx.y*128*K;
    const __half* Wb = W + (size_t)blockIdx.x*128*K;
    uint32_t sbase = smem_u32(smh);

    float acc[4][4][4];
    #pragma unroll
    for (int i = 0; i < 4; i++)
        #pragma unroll
        for (int j = 0; j < 4; j++)
            #pragma unroll
            for (int c = 0; c < 4; c++) acc[i][j][c] = 0.f;

    int NK = K >> 5;

    auto issue = [&](int it, int buf) {
        uint32_t base = sbase + (uint32_t)buf*STAGE_HALFS*2;
        int k0 = it*32;
        #pragma unroll
        for (int i = 0; i < 2; i++) {
            int idx = t + i*256, r = idx >> 2, ch = idx & 3;
            uint32_t off = (uint32_t)(r*TSTR + ch*8)*2;
            cp16(base + off,                  Ab + (size_t)r*K + k0 + ch*8);
            cp16(base + TILE_HALFS*2 + off,   Wb + (size_t)r*K + k0 + ch*8);
        }
        CP_COMMIT();
    };

    issue(0, 0);
    issue(1, 1);

    int a_row = (lane & 15);
    int a_kh8 = (lane >> 4) * 8;
    int b_row = (lane & 7) + ((lane >> 4) & 1) * 8;
    int b_kh8 = ((lane >> 3) & 1) * 8;

    for (int it = 0; it < NK; it++) {
        if (it + 1 < NK) cp_wait<1>(); else cp_wait<0>();
        __syncthreads();
        if (it + 2 < NK) issue(it + 2, (it + 2) % 3);
        uint32_t sA = sbase + (uint32_t)(it % 3)*STAGE_HALFS*2;
        uint32_t sB = sA + TILE_HALFS*2;
        #pragma unroll
        for (int kh = 0; kh < 2; kh++) {
            uint32_t af[4][4], bf[2][4];
            #pragma unroll
            for (int mi = 0; mi < 4; mi++)
                ldm_x4(af[mi], sA + (uint32_t)((wm + mi*16 + a_row)*TSTR + kh*16 + a_kh8)*2);
            #pragma unroll
            for (int nb = 0; nb < 2; nb++)
                ldm_x4(bf[nb], sB + (uint32_t)((wn + nb*16 + b_row)*TSTR + kh*16 + b_kh8)*2);
            #pragma unroll
            for (int mi = 0; mi < 4; mi++) {
                #pragma unroll
                for (int ni = 0; ni < 4; ni++)
                    mma_f16(acc[mi][ni], af[mi], bf[ni >> 1] + (ni & 1)*2);
            }
        }
    }

    int gm = blockIdx.y*128 + wm;
    int gn = blockIdx.x*128 + wn;
    #pragma unroll
    for (int mi = 0; mi < 4; mi++) {
        #pragma unroll
        for (int ni = 0; ni < 4; ni++) {
            int row = gm + mi*16 + r4;
            int col = gn + ni*8 + l4*2;
            float2 v0 = make_float2(acc[mi][ni][0], acc[mi][ni][1]);
            float2 v1 = make_float2(acc[mi][ni][2], acc[mi][ni][3]);
            if (BIAS) {
                float2 bv = *(const float2*)(bias + col);
                v0.x += bv.x; v0.y += bv.y; v1.x += bv.x; v1.y += bv.y;
            }
            if (RELU) {
                v0.x = fmaxf(v0.x, 0.f); v0.y = fmaxf(v0.y, 0.f);
                v1.x = fmaxf(v1.x, 0.f); v1.y = fmaxf(v1.y, 0.f);
            }
            if (RES) {
                float2 r0 = *(const float2*)(res + (size_t)row*N + col);
                float2 r1 = *(const float2*)(res + (size_t)(row+8)*N + col);
                v0.x += r0.x; v0.y += r0.y; v1.x += r1.x; v1.y += r1.y;
            }
            if (OHALF) {
                __half* C = (__half*)Cv;
                __half2 h0 = __floats2half2_rn(v0.x, v0.y);
                __half2 h1 = __floats2half2_rn(v1.x, v1.y);
                *(__half2*)(C + (size_t)row*N + col)     = h0;
                *(__half2*)(C + (size_t)(row+8)*N + col) = h1;
            } else {
                float* C = (float*)Cv;
                *(float2*)(C + (size_t)row*N + col)     = v0;
                *(float2*)(C + (size_t)(row+8)*N + col) = v1;
            }
        }
    }
}

// ---------------------------------------------------------------------------
// Flash attention, fp16 m16n8k16 + ldmatrix.
// Block = 64 q rows of one (b,h), 128 threads (4 warps).
// S-phase: warp w owns q rows [w*16,+16).  PV: O^T = V^T P^T via ldmatrix.trans.
// All smem strides 72 halfs -> conflict-free ldmatrix phases.
// ---------------------------------------------------------------------------
#define ASS 72
#define QS_OFF 0
#define KS_OFF (64*ASS)          // 4608
#define VS_OFF (2*64*ASS)
#define PS_OFF (3*64*ASS)
#define FH_TOT (4*64*ASS)        // 18432 halfs
#define ATTN_SMEM (FH_TOT*2 + 768)

__global__ __launch_bounds__(128)
void attn_mma(const float* __restrict__ Qp, int qstride,
              const float* __restrict__ Kp, const float* __restrict__ Vp, int kvstride,
              __half* __restrict__ Op,
              const int* __restrict__ mtok, int causal) {
    extern __shared__ __half smh[];
    __half* Qs = smh + QS_OFF;
    __half* Ks = smh + KS_OFF;
    __half* Vs = smh + VS_OFF;
    __half* Ps = smh + PS_OFF;
    float* alphas = (float*)(smh + FH_TOT);
    float* linv   = alphas + 64;
    uint32_t* maskv = (uint32_t*)(linv + 64);

    int t = threadIdx.x, lane = t & 31, w = t >> 5;
    int r4 = lane >> 2, l4 = lane & 3;
    int q0 = blockIdx.x * 64, h = blockIdx.y, b = blockIdx.z;
    const float* Qb = Qp + (size_t)b*SEQ*qstride  + h*DHEAD;
    const float* Kb = Kp + (size_t)b*SEQ*kvstride + h*DHEAD;
    const float* Vb = Vp + (size_t)b*SEQ*kvstride + h*DHEAD;

    uint32_t qs_b = smem_u32(Qs), ks_b = smem_u32(Ks);
    uint32_t vs_b = smem_u32(Vs), ps_b = smem_u32(Ps);

    // ldmatrix lane address components
    int a_row = (lane & 15);
    int a_k8  = (lane >> 4) * 8;
    int b_row = (lane & 7) + ((lane >> 4) & 1) * 8;
    int b_k8  = ((lane >> 3) & 1) * 8;
    int v_s   = (lane & 7) + ((lane >> 4) & 1) * 8;   // trans: s row
    int v_d8  = ((lane >> 3) & 1) * 8;                // trans: d offset

    // stage Q as half
    #pragma unroll
    for (int i = 0; i < 8; i++) {
        int idx = t + i*128, s = idx >> 4, dg = idx & 15;
        float4 v = *(const float4*)(Qb + (size_t)(q0+s)*qstride + dg*4);
        __half2 h0 = __floats2half2_rn(v.x, v.y);
        __half2 h1 = __floats2half2_rn(v.z, v.w);
        uint2 o; o.x = *(uint32_t*)&h0; o.y = *(uint32_t*)&h1;
        *(uint2*)(Qs + s*ASS + dg*4) = o;
    }
    __syncthreads();
    int m0 = w*16;
    uint32_t qf[4][4];
    #pragma unroll
    for (int kh = 0; kh < 4; kh++)
        ldm_x4(qf[kh], qs_b + (uint32_t)((m0 + a_row)*ASS + kh*16 + a_k8)*2);

    float oacc[8][4];
    #pragma unroll
    for (int j = 0; j < 8; j++)
        #pragma unroll
        for (int c = 0; c < 4; c++) oacc[j][c] = 0.f;
    float mrA = -1e30f, mrB = -1e30f, lrA = 0.f, lrB = 0.f;

    int qcnk = q0 >> 6;
    int nchunks = causal ? (qcnk + 1) : (SEQ/64);
    int qA = q0 + m0 + r4, qB = qA + 8;

    for (int kt = 0; kt < nchunks; kt++) {
        __syncthreads();
        #pragma unroll
        for (int i = 0; i < 8; i++) {
            int idx = t + i*128, s = idx >> 4, dg = idx & 15;
            float4 kv = *(const float4*)(Kb + (size_t)(kt*64+s)*kvstride + dg*4);
            __half2 k0 = __floats2half2_rn(kv.x, kv.y);
            __half2 k1 = __floats2half2_rn(kv.z, kv.w);
            uint2 ko; ko.x = *(uint32_t*)&k0; ko.y = *(uint32_t*)&k1;
            *(uint2*)(Ks + s*ASS + dg*4) = ko;
            float4 vv = *(const float4*)(Vb + (size_t)(kt*64+s)*kvstride + dg*4);
            __half2 v0 = __floats2half2_rn(vv.x, vv.y);
            __half2 v1 = __floats2half2_rn(vv.z, vv.w);
            uint2 vo; vo.x = *(uint32_t*)&v0; vo.y = *(uint32_t*)&v1;
            *(uint2*)(Vs + s*ASS + dg*4) = vo;
        }
        if (t < 64) maskv[t] = (mtok[b*SEQ + kt*64 + t] != 0);
        __syncthreads();

        // ---- S = Q K^T : warp's 16 q rows x 64 k cols ----
        float sacc[8][4];
        #pragma unroll
        for (int j = 0; j < 8; j++)
            #pragma unroll
            for (int c = 0; c < 4; c++) sacc[j][c] = 0.f;
        #pragma unroll
        for (int kh = 0; kh < 4; kh++) {
            uint32_t bf[4][4];
            #pragma unroll
            for (int nb = 0; nb < 4; nb++)
                ldm_x4(bf[nb], ks_b + (uint32_t)((nb*16 + b_row)*ASS + kh*16 + b_k8)*2);
            #pragma unroll
            for (int nb = 0; nb < 4; nb++) {
                mma_f16(sacc[nb*2],     qf[kh], bf[nb]);
                mma_f16(sacc[nb*2 + 1], qf[kh], bf[nb] + 2);
            }
        }
        // ---- mask + scale + row max ----
        bool diag = causal && (kt == qcnk);
        float mA = -1e30f, mB = -1e30f;
        #pragma unroll
        for (int j = 0; j < 8; j++) {
            int kl = j*8 + 2*l4;
            int kg = kt*64 + kl;
            bool pv0 = maskv[kl] != 0, pv1 = maskv[kl+1] != 0;
            bool a0 = pv0 && (!diag || kg   <= qA);
            bool a1 = pv1 && (!diag || kg+1 <= qA);
            bool b0 = pv0 && (!diag || kg   <= qB);
            bool b1 = pv1 && (!diag || kg+1 <= qB);
            sacc[j][0] = a0 ? sacc[j][0]*0.125f : -1e9f;
            sacc[j][1] = a1 ? sacc[j][1]*0.125f : -1e9f;
            sacc[j][2] = b0 ? sacc[j][2]*0.125f : -1e9f;
            sacc[j][3] = b1 ? sacc[j][3]*0.125f : -1e9f;
            mA = fmaxf(mA, fmaxf(sacc[j][0], sacc[j][1]));
            mB = fmaxf(mB, fmaxf(sacc[j][2], sacc[j][3]));
        }
        mA = fmaxf(mA, __shfl_xor_sync(0xffffffffu, mA, 1));
        mA = fmaxf(mA, __shfl_xor_sync(0xffffffffu, mA, 2));
        mB = fmaxf(mB, __shfl_xor_sync(0xffffffffu, mB, 1));
        mB = fmaxf(mB, __shfl_xor_sync(0xffffffffu, mB, 2));
        float mnA = fmaxf(mrA, mA), mnB = fmaxf(mrB, mB);
        float aA = __expf(mrA - mnA), aB = __expf(mrB - mnB);
        mrA = mnA; mrB = mnB;
        // ---- exp + write P (half) + row sums ----
        float lA = 0.f, lB = 0.f;
        #pragma unroll
        for (int j = 0; j < 8; j++) {
            float p0 = __expf(sacc[j][0] - mnA);
            float p1 = __expf(sacc[j][1] - mnA);
            float p2 = __expf(sacc[j][2] - mnB);
            float p3 = __expf(sacc[j][3] - mnB);
            lA += p0 + p1; lB += p2 + p3;
            *(__half2*)(Ps + (m0 + r4)*ASS     + j*8 + 2*l4) = __floats2half2_rn(p0, p1);
            *(__half2*)(Ps + (m0 + r4 + 8)*ASS + j*8 + 2*l4) = __floats2half2_rn(p2, p3);
        }
        lA += __shfl_xor_sync(0xffffffffu, lA, 1);
        lA += __shfl_xor_sync(0xffffffffu, lA, 2);
        lB += __shfl_xor_sync(0xffffffffu, lB, 1);
        lB += __shfl_xor_sync(0xffffffffu, lB, 2);
        lrA = lrA*aA + lA;
        lrB = lrB*aB + lB;
        if (l4 == 0) {
            alphas[m0 + r4]     = aA;
            alphas[m0 + r4 + 8] = aB;
            if (kt == nchunks - 1) {
                linv[m0 + r4]     = 1.f / lrA;
                linv[m0 + r4 + 8] = 1.f / lrB;
            }
        }
        __syncthreads();

        // ---- PV: O^T[d,q] += V^T P^T ; warp d-tile [m0,m0+16) ----
        #pragma unroll
        for (int j = 0; j < 8; j++) {
            float a0 = alphas[j*8 + 2*l4];
            float a1 = alphas[j*8 + 2*l4 + 1];
            oacc[j][0] *= a0; oacc[j][1] *= a1;
            oacc[j][2] *= a0; oacc[j][3] *= a1;
        }
        #pragma unroll
        for (int kh = 0; kh < 4; kh++) {
            uint32_t af[4];
            ldm_x4_t(af, vs_b + (uint32_t)((kh*16 + v_s)*ASS + m0 + v_d8)*2);
            #pragma unroll
            for (int jb = 0; jb < 4; jb++) {
                uint32_t bf[4];
                ldm_x4(bf, ps_b + (uint32_t)((jb*16 + b_row)*ASS + kh*16 + b_k8)*2);
                mma_f16(oacc[jb*2],     af, bf);
                mma_f16(oacc[jb*2 + 1], af, bf + 2);
            }
        }
    }

    // ---- output fp16: O[b,q,h*64+d] = O^T[d,q] * linv[q] ----
    #pragma unroll
    for (int j = 0; j < 8; j++) {
        int qc2 = j*8 + 2*l4;
        float i0 = linv[qc2], i1 = linv[qc2 + 1];
        int d0 = m0 + r4;
        size_t ro0 = ((size_t)b*SEQ + q0 + qc2)*DMODEL + h*DHEAD;
        size_t ro1 = ro0 + DMODEL;
        Op[ro0 + d0]     = __float2half_rn(oacc[j][0]*i0);
        Op[ro1 + d0]     = __float2half_rn(oacc[j][1]*i1);
        Op[ro0 + d0 + 8] = __float2half_rn(oacc[j][2]*i0);
        Op[ro1 + d0 + 8] = __float2half_rn(oacc[j][3]*i1);
    }
}

// ---------------------------------------------------------------------------
// Orchestration
// ---------------------------------------------------------------------------
static inline void launch_gemm(const __half* A, const __half* W, const float* bias,
                               const float* res, void* C, int M, int N, int K,
                               bool relu, bool ohalf) {
    dim3 grid(N/128, M/128), block(256);
    if (res) {
        cudaFuncSetAttribute(gemm_mma<false,true,true,false>, cudaFuncAttributeMaxDynamicSharedMemorySize, GEMM_SMEM);
        gemm_mma<false,true,true,false><<<grid, block, GEMM_SMEM>>>(A, W, bias, res, C, M, N, K);
    } else if (relu) {
        cudaFuncSetAttribute(gemm_mma<true,false,true,true>, cudaFuncAttributeMaxDynamicSharedMemorySize, GEMM_SMEM);
        gemm_mma<true,false,true,true><<<grid, block, GEMM_SMEM>>>(A, W, bias, nullptr, C, M, N, K);
    } else if (bias) {
        cudaFuncSetAttribute(gemm_mma<false,false,true,false>, cudaFuncAttributeMaxDynamicSharedMemorySize, GEMM_SMEM);
        gemm_mma<false,false,true,false><<<grid, block, GEMM_SMEM>>>(A, W, bias, nullptr, C, M, N, K);
    } else {
        cudaFuncSetAttribute(gemm_mma<false,false,false,false>, cudaFuncAttributeMaxDynamicSharedMemorySize, GEMM_SMEM);
        gemm_mma<false,false,false,false><<<grid, block, GEMM_SMEM>>>(A, W, nullptr, nullptr, C, M, N, K);
    }
}

extern "C" void kernel_launch(void* const* d_in, const int* in_sizes, int n_in,
                              void* d_out, int out_size) {
    const int*   src        = (const int*)  d_in[0];
    const int*   tgt        = (const int*)  d_in[1];
    const float* emb        = (const float*)d_in[2];
    const float* enc_attn_w = (const float*)d_in[3];
    const float* enc_attn_b = (const float*)d_in[4];
    const float* enc_ln_g   = (const float*)d_in[5];
    const float* enc_ln_b   = (const float*)d_in[6];
    const float* enc_w1     = (const float*)d_in[7];
    const float* enc_b1     = (const float*)d_in[8];
    const float* enc_w2     = (const float*)d_in[9];
    const float* enc_b2     = (const float*)d_in[10];
    const float* dec_attn_w = (const float*)d_in[11];
    const float* dec_attn_b = (const float*)d_in[12];
    const float* dec_ln_g   = (const float*)d_in[13];
    const float* dec_ln_b   = (const float*)d_in[14];
    const float* dec_w1     = (const float*)d_in[15];
    const float* dec_b1     = (const float*)d_in[16];
    const float* dec_w2     = (const float*)d_in[17];
    const float* dec_b2     = (const float*)d_in[18];
    const float* enc_norm_g = (const float*)d_in[19];
    const float* enc_norm_b = (const float*)d_in[20];
    const float* dec_norm_g = (const float*)d_in[21];
    const float* dec_norm_b = (const float*)d_in[22];

    float *x, *qb, *qkv, *kv;
    __half *x2, *ctx, *enc, *hbuf, *wv;
    cudaGetSymbolAddress((void**)&x,    g_x);
    cudaGetSymbolAddress((void**)&x2,   g_x2);
    cudaGetSymbolAddress((void**)&qb,   g_q);
    cudaGetSymbolAddress((void**)&ctx,  g_ctx);
    cudaGetSymbolAddress((void**)&enc,  g_enc);
    cudaGetSymbolAddress((void**)&hbuf, g_h);
    cudaGetSymbolAddress((void**)&qkv,  g_qkv);
    cudaGetSymbolAddress((void**)&kv,   g_kv);
    cudaGetSymbolAddress((void**)&wv,   g_w);

    cudaFuncSetAttribute(attn_mma, cudaFuncAttributeMaxDynamicSharedMemorySize, ATTN_SMEM);

    // --------------- weight conversion (fp16) ---------------
    {
        struct { const float* src; int off; int n; } cv[7] = {
            { enc_attn_w, OFF_ENC_ATTN, NLAYER*4*DMODEL*DMODEL },
            { enc_w1,     OFF_ENC_W1,   NLAYER*DFF*DMODEL },
            { enc_w2,     OFF_ENC_W2,   NLAYER*DMODEL*DFF },
            { dec_attn_w, OFF_DEC_ATTN, NLAYER*8*DMODEL*DMODEL },
            { dec_w1,     OFF_DEC_W1,   NLAYER*DFF*DMODEL },
            { dec_w2,     OFF_DEC_W2,   NLAYER*DMODEL*DFF },
            { emb,        OFF_EMB,      VOCAB*DMODEL },
        };
        for (int i = 0; i < 7; i++)
            cvt_kernel<<<cv[i].n/2048, 256>>>(cv[i].src, wv + cv[i].off, cv[i].n);
    }

    const int D = DMODEL, M = MROWS;
    const size_t WSZ = (size_t)D*D;
    dim3 attnGrid(SEQ/64, NHEAD, BATCH);
    const __half* ew = wv + OFF_ENC_ATTN;
    const __half* dw = wv + OFF_DEC_ATTN;

    // ===================== ENCODER =====================
    embed_kernel<<<M, 128>>>(src, emb, x);
    for (int l = 0; l < NLAYER; l++) {
        const __half* w  = ew + (size_t)l*4*WSZ;
        const float*  bb = enc_attn_b + (size_t)l*4*D;
        ln_kernel<<<M, 128>>>(x, enc_ln_g + (size_t)(l*2+0)*D, enc_ln_b + (size_t)(l*2+0)*D, x2);
        launch_gemm(x2, w, bb, nullptr, qkv, M, 3*D, D, false, false);
        attn_mma<<<attnGrid, 128, ATTN_SMEM>>>(qkv, 3*D, qkv + D, qkv + 2*D, 3*D, ctx, src, 0);
        launch_gemm(ctx, w + 3*WSZ, bb + 3*D, x, x, M, D, D, false, false);
        ln_kernel<<<M, 128>>>(x, enc_ln_g + (size_t)(l*2+1)*D, enc_ln_b + (size_t)(l*2+1)*D, x2);
        launch_gemm(x2, wv + OFF_ENC_W1 + (size_t)l*DFF*D, enc_b1 + (size_t)l*DFF, nullptr, hbuf, M, DFF, D, true, true);
        launch_gemm(hbuf, wv + OFF_ENC_W2 + (size_t)l*D*DFF, enc_b2 + (size_t)l*D, x, x, M, D, DFF, false, false);
    }
    ln_kernel<<<M, 128>>>(x, enc_norm_g, enc_norm_b, enc);

    // ===================== DECODER =====================
    embed_kernel<<<M, 128>>>(tgt, emb, x);
    for (int l = 0; l < NLAYER; l++) {
        const __half* w  = dw + (size_t)l*8*WSZ;
        const float*  bb = dec_attn_b + (size_t)l*8*D;
        ln_kernel<<<M, 128>>>(x, dec_ln_g + (size_t)(l*3+0)*D, dec_ln_b + (size_t)(l*3+0)*D, x2);
        launch_gemm(x2, w, bb, nullptr, qkv, M, 3*D, D, false, false);
        attn_mma<<<attnGrid, 128, ATTN_SMEM>>>(qkv, 3*D, qkv + D, qkv + 2*D, 3*D, ctx, tgt, 1);
        launch_gemm(ctx, w + 3*WSZ, bb + 3*D, x, x, M, D, D, false, false);
        ln_kernel<<<M, 128>>>(x, dec_ln_g + (size_t)(l*3+1)*D, dec_ln_b + (size_t)(l*3+1)*D, x2);
        launch_gemm(x2,  w + 4*WSZ, bb + 4*D, nullptr, qb, M, D, D, false, false);
        launch_gemm(enc, w + 5*WSZ, bb + 5*D, nullptr, kv, M, 2*D, D, false, false);
        attn_mma<<<attnGrid, 128, ATTN_SMEM>>>(qb, D, kv, kv + D, 2*D, ctx, src, 0);
        launch_gemm(ctx, w + 7*WSZ, bb + 7*D, x, x, M, D, D, false, false);
        ln_kernel<<<M, 128>>>(x, dec_ln_g + (size_t)(l*3+2)*D, dec_ln_b + (size_t)(l*3+2)*D, x2);
        launch_gemm(x2, wv + OFF_DEC_W1 + (size_t)l*DFF*D, dec_b1 + (size_t)l*DFF, nullptr, hbuf, M, DFF, D, true, true);
        launch_gemm(hbuf, wv + OFF_DEC_W2 + (size_t)l*D*DFF, dec_b2 + (size_t)l*D, x, x, M, D, DFF, false, false);
    }
    ln_kernel<<<M, 128>>>(x, dec_norm_g, dec_norm_b, x2);

    // ===================== tied output projection =====================
    launch_gemm(x2, wv + OFF_EMB, nullptr, nullptr, (float*)d_out, M, VOCAB, D, false, false);
}

// round 8
// speedup vs baseline: 11.9040x; 1.0416x over previous
#include <cuda_runtime.h>
#include <cuda_fp16.h>
#include <cstdint>
#include <math.h>

// ---------------------------------------------------------------------------
// Problem constants
// ---------------------------------------------------------------------------
#define BATCH 8
#define SEQ   512
#define DMODEL 512
#define NHEAD 8
#define DHEAD 64
#define NLAYER 4
#define DFF   2048
#define VOCAB 32000
#define MROWS (BATCH*SEQ)   // 4096

__device__ __forceinline__ uint32_t smem_u32(const void* p) {
    uint32_t a;
    asm("{ .reg .u64 t; cvta.to.shared.u64 t, %1; cvt.u32.u64 %0, t; }" : "=r"(a) : "l"(p));
    return a;
}
__device__ __forceinline__ void cp16(uint32_t s, const void* g) {
    asm volatile("cp.async.cg.shared.global [%0], [%1], 16;" :: "r"(s), "l"(g));
}
#define CP_COMMIT() asm volatile("cp.async.commit_group;" ::: "memory")
template<int N> __device__ __forceinline__ void cp_wait() {
    asm volatile("cp.async.wait_group %0;" :: "n"(N) : "memory");
}
__device__ __forceinline__ void ldm_x4(uint32_t* r, uint32_t addr) {
    asm volatile("ldmatrix.sync.aligned.m8n8.x4.shared.b16 {%0,%1,%2,%3}, [%4];"
        : "=r"(r[0]), "=r"(r[1]), "=r"(r[2]), "=r"(r[3]) : "r"(addr));
}
__device__ __forceinline__ void ldm_x4_t(uint32_t* r, uint32_t addr) {
    asm volatile("ldmatrix.sync.aligned.m8n8.x4.trans.shared.b16 {%0,%1,%2,%3}, [%4];"
        : "=r"(r[0]), "=r"(r[1]), "=r"(r[2]), "=r"(r[3]) : "r"(addr));
}
__device__ __forceinline__ void mma_f16(float* c, const uint32_t* a, const uint32_t* b) {
    asm volatile(
        "mma.sync.aligned.m16n8k16.row.col.f32.f16.f16.f32 "
        "{%0,%1,%2,%3}, {%4,%5,%6,%7}, {%8,%9}, {%0,%1,%2,%3};"
        : "+f"(c[0]), "+f"(c[1]), "+f"(c[2]), "+f"(c[3])
        : "r"(a[0]), "r"(a[1]), "r"(a[2]), "r"(a[3]), "r"(b[0]), "r"(b[1]));
}

// ---------------------------------------------------------------------------
// Scratch (device globals; no allocation allowed)
// ---------------------------------------------------------------------------
__device__ __align__(16) float  g_x  [MROWS*DMODEL];
__device__ __align__(16) __half g_x2 [MROWS*DMODEL];
__device__ __align__(16) __half g_q  [MROWS*DMODEL];
__device__ __align__(16) __half g_ctx[MROWS*DMODEL];
__device__ __align__(16) __half g_enc[MROWS*DMODEL];
__device__ __align__(16) __half g_h  [MROWS*DFF];
__device__ __align__(16) __half g_qkv[MROWS*3*DMODEL];
__device__ __align__(16) __half g_kv [MROWS*2*DMODEL];

// converted-weight arena (fp16)
#define OFF_ENC_ATTN 0
#define OFF_ENC_W1   (OFF_ENC_ATTN + NLAYER*4*DMODEL*DMODEL)
#define OFF_ENC_W2   (OFF_ENC_W1   + NLAYER*DFF*DMODEL)
#define OFF_DEC_ATTN (OFF_ENC_W2   + NLAYER*DMODEL*DFF)
#define OFF_DEC_W1   (OFF_DEC_ATTN + NLAYER*8*DMODEL*DMODEL)
#define OFF_DEC_W2   (OFF_DEC_W1   + NLAYER*DFF*DMODEL)
#define OFF_EMB      (OFF_DEC_W2   + NLAYER*DMODEL*DFF)
#define W_TOTAL      (OFF_EMB      + VOCAB*DMODEL)
__device__ __align__(16) __half g_w[W_TOTAL];

// ---------------------------------------------------------------------------
// fp32 -> fp16 conversion
// ---------------------------------------------------------------------------
__global__ void cvt_kernel(const float* __restrict__ in, __half* __restrict__ out, int n) {
    int i = (blockIdx.x*blockDim.x + threadIdx.x)*8;
    if (i < n) {
        float4 a = *(const float4*)(in + i);
        float4 b = *(const float4*)(in + i + 4);
        __half2 h0 = __floats2half2_rn(a.x, a.y);
        __half2 h1 = __floats2half2_rn(a.z, a.w);
        __half2 h2 = __floats2half2_rn(b.x, b.y);
        __half2 h3 = __floats2half2_rn(b.z, b.w);
        uint4 o;
        o.x = *(uint32_t*)&h0; o.y = *(uint32_t*)&h1;
        o.z = *(uint32_t*)&h2; o.w = *(uint32_t*)&h3;
        *(uint4*)(out + i) = o;
    }
}

// ---------------------------------------------------------------------------
// Embedding + sinusoidal positional encoding (residual stream, fp32)
// ---------------------------------------------------------------------------
__global__ void embed_kernel(const int* __restrict__ tok,
                             const float* __restrict__ emb,
                             float* __restrict__ y) {
    int row = blockIdx.x;
    int s   = row % SEQ;
    int t   = tok[row];
    const float scale = 22.62741699796952f;
    const float c0 = -9.210340371976184f / (float)DMODEL;
    int tid = threadIdx.x;
    #pragma unroll
    for (int i = 0; i < 4; i++) {
        int d = tid + i*128;
        float e = (t == 0) ? 0.f : emb[(size_t)t*DMODEL + d];
        int half = d >> 1;
        float div = expf((float)(2*half) * c0);
        float ang = (float)s * div;
        float pe = (d & 1) ? cosf(ang) : sinf(ang);
        y[(size_t)row*DMODEL + d] = e*scale + pe;
    }
}

// ---------------------------------------------------------------------------
// LayerNorm, warp-per-row (8 rows / 256-thread block, no __syncthreads).
// ---------------------------------------------------------------------------
__global__ __launch_bounds__(256)
void ln_kernel(const float* __restrict__ x,
               const float* __restrict__ g,
               const float* __restrict__ b,
               __half* __restrict__ y) {
    int row  = blockIdx.x*8 + (threadIdx.x >> 5);
    int lane = threadIdx.x & 31;
    const float* xr = x + (size_t)row*DMODEL;
    float4 v[4];
    float s = 0.f;
    #pragma unroll
    for (int c = 0; c < 4; c++) {
        v[c] = *(const float4*)(xr + lane*4 + c*128);
        s += (v[c].x + v[c].y) + (v[c].z + v[c].w);
    }
    #pragma unroll
    for (int o = 16; o > 0; o >>= 1) s += __shfl_xor_sync(0xffffffffu, s, o);
    float mean = s * (1.f/(float)DMODEL);
    float vs = 0.f;
    #pragma unroll
    for (int c = 0; c < 4; c++) {
        float d0 = v[c].x-mean, d1 = v[c].y-mean, d2 = v[c].z-mean, d3 = v[c].w-mean;
        vs += d0*d0 + d1*d1 + d2*d2 + d3*d3;
    }
    #pragma unroll
    for (int o = 16; o > 0; o >>= 1) vs += __shfl_xor_sync(0xffffffffu, vs, o);
    float inv = rsqrtf(vs * (1.f/(float)DMODEL) + 1e-5f);
    #pragma unroll
    for (int c = 0; c < 4; c++) {
        int d = lane*4 + c*128;
        float4 gv = *(const float4*)(g + d);
        float4 bv = *(const float4*)(b + d);
        float r0 = (v[c].x-mean)*inv*gv.x + bv.x;
        float r1 = (v[c].y-mean)*inv*gv.y + bv.y;
        float r2 = (v[c].z-mean)*inv*gv.z + bv.z;
        float r3 = (v[c].w-mean)*inv*gv.w + bv.w;
        __half2 h0 = __floats2half2_rn(r0, r1);
        __half2 h1 = __floats2half2_rn(r2, r3);
        uint2 o; o.x = *(uint32_t*)&h0; o.y = *(uint32_t*)&h1;
        *(uint2*)(y + (size_t)row*DMODEL + d) = o;
    }
}

// ---------------------------------------------------------------------------
// fp16 mma.sync GEMM (m16n8k16, ldmatrix, cp.async 3-stage). (R6/R7, unchanged)
// ---------------------------------------------------------------------------
#define TSTR 40
#define TILE_HALFS (128*TSTR)
#define STAGE_HALFS (2*TILE_HALFS)
#define GEMM_SMEM (3*STAGE_HALFS*2)

template<bool RELU, bool RES, bool BIAS, bool OHALF>
__global__ __launch_bounds__(256, 2)
void gemm_mma(const __half* __restrict__ A, const __half* __restrict__ W,
              const float* __restrict__ bias, const float* __restrict__ res,
              void* __restrict__ Cv, int M, int N, int K) {
    extern __shared__ __half smh[];
    int t = threadIdx.x, lane = t & 31, wid = t >> 5;
    int wm = (wid & 1) * 64;
    int wn = (wid >> 1) * 32;
    int r4 = lane >> 2, l4 = lane & 3;

    const __half* Ab = A + (size_t)blockIdx.y*128*K;
    const __half* Wb = W + (size_t)blockIdx.x*128*K;
    uint32_t sbase = smem_u32(smh);

    float acc[4][4][4];
    #pragma unroll
    for (int i = 0; i < 4; i++)
        #pragma unroll
        for (int j = 0; j < 4; j++)
            #pragma unroll
            for (int c = 0; c < 4; c++) acc[i][j][c] = 0.f;

    int NK = K >> 5;

    auto issue = [&](int it, int buf) {
        uint32_t base = sbase + (uint32_t)buf*STAGE_HALFS*2;
        int k0 = it*32;
        #pragma unroll
        for (int i = 0; i < 2; i++) {
            int idx = t + i*256, r = idx >> 2, ch = idx & 3;
            uint32_t off = (uint32_t)(r*TSTR + ch*8)*2;
            cp16(base + off,                  Ab + (size_t)r*K + k0 + ch*8);
            cp16(base + TILE_HALFS*2 + off,   Wb + (size_t)r*K + k0 + ch*8);
        }
        CP_COMMIT();
    };

    issue(0, 0);
    issue(1, 1);

    int a_row = (lane & 15);
    int a_kh8 = (lane >> 4) * 8;
    int b_row = (lane & 7) + ((lane >> 4) & 1) * 8;
    int b_kh8 = ((lane >> 3) & 1) * 8;

    for (int it = 0; it < NK; it++) {
        if (it + 1 < NK) cp_wait<1>(); else cp_wait<0>();
        __syncthreads();
        if (it + 2 < NK) issue(it + 2, (it + 2) % 3);
        uint32_t sA = sbase + (uint32_t)(it % 3)*STAGE_HALFS*2;
        uint32_t sB = sA + TILE_HALFS*2;
        #pragma unroll
        for (int kh = 0; kh < 2; kh++) {
            uint32_t af[4][4], bf[2][4];
            #pragma unroll
            for (int mi = 0; mi < 4; mi++)
                ldm_x4(af[mi], sA + (uint32_t)((wm + mi*16 + a_row)*TSTR + kh*16 + a_kh8)*2);
            #pragma unroll
            for (int nb = 0; nb < 2; nb++)
                ldm_x4(bf[nb], sB + (uint32_t)((wn + nb*16 + b_row)*TSTR + kh*16 + b_kh8)*2);
            #pragma unroll
            for (int mi = 0; mi < 4; mi++) {
                #pragma unroll
                for (int ni = 0; ni < 4; ni++)
                    mma_f16(acc[mi][ni], af[mi], bf[ni >> 1] + (ni & 1)*2);
            }
        }
    }

    int gm = blockIdx.y*128 + wm;
    int gn = blockIdx.x*128 + wn;
    #pragma unroll
    for (int mi = 0; mi < 4; mi++) {
        #pragma unroll
        for (int ni = 0; ni < 4; ni++) {
            int row = gm + mi*16 + r4;
            int col = gn + ni*8 + l4*2;
            float2 v0 = make_float2(acc[mi][ni][0], acc[mi][ni][1]);
            float2 v1 = make_float2(acc[mi][ni][2], acc[mi][ni][3]);
            if (BIAS) {
                float2 bv = *(const float2*)(bias + col);
                v0.x += bv.x; v0.y += bv.y; v1.x += bv.x; v1.y += bv.y;
            }
            if (RELU) {
                v0.x = fmaxf(v0.x, 0.f); v0.y = fmaxf(v0.y, 0.f);
                v1.x = fmaxf(v1.x, 0.f); v1.y = fmaxf(v1.y, 0.f);
            }
            if (RES) {
                float2 r0 = *(const float2*)(res + (size_t)row*N + col);
                float2 r1 = *(const float2*)(res + (size_t)(row+8)*N + col);
                v0.x += r0.x; v0.y += r0.y; v1.x += r1.x; v1.y += r1.y;
            }
            if (OHALF) {
                __half* C = (__half*)Cv;
                __half2 h0 = __floats2half2_rn(v0.x, v0.y);
                __half2 h1 = __floats2half2_rn(v1.x, v1.y);
                *(__half2*)(C + (size_t)row*N + col)     = h0;
                *(__half2*)(C + (size_t)(row+8)*N + col) = h1;
            } else {
                float* C = (float*)Cv;
                *(float2*)(C + (size_t)row*N + col)     = v0;
                *(float2*)(C + (size_t)(row+8)*N + col) = v1;
            }
        }
    }
}

// ---------------------------------------------------------------------------
// Flash attention, fp16 inputs, cp.async double-buffered K/V.
// Block = 64 q rows of one (b,h), 128 threads (4 warps).
// ---------------------------------------------------------------------------
#define ASS 72
#define ATILE (64*ASS)                 // 4608 halfs per tile
#define FH_TOT (6*ATILE)               // Q, K0, K1, V0, V1, P
#define ATTN_SMEM (FH_TOT*2 + 2816)

__global__ __launch_bounds__(128)
void attn_mma(const __half* __restrict__ Qp, int qstride,
              const __half* __restrict__ Kp, const __half* __restrict__ Vp, int kvstride,
              __half* __restrict__ Op,
              const int* __restrict__ mtok, int causal) {
    extern __shared__ __half smh[];
    __half* Ps = smh + 5*ATILE;
    float* alphas = (float*)(smh + FH_TOT);
    float* linv   = alphas + 64;
    uint32_t* maskv = (uint32_t*)(linv + 64);   // [SEQ]

    int t = threadIdx.x, lane = t & 31, w = t >> 5;
    int r4 = lane >> 2, l4 = lane & 3;
    int q0 = blockIdx.x * 64, h = blockIdx.y, b = blockIdx.z;
    const __half* Qb = Qp + (size_t)b*SEQ*qstride  + h*DHEAD;
    const __half* Kb = Kp + (size_t)b*SEQ*kvstride + h*DHEAD;
    const __half* Vb = Vp + (size_t)b*SEQ*kvstride + h*DHEAD;

    uint32_t qs_b = smem_u32(smh);
    uint32_t ps_b = smem_u32(Ps);

    // ldmatrix lane address components
    int a_row = (lane & 15);
    int a_k8  = (lane >> 4) * 8;
    int b_row = (lane & 7) + ((lane >> 4) & 1) * 8;
    int b_k8  = ((lane >> 3) & 1) * 8;
    int v_s   = (lane & 7) + ((lane >> 4) & 1) * 8;
    int v_d8  = ((lane >> 3) & 1) * 8;

    int qcnk = q0 >> 6;
    int nchunks = causal ? (qcnk + 1) : (SEQ/64);

    auto issue_kv = [&](int kt, int buf) {
        uint32_t kbase = qs_b + (uint32_t)(1 + buf)*ATILE*2;
        uint32_t vbase = qs_b + (uint32_t)(3 + buf)*ATILE*2;
        const __half* Kc = Kb + (size_t)kt*64*kvstride;
        const __half* Vc = Vb + (size_t)kt*64*kvstride;
        #pragma unroll
        for (int i = 0; i < 4; i++) {
            int idx = t + i*128, s = idx >> 3, ch = idx & 7;
            uint32_t off = (uint32_t)(s*ASS + ch*8)*2;
            cp16(kbase + off, Kc + (size_t)s*kvstride + ch*8);
            cp16(vbase + off, Vc + (size_t)s*kvstride + ch*8);
        }
        CP_COMMIT();
    };

    // stage Q (cp.async) + mask preload
    #pragma unroll
    for (int i = 0; i < 4; i++) {
        int idx = t + i*128, s = idx >> 3, ch = idx & 7;
        cp16(qs_b + (uint32_t)(s*ASS + ch*8)*2, Qb + (size_t)(q0+s)*qstride + ch*8);
    }
    CP_COMMIT();
    #pragma unroll
    for (int i = 0; i < 4; i++) {
        int idx = t + i*128;
        maskv[idx] = (mtok[b*SEQ + idx] != 0);
    }
    issue_kv(0, 0);
    cp_wait<1>();          // Q group done (kv0 may still be in flight)
    __syncthreads();

    int m0 = w*16;
    uint32_t qf[4][4];
    #pragma unroll
    for (int kh = 0; kh < 4; kh++)
        ldm_x4(qf[kh], qs_b + (uint32_t)((m0 + a_row)*ASS + kh*16 + a_k8)*2);

    float oacc[8][4];
    #pragma unroll
    for (int j = 0; j < 8; j++)
        #pragma unroll
        for (int c = 0; c < 4; c++) oacc[j][c] = 0.f;
    float mrA = -1e30f, mrB = -1e30f, lrA = 0.f, lrB = 0.f;
    int qA = q0 + m0 + r4, qB = qA + 8;

    for (int kt = 0; kt < nchunks; kt++) {
        cp_wait<0>();
        __syncthreads();
        if (kt + 1 < nchunks) issue_kv(kt + 1, (kt + 1) & 1);
        uint32_t ks_b = qs_b + (uint32_t)(1 + (kt & 1))*ATILE*2;
        uint32_t vs_b = qs_b + (uint32_t)(3 + (kt & 1))*ATILE*2;

        // ---- S = Q K^T ----
        float sacc[8][4];
        #pragma unroll
        for (int j = 0; j < 8; j++)
            #pragma unroll
            for (int c = 0; c < 4; c++) sacc[j][c] = 0.f;
        #pragma unroll
        for (int kh = 0; kh < 4; kh++) {
            uint32_t bf[4][4];
            #pragma unroll
            for (int nb = 0; nb < 4; nb++)
                ldm_x4(bf[nb], ks_b + (uint32_t)((nb*16 + b_row)*ASS + kh*16 + b_k8)*2);
            #pragma unroll
            for (int nb = 0; nb < 4; nb++) {
                mma_f16(sacc[nb*2],     qf[kh], bf[nb]);
                mma_f16(sacc[nb*2 + 1], qf[kh], bf[nb] + 2);
            }
        }
        // ---- mask + scale + row max ----
        bool diag = causal && (kt == qcnk);
        float mA = -1e30f, mB = -1e30f;
        #pragma unroll
        for (int j = 0; j < 8; j++) {
            int kl = j*8 + 2*l4;
            int kg = kt*64 + kl;
            bool pv0 = maskv[kg] != 0, pv1 = maskv[kg+1] != 0;
            bool a0 = pv0 && (!diag || kg   <= qA);
            bool a1 = pv1 && (!diag || kg+1 <= qA);
            bool b0 = pv0 && (!diag || kg   <= qB);
            bool b1 = pv1 && (!diag || kg+1 <= qB);
            sacc[j][0] = a0 ? sacc[j][0]*0.125f : -1e9f;
            sacc[j][1] = a1 ? sacc[j][1]*0.125f : -1e9f;
            sacc[j][2] = b0 ? sacc[j][2]*0.125f : -1e9f;
            sacc[j][3] = b1 ? sacc[j][3]*0.125f : -1e9f;
            mA = fmaxf(mA, fmaxf(sacc[j][0], sacc[j][1]));
            mB = fmaxf(mB, fmaxf(sacc[j][2], sacc[j][3]));
        }
        mA = fmaxf(mA, __shfl_xor_sync(0xffffffffu, mA, 1));
        mA = fmaxf(mA, __shfl_xor_sync(0xffffffffu, mA, 2));
        mB = fmaxf(mB, __shfl_xor_sync(0xffffffffu, mB, 1));
        mB = fmaxf(mB, __shfl_xor_sync(0xffffffffu, mB, 2));
        float mnA = fmaxf(mrA, mA), mnB = fmaxf(mrB, mB);
        float aA = __expf(mrA - mnA), aB = __expf(mrB - mnB);
        mrA = mnA; mrB = mnB;
        // ---- exp + write P (half) + row sums ----
        float lA = 0.f, lB = 0.f;
        #pragma unroll
        for (int j = 0; j < 8; j++) {
            float p0 = __expf(sacc[j][0] - mnA);
            float p1 = __expf(sacc[j][1] - mnA);
            float p2 = __expf(sacc[j][2] - mnB);
            float p3 = __expf(sacc[j][3] - mnB);
            lA += p0 + p1; lB += p2 + p3;
            *(__half2*)(Ps + (m0 + r4)*ASS     + j*8 + 2*l4) = __floats2half2_rn(p0, p1);
            *(__half2*)(Ps + (m0 + r4 + 8)*ASS + j*8 + 2*l4) = __floats2half2_rn(p2, p3);
        }
        lA += __shfl_xor_sync(0xffffffffu, lA, 1);
        lA += __shfl_xor_sync(0xffffffffu, lA, 2);
        lB += __shfl_xor_sync(0xffffffffu, lB, 1);
        lB += __shfl_xor_sync(0xffffffffu, lB, 2);
        lrA = lrA*aA + lA;
        lrB = lrB*aB + lB;
        if (l4 == 0) {
            alphas[m0 + r4]     = aA;
            alphas[m0 + r4 + 8] = aB;
            if (kt == nchunks - 1) {
                linv[m0 + r4]     = 1.f / lrA;
                linv[m0 + r4 + 8] = 1.f / lrB;
            }
        }
        __syncthreads();

        // ---- PV: O^T[d,q] += V^T P^T ----
        #pragma unroll
        for (int j = 0; j < 8; j++) {
            float a0 = alphas[j*8 + 2*l4];
            float a1 = alphas[j*8 + 2*l4 + 1];
            oacc[j][0] *= a0; oacc[j][1] *= a1;
            oacc[j][2] *= a0; oacc[j][3] *= a1;
        }
        #pragma unroll
        for (int kh = 0; kh < 4; kh++) {
            uint32_t af[4];
            ldm_x4_t(af, vs_b + (uint32_t)((kh*16 + v_s)*ASS + m0 + v_d8)*2);
            #pragma unroll
            for (int jb = 0; jb < 4; jb++) {
                uint32_t bf[4];
                ldm_x4(bf, ps_b + (uint32_t)((jb*16 + b_row)*ASS + kh*16 + b_k8)*2);
                mma_f16(oacc[jb*2],     af, bf);
                mma_f16(oacc[jb*2 + 1], af, bf + 2);
            }
        }
    }

    // ---- output fp16 ----
    #pragma unroll
    for (int j = 0; j < 8; j++) {
        int qc2 = j*8 + 2*l4;
        float i0 = linv[qc2], i1 = linv[qc2 + 1];
        int d0 = m0 + r4;
        size_t ro0 = ((size_t)b*SEQ + q0 + qc2)*DMODEL + h*DHEAD;
        size_t ro1 = ro0 + DMODEL;
        Op[ro0 + d0]     = __float2half_rn(oacc[j][0]*i0);
        Op[ro1 + d0]     = __float2half_rn(oacc[j][1]*i1);
        Op[ro0 + d0 + 8] = __float2half_rn(oacc[j][2]*i0);
        Op[ro1 + d0 + 8] = __float2half_rn(oacc[j][3]*i1);
    }
}

// ---------------------------------------------------------------------------
// Orchestration
// ---------------------------------------------------------------------------
static inline void launch_gemm(const __half* A, const __half* W, const float* bias,
                               const float* res, void* C, int M, int N, int K,
                               bool relu, bool ohalf) {
    dim3 grid(N/128, M/128), block(256);
    if (res) {
        cudaFuncSetAttribute(gemm_mma<false,true,true,false>, cudaFuncAttributeMaxDynamicSharedMemorySize, GEMM_SMEM);
        gemm_mma<false,true,true,false><<<grid, block, GEMM_SMEM>>>(A, W, bias, res, C, M, N, K);
    } else if (relu) {
        cudaFuncSetAttribute(gemm_mma<true,false,true,true>, cudaFuncAttributeMaxDynamicSharedMemorySize, GEMM_SMEM);
        gemm_mma<true,false,true,true><<<grid, block, GEMM_SMEM>>>(A, W, bias, nullptr, C, M, N, K);
    } else if (bias) {
        cudaFuncSetAttribute(gemm_mma<false,false,true,true>, cudaFuncAttributeMaxDynamicSharedMemorySize, GEMM_SMEM);
        gemm_mma<false,false,true,true><<<grid, block, GEMM_SMEM>>>(A, W, bias, nullptr, C, M, N, K);
    } else {
        cudaFuncSetAttribute(gemm_mma<false,false,false,false>, cudaFuncAttributeMaxDynamicSharedMemorySize, GEMM_SMEM);
        gemm_mma<false,false,false,false><<<grid, block, GEMM_SMEM>>>(A, W, nullptr, nullptr, C, M, N, K);
    }
}

extern "C" void kernel_launch(void* const* d_in, const int* in_sizes, int n_in,
                              void* d_out, int out_size) {
    const int*   src        = (const int*)  d_in[0];
    const int*   tgt        = (const int*)  d_in[1];
    const float* emb        = (const float*)d_in[2];
    const float* enc_attn_w = (const float*)d_in[3];
    const float* enc_attn_b = (const float*)d_in[4];
    const float* enc_ln_g   = (const float*)d_in[5];
    const float* enc_ln_b   = (const float*)d_in[6];
    const float* enc_w1     = (const float*)d_in[7];
    const float* enc_b1     = (const float*)d_in[8];
    const float* enc_w2     = (const float*)d_in[9];
    const float* enc_b2     = (const float*)d_in[10];
    const float* dec_attn_w = (const float*)d_in[11];
    const float* dec_attn_b = (const float*)d_in[12];
    const float* dec_ln_g   = (const float*)d_in[13];
    const float* dec_ln_b   = (const float*)d_in[14];
    const float* dec_w1     = (const float*)d_in[15];
    const float* dec_b1     = (const float*)d_in[16];
    const float* dec_w2     = (const float*)d_in[17];
    const float* dec_b2     = (const float*)d_in[18];
    const float* enc_norm_g = (const float*)d_in[19];
    const float* enc_norm_b = (const float*)d_in[20];
    const float* dec_norm_g = (const float*)d_in[21];
    const float* dec_norm_b = (const float*)d_in[22];

    float *x;
    __half *x2, *qb, *ctx, *enc, *hbuf, *qkv, *kv, *wv;
    cudaGetSymbolAddress((void**)&x,    g_x);
    cudaGetSymbolAddress((void**)&x2,   g_x2);
    cudaGetSymbolAddress((void**)&qb,   g_q);
    cudaGetSymbolAddress((void**)&ctx,  g_ctx);
    cudaGetSymbolAddress((void**)&enc,  g_enc);
    cudaGetSymbolAddress((void**)&hbuf, g_h);
    cudaGetSymbolAddress((void**)&qkv,  g_qkv);
    cudaGetSymbolAddress((void**)&kv,   g_kv);
    cudaGetSymbolAddress((void**)&wv,   g_w);

    cudaFuncSetAttribute(attn_mma, cudaFuncAttributeMaxDynamicSharedMemorySize, ATTN_SMEM);

    // --------------- weight conversion (fp16) ---------------
    {
        struct { const float* src; int off; int n; } cv[7] = {
            { enc_attn_w, OFF_ENC_ATTN, NLAYER*4*DMODEL*DMODEL },
            { enc_w1,     OFF_ENC_W1,   NLAYER*DFF*DMODEL },
            { enc_w2,     OFF_ENC_W2,   NLAYER*DMODEL*DFF },
            { dec_attn_w, OFF_DEC_ATTN, NLAYER*8*DMODEL*DMODEL },
            { dec_w1,     OFF_DEC_W1,   NLAYER*DFF*DMODEL },
            { dec_w2,     OFF_DEC_W2,   NLAYER*DMODEL*DFF },
            { emb,        OFF_EMB,      VOCAB*DMODEL },
        };
        for (int i = 0; i < 7; i++)
            cvt_kernel<<<cv[i].n/2048, 256>>>(cv[i].src, wv + cv[i].off, cv[i].n);
    }

    const int D = DMODEL, M = MROWS;
    const size_t WSZ = (size_t)D*D;
    dim3 attnGrid(SEQ/64, NHEAD, BATCH);
    const __half* ew = wv + OFF_ENC_ATTN;
    const __half* dw = wv + OFF_DEC_ATTN;

    // ===================== ENCODER =====================
    embed_kernel<<<M, 128>>>(src, emb, x);
    for (int l = 0; l < NLAYER; l++) {
        const __half* w  = ew + (size_t)l*4*WSZ;
        const float*  bb = enc_attn_b + (size_t)l*4*D;
        ln_kernel<<<M/8, 256>>>(x, enc_ln_g + (size_t)(l*2+0)*D, enc_ln_b + (size_t)(l*2+0)*D, x2);
        launch_gemm(x2, w, bb, nullptr, qkv, M, 3*D, D, false, true);
        attn_mma<<<attnGrid, 128, ATTN_SMEM>>>(qkv, 3*D, qkv + D, qkv + 2*D, 3*D, ctx, src, 0);
        launch_gemm(ctx, w + 3*WSZ, bb + 3*D, x, x, M, D, D, false, false);
        ln_kernel<<<M/8, 256>>>(x, enc_ln_g + (size_t)(l*2+1)*D, enc_ln_b + (size_t)(l*2+1)*D, x2);
        launch_gemm(x2, wv + OFF_ENC_W1 + (size_t)l*DFF*D, enc_b1 + (size_t)l*DFF, nullptr, hbuf, M, DFF, D, true, true);
        launch_gemm(hbuf, wv + OFF_ENC_W2 + (size_t)l*D*DFF, enc_b2 + (size_t)l*D, x, x, M, D, DFF, false, false);
    }
    ln_kernel<<<M/8, 256>>>(x, enc_norm_g, enc_norm_b, enc);

    // ===================== DECODER =====================
    embed_kernel<<<M, 128>>>(tgt, emb, x);
    for (int l = 0; l < NLAYER; l++) {
        const __half* w  = dw + (size_t)l*8*WSZ;
        const float*  bb = dec_attn_b + (size_t)l*8*D;
        ln_kernel<<<M/8, 256>>>(x, dec_ln_g + (size_t)(l*3+0)*D, dec_ln_b + (size_t)(l*3+0)*D, x2);
        launch_gemm(x2, w, bb, nullptr, qkv, M, 3*D, D, false, true);
        attn_mma<<<attnGrid, 128, ATTN_SMEM>>>(qkv, 3*D, qkv + D, qkv + 2*D, 3*D, ctx, tgt, 1);
        launch_gemm(ctx, w + 3*WSZ, bb + 3*D, x, x, M, D, D, false, false);
        ln_kernel<<<M/8, 256>>>(x, dec_ln_g + (size_t)(l*3+1)*D, dec_ln_b + (size_t)(l*3+1)*D, x2);
        launch_gemm(x2,  w + 4*WSZ, bb + 4*D, nullptr, qb, M, D, D, false, true);
        launch_gemm(enc, w + 5*WSZ, bb + 5*D, nullptr, kv, M, 2*D, D, false, true);
        attn_mma<<<attnGrid, 128, ATTN_SMEM>>>(qb, D, kv, kv + D, 2*D, ctx, src, 0);
        launch_gemm(ctx, w + 7*WSZ, bb + 7*D, x, x, M, D, D, false, false);
        ln_kernel<<<M/8, 256>>>(x, dec_ln_g + (size_t)(l*3+2)*D, dec_ln_b + (size_t)(l*3+2)*D, x2);
        launch_gemm(x2, wv + OFF_DEC_W1 + (size_t)l*DFF*D, dec_b1 + (size_t)l*DFF, nullptr, hbuf, M, DFF, D, true, true);
        launch_gemm(hbuf, wv + OFF_DEC_W2 + (size_t)l*D*DFF, dec_b2 + (size_t)l*D, x, x, M, D, DFF, false, false);
    }
    ln_kernel<<<M/8, 256>>>(x, dec_norm_g, dec_norm_b, x2);

    // ===================== tied output projection =====================
    launch_gemm(x2, wv + OFF_EMB, nullptr, nullptr, (float*)d_out, M, VOCAB, D, false, false);
}

// round 9
// speedup vs baseline: 11.9095x; 1.0005x over previous
#include <cuda_runtime.h>
#include <cuda_fp16.h>
#include <cstdint>
#include <math.h>

// ---------------------------------------------------------------------------
// Problem constants
// ---------------------------------------------------------------------------
#define BATCH 8
#define SEQ   512
#define DMODEL 512
#define NHEAD 8
#define DHEAD 64
#define NLAYER 4
#define DFF   2048
#define VOCAB 32000
#define MROWS (BATCH*SEQ)   // 4096

__device__ __forceinline__ uint32_t smem_u32(const void* p) {
    uint32_t a;
    asm("{ .reg .u64 t; cvta.to.shared.u64 t, %1; cvt.u32.u64 %0, t; }" : "=r"(a) : "l"(p));
    return a;
}
__device__ __forceinline__ void cp16(uint32_t s, const void* g) {
    asm volatile("cp.async.cg.shared.global [%0], [%1], 16;" :: "r"(s), "l"(g));
}
#define CP_COMMIT() asm volatile("cp.async.commit_group;" ::: "memory")
template<int N> __device__ __forceinline__ void cp_wait() {
    asm volatile("cp.async.wait_group %0;" :: "n"(N) : "memory");
}
__device__ __forceinline__ void ldm_x4(uint32_t* r, uint32_t addr) {
    asm volatile("ldmatrix.sync.aligned.m8n8.x4.shared.b16 {%0,%1,%2,%3}, [%4];"
        : "=r"(r[0]), "=r"(r[1]), "=r"(r[2]), "=r"(r[3]) : "r"(addr));
}
__device__ __forceinline__ void ldm_x4_t(uint32_t* r, uint32_t addr) {
    asm volatile("ldmatrix.sync.aligned.m8n8.x4.trans.shared.b16 {%0,%1,%2,%3}, [%4];"
        : "=r"(r[0]), "=r"(r[1]), "=r"(r[2]), "=r"(r[3]) : "r"(addr));
}
__device__ __forceinline__ void mma_f16(float* c, const uint32_t* a, const uint32_t* b) {
    asm volatile(
        "mma.sync.aligned.m16n8k16.row.col.f32.f16.f16.f32 "
        "{%0,%1,%2,%3}, {%4,%5,%6,%7}, {%8,%9}, {%0,%1,%2,%3};"
        : "+f"(c[0]), "+f"(c[1]), "+f"(c[2]), "+f"(c[3])
        : "r"(a[0]), "r"(a[1]), "r"(a[2]), "r"(a[3]), "r"(b[0]), "r"(b[1]));
}

// ---------------------------------------------------------------------------
// Scratch (device globals; no allocation allowed)
// ---------------------------------------------------------------------------
__device__ __align__(16) float  g_x  [MROWS*DMODEL];
__device__ __align__(16) __half g_x2 [MROWS*DMODEL];
__device__ __align__(16) __half g_q  [MROWS*DMODEL];
__device__ __align__(16) __half g_ctx[MROWS*DMODEL];
__device__ __align__(16) __half g_enc[MROWS*DMODEL];
__device__ __align__(16) __half g_h  [MROWS*DFF];
__device__ __align__(16) __half g_qkv[MROWS*3*DMODEL];
__device__ __align__(16) __half g_kv [MROWS*2*DMODEL];

// converted-weight arena (fp16)
#define OFF_ENC_ATTN 0
#define OFF_ENC_W1   (OFF_ENC_ATTN + NLAYER*4*DMODEL*DMODEL)
#define OFF_ENC_W2   (OFF_ENC_W1   + NLAYER*DFF*DMODEL)
#define OFF_DEC_ATTN (OFF_ENC_W2   + NLAYER*DMODEL*DFF)
#define OFF_DEC_W1   (OFF_DEC_ATTN + NLAYER*8*DMODEL*DMODEL)
#define OFF_DEC_W2   (OFF_DEC_W1   + NLAYER*DFF*DMODEL)
#define OFF_EMB      (OFF_DEC_W2   + NLAYER*DMODEL*DFF)
#define W_TOTAL      (OFF_EMB      + VOCAB*DMODEL)
__device__ __align__(16) __half g_w[W_TOTAL];

// ---------------------------------------------------------------------------
// fp32 -> fp16 conversion
// ---------------------------------------------------------------------------
__global__ void cvt_kernel(const float* __restrict__ in, __half* __restrict__ out, int n) {
    int i = (blockIdx.x*blockDim.x + threadIdx.x)*8;
    if (i < n) {
        float4 a = *(const float4*)(in + i);
        float4 b = *(const float4*)(in + i + 4);
        __half2 h0 = __floats2half2_rn(a.x, a.y);
        __half2 h1 = __floats2half2_rn(a.z, a.w);
        __half2 h2 = __floats2half2_rn(b.x, b.y);
        __half2 h3 = __floats2half2_rn(b.z, b.w);
        uint4 o;
        o.x = *(uint32_t*)&h0; o.y = *(uint32_t*)&h1;
        o.z = *(uint32_t*)&h2; o.w = *(uint32_t*)&h3;
        *(uint4*)(out + i) = o;
    }
}

// ---------------------------------------------------------------------------
// Embedding + sinusoidal positional encoding (residual stream, fp32)
// ---------------------------------------------------------------------------
__global__ void embed_kernel(const int* __restrict__ tok,
                             const float* __restrict__ emb,
                             float* __restrict__ y) {
    int row = blockIdx.x;
    int s   = row % SEQ;
    int t   = tok[row];
    const float scale = 22.62741699796952f;
    const float c0 = -9.210340371976184f / (float)DMODEL;
    int tid = threadIdx.x;
    #pragma unroll
    for (int i = 0; i < 4; i++) {
        int d = tid + i*128;
        float e = (t == 0) ? 0.f : emb[(size_t)t*DMODEL + d];
        int half = d >> 1;
        float div = expf((float)(2*half) * c0);
        float ang = (float)s * div;
        float pe = (d & 1) ? cosf(ang) : sinf(ang);
        y[(size_t)row*DMODEL + d] = e*scale + pe;
    }
}

// ---------------------------------------------------------------------------
// LayerNorm, warp-per-row (8 rows / 256-thread block, no __syncthreads).
// ---------------------------------------------------------------------------
__global__ __launch_bounds__(256)
void ln_kernel(const float* __restrict__ x,
               const float* __restrict__ g,
               const float* __restrict__ b,
               __half* __restrict__ y) {
    int row  = blockIdx.x*8 + (threadIdx.x >> 5);
    int lane = threadIdx.x & 31;
    const float* xr = x + (size_t)row*DMODEL;
    float4 v[4];
    float s = 0.f;
    #pragma unroll
    for (int c = 0; c < 4; c++) {
        v[c] = *(const float4*)(xr + lane*4 + c*128);
        s += (v[c].x + v[c].y) + (v[c].z + v[c].w);
    }
    #pragma unroll
    for (int o = 16; o > 0; o >>= 1) s += __shfl_xor_sync(0xffffffffu, s, o);
    float mean = s * (1.f/(float)DMODEL);
    float vs = 0.f;
    #pragma unroll
    for (int c = 0; c < 4; c++) {
        float d0 = v[c].x-mean, d1 = v[c].y-mean, d2 = v[c].z-mean, d3 = v[c].w-mean;
        vs += d0*d0 + d1*d1 + d2*d2 + d3*d3;
    }
    #pragma unroll
    for (int o = 16; o > 0; o >>= 1) vs += __shfl_xor_sync(0xffffffffu, vs, o);
    float inv = rsqrtf(vs * (1.f/(float)DMODEL) + 1e-5f);
    #pragma unroll
    for (int c = 0; c < 4; c++) {
        int d = lane*4 + c*128;
        float4 gv = *(const float4*)(g + d);
        float4 bv = *(const float4*)(b + d);
        float r0 = (v[c].x-mean)*inv*gv.x + bv.x;
        float r1 = (v[c].y-mean)*inv*gv.y + bv.y;
        float r2 = (v[c].z-mean)*inv*gv.z + bv.z;
        float r3 = (v[c].w-mean)*inv*gv.w + bv.w;
        __half2 h0 = __floats2half2_rn(r0, r1);
        __half2 h1 = __floats2half2_rn(r2, r3);
        uint2 o; o.x = *(uint32_t*)&h0; o.y = *(uint32_t*)&h1;
        *(uint2*)(y + (size_t)row*DMODEL + d) = o;
    }
}

// ---------------------------------------------------------------------------
// fp16 mma.sync GEMM, CTA 128x128x32 (wide-N shapes). (unchanged)
// ---------------------------------------------------------------------------
#define TSTR 40
#define TILE_HALFS (128*TSTR)
#define STAGE_HALFS (2*TILE_HALFS)
#define GEMM_SMEM (3*STAGE_HALFS*2)

template<bool RELU, bool RES, bool BIAS, bool OHALF>
__global__ __launch_bounds__(256, 2)
void gemm_mma(const __half* __restrict__ A, const __half* __restrict__ W,
              const float* __restrict__ bias, const float* __restrict__ res,
              void* __restrict__ Cv, int M, int N, int K) {
    extern __shared__ __half smh[];
    int t = threadIdx.x, lane = t & 31, wid = t >> 5;
    int wm = (wid & 1) * 64;
    int wn = (wid >> 1) * 32;
    int r4 = lane >> 2, l4 = lane & 3;

    const __half* Ab = A + (size_t)blockIdx.y*128*K;
    const __half* Wb = W + (size_t)blockIdx.x*128*K;
    uint32_t sbase = smem_u32(smh);

    float acc[4][4][4];
    #pragma unroll
    for (int i = 0; i < 4; i++)
        #pragma unroll
        for (int j = 0; j < 4; j++)
            #pragma unroll
            for (int c = 0; c < 4; c++) acc[i][j][c] = 0.f;

    int NK = K >> 5;

    auto issue = [&](int it, int buf) {
        uint32_t base = sbase + (uint32_t)buf*STAGE_HALFS*2;
        int k0 = it*32;
        #pragma unroll
        for (int i = 0; i < 2; i++) {
            int idx = t + i*256, r = idx >> 2, ch = idx & 3;
            uint32_t off = (uint32_t)(r*TSTR + ch*8)*2;
            cp16(base + off,                  Ab + (size_t)r*K + k0 + ch*8);
            cp16(base + TILE_HALFS*2 + off,   Wb + (size_t)r*K + k0 + ch*8);
        }
        CP_COMMIT();
    };

    issue(0, 0);
    issue(1, 1);

    int a_row = (lane & 15);
    int a_kh8 = (lane >> 4) * 8;
    int b_row = (lane & 7) + ((lane >> 4) & 1) * 8;
    int b_kh8 = ((lane >> 3) & 1) * 8;

    for (int it = 0; it < NK; it++) {
        if (it + 1 < NK) cp_wait<1>(); else cp_wait<0>();
        __syncthreads();
        if (it + 2 < NK) issue(it + 2, (it + 2) % 3);
        uint32_t sA = sbase + (uint32_t)(it % 3)*STAGE_HALFS*2;
        uint32_t sB = sA + TILE_HALFS*2;
        #pragma unroll
        for (int kh = 0; kh < 2; kh++) {
            uint32_t af[4][4], bf[2][4];
            #pragma unroll
            for (int mi = 0; mi < 4; mi++)
                ldm_x4(af[mi], sA + (uint32_t)((wm + mi*16 + a_row)*TSTR + kh*16 + a_kh8)*2);
            #pragma unroll
            for (int nb = 0; nb < 2; nb++)
                ldm_x4(bf[nb], sB + (uint32_t)((wn + nb*16 + b_row)*TSTR + kh*16 + b_kh8)*2);
            #pragma unroll
            for (int mi = 0; mi < 4; mi++) {
                #pragma unroll
                for (int ni = 0; ni < 4; ni++)
                    mma_f16(acc[mi][ni], af[mi], bf[ni >> 1] + (ni & 1)*2);
            }
        }
    }

    int gm = blockIdx.y*128 + wm;
    int gn = blockIdx.x*128 + wn;
    #pragma unroll
    for (int mi = 0; mi < 4; mi++) {
        #pragma unroll
        for (int ni = 0; ni < 4; ni++) {
            int row = gm + mi*16 + r4;
            int col = gn + ni*8 + l4*2;
            float2 v0 = make_float2(acc[mi][ni][0], acc[mi][ni][1]);
            float2 v1 = make_float2(acc[mi][ni][2], acc[mi][ni][3]);
            if (BIAS) {
                float2 bv = *(const float2*)(bias + col);
                v0.x += bv.x; v0.y += bv.y; v1.x += bv.x; v1.y += bv.y;
            }
            if (RELU) {
                v0.x = fmaxf(v0.x, 0.f); v0.y = fmaxf(v0.y, 0.f);
                v1.x = fmaxf(v1.x, 0.f); v1.y = fmaxf(v1.y, 0.f);
            }
            if (RES) {
                float2 r0 = *(const float2*)(res + (size_t)row*N + col);
                float2 r1 = *(const float2*)(res + (size_t)(row+8)*N + col);
                v0.x += r0.x; v0.y += r0.y; v1.x += r1.x; v1.y += r1.y;
            }
            if (OHALF) {
                __half* C = (__half*)Cv;
                __half2 h0 = __floats2half2_rn(v0.x, v0.y);
                __half2 h1 = __floats2half2_rn(v1.x, v1.y);
                *(__half2*)(C + (size_t)row*N + col)     = h0;
                *(__half2*)(C + (size_t)(row+8)*N + col) = h1;
            } else {
                float* C = (float*)Cv;
                *(float2*)(C + (size_t)row*N + col)     = v0;
                *(float2*)(C + (size_t)(row+8)*N + col) = v1;
            }
        }
    }
}

// ---------------------------------------------------------------------------
// fp16 mma.sync GEMM, CTA 64x128x32 (narrow-N shapes: 2x the grid).
// 8 warps, warp tile 32x32. smem/stage 15360B, 3 stages.
// ---------------------------------------------------------------------------
#define A64_HALFS (64*TSTR)              // 2560
#define S64_HALFS (A64_HALFS + TILE_HALFS)  // A + B = 7680
#define GEMM64_SMEM (3*S64_HALFS*2)      // 46080

template<bool RELU, bool RES, bool BIAS, bool OHALF>
__global__ __launch_bounds__(256)
void gemm_mma64(const __half* __restrict__ A, const __half* __restrict__ W,
                const float* __restrict__ bias, const float* __restrict__ res,
                void* __restrict__ Cv, int M, int N, int K) {
    extern __shared__ __half smh[];
    int t = threadIdx.x, lane = t & 31, wid = t >> 5;
    int wm = (wid & 1) * 32;
    int wn = (wid >> 1) * 32;
    int r4 = lane >> 2, l4 = lane & 3;

    const __half* Ab = A + (size_t)blockIdx.y*64*K;
    const __half* Wb = W + (size_t)blockIdx.x*128*K;
    uint32_t sbase = smem_u32(smh);

    float acc[2][4][4];
    #pragma unroll
    for (int i = 0; i < 2; i++)
        #pragma unroll
        for (int j = 0; j < 4; j++)
            #pragma unroll
            for (int c = 0; c < 4; c++) acc[i][j][c] = 0.f;

    int NK = K >> 5;

    auto issue = [&](int it, int buf) {
        uint32_t base = sbase + (uint32_t)buf*S64_HALFS*2;
        int k0 = it*32;
        {   // A: 64 rows x 4 chunks = 256
            int r = t >> 2, ch = t & 3;
            cp16(base + (uint32_t)(r*TSTR + ch*8)*2, Ab + (size_t)r*K + k0 + ch*8);
        }
        #pragma unroll
        for (int i = 0; i < 2; i++) {   // B: 128 rows x 4 chunks = 512
            int idx = t + i*256, r = idx >> 2, ch = idx & 3;
            cp16(base + A64_HALFS*2 + (uint32_t)(r*TSTR + ch*8)*2,
                 Wb + (size_t)r*K + k0 + ch*8);
        }
        CP_COMMIT();
    };

    issue(0, 0);
    issue(1, 1);

    int a_row = (lane & 15);
    int a_kh8 = (lane >> 4) * 8;
    int b_row = (lane & 7) + ((lane >> 4) & 1) * 8;
    int b_kh8 = ((lane >> 3) & 1) * 8;

    for (int it = 0; it < NK; it++) {
        if (it + 1 < NK) cp_wait<1>(); else cp_wait<0>();
        __syncthreads();
        if (it + 2 < NK) issue(it + 2, (it + 2) % 3);
        uint32_t sA = sbase + (uint32_t)(it % 3)*S64_HALFS*2;
        uint32_t sB = sA + A64_HALFS*2;
        #pragma unroll
        for (int kh = 0; kh < 2; kh++) {
            uint32_t af[2][4], bf[2][4];
            #pragma unroll
            for (int mi = 0; mi < 2; mi++)
                ldm_x4(af[mi], sA + (uint32_t)((wm + mi*16 + a_row)*TSTR + kh*16 + a_kh8)*2);
            #pragma unroll
            for (int nb = 0; nb < 2; nb++)
                ldm_x4(bf[nb], sB + (uint32_t)((wn + nb*16 + b_row)*TSTR + kh*16 + b_kh8)*2);
            #pragma unroll
            for (int mi = 0; mi < 2; mi++) {
                #pragma unroll
                for (int ni = 0; ni < 4; ni++)
                    mma_f16(acc[mi][ni], af[mi], bf[ni >> 1] + (ni & 1)*2);
            }
        }
    }

    int gm = blockIdx.y*64 + wm;
    int gn = blockIdx.x*128 + wn;
    #pragma unroll
    for (int mi = 0; mi < 2; mi++) {
        #pragma unroll
        for (int ni = 0; ni < 4; ni++) {
            int row = gm + mi*16 + r4;
            int col = gn + ni*8 + l4*2;
            float2 v0 = make_float2(acc[mi][ni][0], acc[mi][ni][1]);
            float2 v1 = make_float2(acc[mi][ni][2], acc[mi][ni][3]);
            if (BIAS) {
                float2 bv = *(const float2*)(bias + col);
                v0.x += bv.x; v0.y += bv.y; v1.x += bv.x; v1.y += bv.y;
            }
            if (RELU) {
                v0.x = fmaxf(v0.x, 0.f); v0.y = fmaxf(v0.y, 0.f);
                v1.x = fmaxf(v1.x, 0.f); v1.y = fmaxf(v1.y, 0.f);
            }
            if (RES) {
                float2 r0 = *(const float2*)(res + (size_t)row*N + col);
                float2 r1 = *(const float2*)(res + (size_t)(row+8)*N + col);
                v0.x += r0.x; v0.y += r0.y; v1.x += r1.x; v1.y += r1.y;
            }
            if (OHALF) {
                __half* C = (__half*)Cv;
                *(__half2*)(C + (size_t)row*N + col)     = __floats2half2_rn(v0.x, v0.y);
                *(__half2*)(C + (size_t)(row+8)*N + col) = __floats2half2_rn(v1.x, v1.y);
            } else {
                float* C = (float*)Cv;
                *(float2*)(C + (size_t)row*N + col)     = v0;
                *(float2*)(C + (size_t)(row+8)*N + col) = v1;
            }
        }
    }
}

// ---------------------------------------------------------------------------
// Flash attention, fp16 inputs, cp.async double-buffered K/V. (R8, unchanged)
// ---------------------------------------------------------------------------
#define ASS 72
#define ATILE (64*ASS)
#define FH_TOT (6*ATILE)
#define ATTN_SMEM (FH_TOT*2 + 2816)

__global__ __launch_bounds__(128)
void attn_mma(const __half* __restrict__ Qp, int qstride,
              const __half* __restrict__ Kp, const __half* __restrict__ Vp, int kvstride,
              __half* __restrict__ Op,
              const int* __restrict__ mtok, int causal) {
    extern __shared__ __half smh[];
    __half* Ps = smh + 5*ATILE;
    float* alphas = (float*)(smh + FH_TOT);
    float* linv   = alphas + 64;
    uint32_t* maskv = (uint32_t*)(linv + 64);

    int t = threadIdx.x, lane = t & 31, w = t >> 5;
    int r4 = lane >> 2, l4 = lane & 3;
    int q0 = blockIdx.x * 64, h = blockIdx.y, b = blockIdx.z;
    const __half* Qb = Qp + (size_t)b*SEQ*qstride  + h*DHEAD;
    const __half* Kb = Kp + (size_t)b*SEQ*kvstride + h*DHEAD;
    const __half* Vb = Vp + (size_t)b*SEQ*kvstride + h*DHEAD;

    uint32_t qs_b = smem_u32(smh);
    uint32_t ps_b = smem_u32(Ps);

    int a_row = (lane & 15);
    int a_k8  = (lane >> 4) * 8;
    int b_row = (lane & 7) + ((lane >> 4) & 1) * 8;
    int b_k8  = ((lane >> 3) & 1) * 8;
    int v_s   = (lane & 7) + ((lane >> 4) & 1) * 8;
    int v_d8  = ((lane >> 3) & 1) * 8;

    int qcnk = q0 >> 6;
    int nchunks = causal ? (qcnk + 1) : (SEQ/64);

    auto issue_kv = [&](int kt, int buf) {
        uint32_t kbase = qs_b + (uint32_t)(1 + buf)*ATILE*2;
        uint32_t vbase = qs_b + (uint32_t)(3 + buf)*ATILE*2;
        const __half* Kc = Kb + (size_t)kt*64*kvstride;
        const __half* Vc = Vb + (size_t)kt*64*kvstride;
        #pragma unroll
        for (int i = 0; i < 4; i++) {
            int idx = t + i*128, s = idx >> 3, ch = idx & 7;
            uint32_t off = (uint32_t)(s*ASS + ch*8)*2;
            cp16(kbase + off, Kc + (size_t)s*kvstride + ch*8);
            cp16(vbase + off, Vc + (size_t)s*kvstride + ch*8);
        }
        CP_COMMIT();
    };

    #pragma unroll
    for (int i = 0; i < 4; i++) {
        int idx = t + i*128, s = idx >> 3, ch = idx & 7;
        cp16(qs_b + (uint32_t)(s*ASS + ch*8)*2, Qb + (size_t)(q0+s)*qstride + ch*8);
    }
    CP_COMMIT();
    #pragma unroll
    for (int i = 0; i < 4; i++) {
        int idx = t + i*128;
        maskv[idx] = (mtok[b*SEQ + idx] != 0);
    }
    issue_kv(0, 0);
    cp_wait<1>();
    __syncthreads();

    int m0 = w*16;
    uint32_t qf[4][4];
    #pragma unroll
    for (int kh = 0; kh < 4; kh++)
        ldm_x4(qf[kh], qs_b + (uint32_t)((m0 + a_row)*ASS + kh*16 + a_k8)*2);

    float oacc[8][4];
    #pragma unroll
    for (int j = 0; j < 8; j++)
        #pragma unroll
        for (int c = 0; c < 4; c++) oacc[j][c] = 0.f;
    float mrA = -1e30f, mrB = -1e30f, lrA = 0.f, lrB = 0.f;
    int qA = q0 + m0 + r4, qB = qA + 8;

    for (int kt = 0; kt < nchunks; kt++) {
        cp_wait<0>();
        __syncthreads();
        if (kt + 1 < nchunks) issue_kv(kt + 1, (kt + 1) & 1);
        uint32_t ks_b = qs_b + (uint32_t)(1 + (kt & 1))*ATILE*2;
        uint32_t vs_b = qs_b + (uint32_t)(3 + (kt & 1))*ATILE*2;

        float sacc[8][4];
        #pragma unroll
        for (int j = 0; j < 8; j++)
            #pragma unroll
            for (int c = 0; c < 4; c++) sacc[j][c] = 0.f;
        #pragma unroll
        for (int kh = 0; kh < 4; kh++) {
            uint32_t bf[4][4];
            #pragma unroll
            for (int nb = 0; nb < 4; nb++)
                ldm_x4(bf[nb], ks_b + (uint32_t)((nb*16 + b_row)*ASS + kh*16 + b_k8)*2);
            #pragma unroll
            for (int nb = 0; nb < 4; nb++) {
                mma_f16(sacc[nb*2],     qf[kh], bf[nb]);
                mma_f16(sacc[nb*2 + 1], qf[kh], bf[nb] + 2);
            }
        }
        bool diag = causal && (kt == qcnk);
        float mA = -1e30f, mB = -1e30f;
        #pragma unroll
        for (int j = 0; j < 8; j++) {
            int kl = j*8 + 2*l4;
            int kg = kt*64 + kl;
            bool pv0 = maskv[kg] != 0, pv1 = maskv[kg+1] != 0;
            bool a0 = pv0 && (!diag || kg   <= qA);
            bool a1 = pv1 && (!diag || kg+1 <= qA);
            bool b0 = pv0 && (!diag || kg   <= qB);
            bool b1 = pv1 && (!diag || kg+1 <= qB);
            sacc[j][0] = a0 ? sacc[j][0]*0.125f : -1e9f;
            sacc[j][1] = a1 ? sacc[j][1]*0.125f : -1e9f;
            sacc[j][2] = b0 ? sacc[j][2]*0.125f : -1e9f;
            sacc[j][3] = b1 ? sacc[j][3]*0.125f : -1e9f;
            mA = fmaxf(mA, fmaxf(sacc[j][0], sacc[j][1]));
            mB = fmaxf(mB, fmaxf(sacc[j][2], sacc[j][3]));
        }
        mA = fmaxf(mA, __shfl_xor_sync(0xffffffffu, mA, 1));
        mA = fmaxf(mA, __shfl_xor_sync(0xffffffffu, mA, 2));
        mB = fmaxf(mB, __shfl_xor_sync(0xffffffffu, mB, 1));
        mB = fmaxf(mB, __shfl_xor_sync(0xffffffffu, mB, 2));
        float mnA = fmaxf(mrA, mA), mnB = fmaxf(mrB, mB);
        float aA = __expf(mrA - mnA), aB = __expf(mrB - mnB);
        mrA = mnA; mrB = mnB;
        float lA = 0.f, lB = 0.f;
        #pragma unroll
        for (int j = 0; j < 8; j++) {
            float p0 = __expf(sacc[j][0] - mnA);
            float p1 = __expf(sacc[j][1] - mnA);
            float p2 = __expf(sacc[j][2] - mnB);
            float p3 = __expf(sacc[j][3] - mnB);
            lA += p0 + p1; lB += p2 + p3;
            *(__half2*)(Ps + (m0 + r4)*ASS     + j*8 + 2*l4) = __floats2half2_rn(p0, p1);
            *(__half2*)(Ps + (m0 + r4 + 8)*ASS + j*8 + 2*l4) = __floats2half2_rn(p2, p3);
        }
        lA += __shfl_xor_sync(0xffffffffu, lA, 1);
        lA += __shfl_xor_sync(0xffffffffu, lA, 2);
        lB += __shfl_xor_sync(0xffffffffu, lB, 1);
        lB += __shfl_xor_sync(0xffffffffu, lB, 2);
        lrA = lrA*aA + lA;
        lrB = lrB*aB + lB;
        if (l4 == 0) {
            alphas[m0 + r4]     = aA;
            alphas[m0 + r4 + 8] = aB;
            if (kt == nchunks - 1) {
                linv[m0 + r4]     = 1.f / lrA;
                linv[m0 + r4 + 8] = 1.f / lrB;
            }
        }
        __syncthreads();

        #pragma unroll
        for (int j = 0; j < 8; j++) {
            float a0 = alphas[j*8 + 2*l4];
            float a1 = alphas[j*8 + 2*l4 + 1];
            oacc[j][0] *= a0; oacc[j][1] *= a1;
            oacc[j][2] *= a0; oacc[j][3] *= a1;
        }
        #pragma unroll
        for (int kh = 0; kh < 4; kh++) {
            uint32_t af[4];
            ldm_x4_t(af, vs_b + (uint32_t)((kh*16 + v_s)*ASS + m0 + v_d8)*2);
            #pragma unroll
            for (int jb = 0; jb < 4; jb++) {
                uint32_t bf[4];
                ldm_x4(bf, ps_b + (uint32_t)((jb*16 + b_row)*ASS + kh*16 + b_k8)*2);
                mma_f16(oacc[jb*2],     af, bf);
                mma_f16(oacc[jb*2 + 1], af, bf + 2);
            }
        }
    }

    #pragma unroll
    for (int j = 0; j < 8; j++) {
        int qc2 = j*8 + 2*l4;
        float i0 = linv[qc2], i1 = linv[qc2 + 1];
        int d0 = m0 + r4;
        size_t ro0 = ((size_t)b*SEQ + q0 + qc2)*DMODEL + h*DHEAD;
        size_t ro1 = ro0 + DMODEL;
        Op[ro0 + d0]     = __float2half_rn(oacc[j][0]*i0);
        Op[ro1 + d0]     = __float2half_rn(oacc[j][1]*i1);
        Op[ro0 + d0 + 8] = __float2half_rn(oacc[j][2]*i0);
        Op[ro1 + d0 + 8] = __float2half_rn(oacc[j][3]*i1);
    }
}

// ---------------------------------------------------------------------------
// Orchestration
// ---------------------------------------------------------------------------
static inline void launch_gemm(const __half* A, const __half* W, const float* bias,
                               const float* res, void* C, int M, int N, int K,
                               bool relu, bool ohalf) {
    if (N <= 1024) {   // narrow-N: 64-row tiles, 2x grid
        dim3 grid(N/128, M/64), block(256);
        if (res) {
            cudaFuncSetAttribute(gemm_mma64<false,true,true,false>, cudaFuncAttributeMaxDynamicSharedMemorySize, GEMM64_SMEM);
            gemm_mma64<false,true,true,false><<<grid, block, GEMM64_SMEM>>>(A, W, bias, res, C, M, N, K);
        } else if (relu) {
            cudaFuncSetAttribute(gemm_mma64<true,false,true,true>, cudaFuncAttributeMaxDynamicSharedMemorySize, GEMM64_SMEM);
            gemm_mma64<true,false,true,true><<<grid, block, GEMM64_SMEM>>>(A, W, bias, nullptr, C, M, N, K);
        } else if (bias) {
            cudaFuncSetAttribute(gemm_mma64<false,false,true,true>, cudaFuncAttributeMaxDynamicSharedMemorySize, GEMM64_SMEM);
            gemm_mma64<false,false,true,true><<<grid, block, GEMM64_SMEM>>>(A, W, bias, nullptr, C, M, N, K);
        } else {
            cudaFuncSetAttribute(gemm_mma64<false,false,false,false>, cudaFuncAttributeMaxDynamicSharedMemorySize, GEMM64_SMEM);
            gemm_mma64<false,false,false,false><<<grid, block, GEMM64_SMEM>>>(A, W, nullptr, nullptr, C, M, N, K);
        }
        return;
    }
    dim3 grid(N/128, M/128), block(256);
    if (res) {
        cudaFuncSetAttribute(gemm_mma<false,true,true,false>, cudaFuncAttributeMaxDynamicSharedMemorySize, GEMM_SMEM);
        gemm_mma<false,true,true,false><<<grid, block, GEMM_SMEM>>>(A, W, bias, res, C, M, N, K);
    } else if (relu) {
        cudaFuncSetAttribute(gemm_mma<true,false,true,true>, cudaFuncAttributeMaxDynamicSharedMemorySize, GEMM_SMEM);
        gemm_mma<true,false,true,true><<<grid, block, GEMM_SMEM>>>(A, W, bias, nullptr, C, M, N, K);
    } else if (bias) {
        cudaFuncSetAttribute(gemm_mma<false,false,true,true>, cudaFuncAttributeMaxDynamicSharedMemorySize, GEMM_SMEM);
        gemm_mma<false,false,true,true><<<grid, block, GEMM_SMEM>>>(A, W, bias, nullptr, C, M, N, K);
    } else {
        cudaFuncSetAttribute(gemm_mma<false,false,false,false>, cudaFuncAttributeMaxDynamicSharedMemorySize, GEMM_SMEM);
        gemm_mma<false,false,false,false><<<grid, block, GEMM_SMEM>>>(A, W, nullptr, nullptr, C, M, N, K);
    }
}

extern "C" void kernel_launch(void* const* d_in, const int* in_sizes, int n_in,
                              void* d_out, int out_size) {
    const int*   src        = (const int*)  d_in[0];
    const int*   tgt        = (const int*)  d_in[1];
    const float* emb        = (const float*)d_in[2];
    const float* enc_attn_w = (const float*)d_in[3];
    const float* enc_attn_b = (const float*)d_in[4];
    const float* enc_ln_g   = (const float*)d_in[5];
    const float* enc_ln_b   = (const float*)d_in[6];
    const float* enc_w1     = (const float*)d_in[7];
    const float* enc_b1     = (const float*)d_in[8];
    const float* enc_w2     = (const float*)d_in[9];
    const float* enc_b2     = (const float*)d_in[10];
    const float* dec_attn_w = (const float*)d_in[11];
    const float* dec_attn_b = (const float*)d_in[12];
    const float* dec_ln_g   = (const float*)d_in[13];
    const float* dec_ln_b   = (const float*)d_in[14];
    const float* dec_w1     = (const float*)d_in[15];
    const float* dec_b1     = (const float*)d_in[16];
    const float* dec_w2     = (const float*)d_in[17];
    const float* dec_b2     = (const float*)d_in[18];
    const float* enc_norm_g = (const float*)d_in[19];
    const float* enc_norm_b = (const float*)d_in[20];
    const float* dec_norm_g = (const float*)d_in[21];
    const float* dec_norm_b = (const float*)d_in[22];

    float *x;
    __half *x2, *qb, *ctx, *enc, *hbuf, *qkv, *kv, *wv;
    cudaGetSymbolAddress((void**)&x,    g_x);
    cudaGetSymbolAddress((void**)&x2,   g_x2);
    cudaGetSymbolAddress((void**)&qb,   g_q);
    cudaGetSymbolAddress((void**)&ctx,  g_ctx);
    cudaGetSymbolAddress((void**)&enc,  g_enc);
    cudaGetSymbolAddress((void**)&hbuf, g_h);
    cudaGetSymbolAddress((void**)&qkv,  g_qkv);
    cudaGetSymbolAddress((void**)&kv,   g_kv);
    cudaGetSymbolAddress((void**)&wv,   g_w);

    cudaFuncSetAttribute(attn_mma, cudaFuncAttributeMaxDynamicSharedMemorySize, ATTN_SMEM);

    // --------------- weight conversion (fp16) ---------------
    {
        struct { const float* src; int off; int n; } cv[7] = {
            { enc_attn_w, OFF_ENC_ATTN, NLAYER*4*DMODEL*DMODEL },
            { enc_w1,     OFF_ENC_W1,   NLAYER*DFF*DMODEL },
            { enc_w2,     OFF_ENC_W2,   NLAYER*DMODEL*DFF },
            { dec_attn_w, OFF_DEC_ATTN, NLAYER*8*DMODEL*DMODEL },
            { dec_w1,     OFF_DEC_W1,   NLAYER*DFF*DMODEL },
            { dec_w2,     OFF_DEC_W2,   NLAYER*DMODEL*DFF },
            { emb,        OFF_EMB,      VOCAB*DMODEL },
        };
        for (int i = 0; i < 7; i++)
            cvt_kernel<<<cv[i].n/2048, 256>>>(cv[i].src, wv + cv[i].off, cv[i].n);
    }

    const int D = DMODEL, M = MROWS;
    const size_t WSZ = (size_t)D*D;
    dim3 attnGrid(SEQ/64, NHEAD, BATCH);
    const __half* ew = wv + OFF_ENC_ATTN;
    const __half* dw = wv + OFF_DEC_ATTN;

    // ===================== ENCODER =====================
    embed_kernel<<<M, 128>>>(src, emb, x);
    for (int l = 0; l < NLAYER; l++) {
        const __half* w  = ew + (size_t)l*4*WSZ;
        const float*  bb = enc_attn_b + (size_t)l*4*D;
        ln_kernel<<<M/8, 256>>>(x, enc_ln_g + (size_t)(l*2+0)*D, enc_ln_b + (size_t)(l*2+0)*D, x2);
        launch_gemm(x2, w, bb, nullptr, qkv, M, 3*D, D, false, true);
        attn_mma<<<attnGrid, 128, ATTN_SMEM>>>(qkv, 3*D, qkv + D, qkv + 2*D, 3*D, ctx, src, 0);
        launch_gemm(ctx, w + 3*WSZ, bb + 3*D, x, x, M, D, D, false, false);
        ln_kernel<<<M/8, 256>>>(x, enc_ln_g + (size_t)(l*2+1)*D, enc_ln_b + (size_t)(l*2+1)*D, x2);
        launch_gemm(x2, wv + OFF_ENC_W1 + (size_t)l*DFF*D, enc_b1 + (size_t)l*DFF, nullptr, hbuf, M, DFF, D, true, true);
        launch_gemm(hbuf, wv + OFF_ENC_W2 + (size_t)l*D*DFF, enc_b2 + (size_t)l*D, x, x, M, D, DFF, false, false);
    }
    ln_kernel<<<M/8, 256>>>(x, enc_norm_g, enc_norm_b, enc);

    // ===================== DECODER =====================
    embed_kernel<<<M, 128>>>(tgt, emb, x);
    for (int l = 0; l < NLAYER; l++) {
        const __half* w  = dw + (size_t)l*8*WSZ;
        const float*  bb = dec_attn_b + (size_t)l*8*D;
        ln_kernel<<<M/8, 256>>>(x, dec_ln_g + (size_t)(l*3+0)*D, dec_ln_b + (size_t)(l*3+0)*D, x2);
        launch_gemm(x2, w, bb, nullptr, qkv, M, 3*D, D, false, true);
        attn_mma<<<attnGrid, 128, ATTN_SMEM>>>(qkv, 3*D, qkv + D, qkv + 2*D, 3*D, ctx, tgt, 1);
        launch_gemm(ctx, w + 3*WSZ, bb + 3*D, x, x, M, D, D, false, false);
        ln_kernel<<<M/8, 256>>>(x, dec_ln_g + (size_t)(l*3+1)*D, dec_ln_b + (size_t)(l*3+1)*D, x2);
        launch_gemm(x2,  w + 4*WSZ, bb + 4*D, nullptr, qb, M, D, D, false, true);
        launch_gemm(enc, w + 5*WSZ, bb + 5*D, nullptr, kv, M, 2*D, D, false, true);
        attn_mma<<<attnGrid, 128, ATTN_SMEM>>>(qb, D, kv, kv + D, 2*D, ctx, src, 0);
        launch_gemm(ctx, w + 7*WSZ, bb + 7*D, x, x, M, D, D, false, false);
        ln_kernel<<<M/8, 256>>>(x, dec_ln_g + (size_t)(l*3+2)*D, dec_ln_b + (size_t)(l*3+2)*D, x2);
        launch_gemm(x2, wv + OFF_DEC_W1 + (size_t)l*DFF*D, dec_b1 + (size_t)l*DFF, nullptr, hbuf, M, DFF, D, true, true);
        launch_gemm(hbuf, wv + OFF_DEC_W2 + (size_t)l*D*DFF, dec_b2 + (size_t)l*D, x, x, M, D, DFF, false, false);
    }
    ln_kernel<<<M/8, 256>>>(x, dec_norm_g, dec_norm_b, x2);

    // ===================== tied output projection =====================
    launch_gemm(x2, wv + OFF_EMB, nullptr, nullptr, (float*)d_out, M, VOCAB, D, false, false);
}

// round 10
// speedup vs baseline: 12.4566x; 1.0459x over previous
#include <cuda_runtime.h>
#include <cuda_fp16.h>
#include <cstdint>
#include <math.h>

// ---------------------------------------------------------------------------
// Problem constants
// ---------------------------------------------------------------------------
#define BATCH 8
#define SEQ   512
#define DMODEL 512
#define NHEAD 8
#define DHEAD 64
#define NLAYER 4
#define DFF   2048
#define VOCAB 32000
#define MROWS (BATCH*SEQ)   // 4096

__device__ __forceinline__ uint32_t smem_u32(const void* p) {
    uint32_t a;
    asm("{ .reg .u64 t; cvta.to.shared.u64 t, %1; cvt.u32.u64 %0, t; }" : "=r"(a) : "l"(p));
    return a;
}
__device__ __forceinline__ void cp16(uint32_t s, const void* g) {
    asm volatile("cp.async.cg.shared.global [%0], [%1], 16;" :: "r"(s), "l"(g));
}
#define CP_COMMIT() asm volatile("cp.async.commit_group;" ::: "memory")
template<int N> __device__ __forceinline__ void cp_wait() {
    asm volatile("cp.async.wait_group %0;" :: "n"(N) : "memory");
}
__device__ __forceinline__ void ldm_x4(uint32_t* r, uint32_t addr) {
    asm volatile("ldmatrix.sync.aligned.m8n8.x4.shared.b16 {%0,%1,%2,%3}, [%4];"
        : "=r"(r[0]), "=r"(r[1]), "=r"(r[2]), "=r"(r[3]) : "r"(addr));
}
__device__ __forceinline__ void ldm_x4_t(uint32_t* r, uint32_t addr) {
    asm volatile("ldmatrix.sync.aligned.m8n8.x4.trans.shared.b16 {%0,%1,%2,%3}, [%4];"
        : "=r"(r[0]), "=r"(r[1]), "=r"(r[2]), "=r"(r[3]) : "r"(addr));
}
__device__ __forceinline__ void mma_f16(float* c, const uint32_t* a, const uint32_t* b) {
    asm volatile(
        "mma.sync.aligned.m16n8k16.row.col.f32.f16.f16.f32 "
        "{%0,%1,%2,%3}, {%4,%5,%6,%7}, {%8,%9}, {%0,%1,%2,%3};"
        : "+f"(c[0]), "+f"(c[1]), "+f"(c[2]), "+f"(c[3])
        : "r"(a[0]), "r"(a[1]), "r"(a[2]), "r"(a[3]), "r"(b[0]), "r"(b[1]));
}

// ---------------------------------------------------------------------------
// Scratch (device globals; no allocation allowed)
// ---------------------------------------------------------------------------
__device__ __align__(16) float  g_x   [MROWS*DMODEL];   // encoder residual
__device__ __align__(16) float  g_xd  [MROWS*DMODEL];   // decoder residual
__device__ __align__(16) __half g_x2  [MROWS*DMODEL];   // encoder LN out
__device__ __align__(16) __half g_x2d [MROWS*DMODEL];   // decoder LN out
__device__ __align__(16) __half g_qb  [MROWS*DMODEL];   // cross-Q
__device__ __align__(16) __half g_ctx [MROWS*DMODEL];   // encoder attn out
__device__ __align__(16) __half g_ctxd[MROWS*DMODEL];   // decoder attn out
__device__ __align__(16) __half g_enc [MROWS*DMODEL];
__device__ __align__(16) __half g_h   [MROWS*DFF];
__device__ __align__(16) __half g_qkv [MROWS*3*DMODEL]; // encoder QKV
__device__ __align__(16) __half g_qkvd[MROWS*3*DMODEL]; // decoder QKV
__device__ __align__(16) __half g_kvb [NLAYER][MROWS*2*DMODEL]; // per-layer cross KV

// converted-weight arena (fp16)
#define OFF_ENC_ATTN 0
#define OFF_ENC_W1   (OFF_ENC_ATTN + NLAYER*4*DMODEL*DMODEL)
#define OFF_ENC_W2   (OFF_ENC_W1   + NLAYER*DFF*DMODEL)
#define OFF_DEC_ATTN (OFF_ENC_W2   + NLAYER*DMODEL*DFF)
#define OFF_DEC_W1   (OFF_DEC_ATTN + NLAYER*8*DMODEL*DMODEL)
#define OFF_DEC_W2   (OFF_DEC_W1   + NLAYER*DFF*DMODEL)
#define OFF_EMB      (OFF_DEC_W2   + NLAYER*DMODEL*DFF)
#define W_TOTAL      (OFF_EMB      + VOCAB*DMODEL)
__device__ __align__(16) __half g_w[W_TOTAL];

// ---------------------------------------------------------------------------
// fp32 -> fp16 conversion
// ---------------------------------------------------------------------------
__global__ void cvt_kernel(const float* __restrict__ in, __half* __restrict__ out, int n) {
    int i = (blockIdx.x*blockDim.x + threadIdx.x)*8;
    if (i < n) {
        float4 a = *(const float4*)(in + i);
        float4 b = *(const float4*)(in + i + 4);
        __half2 h0 = __floats2half2_rn(a.x, a.y);
        __half2 h1 = __floats2half2_rn(a.z, a.w);
        __half2 h2 = __floats2half2_rn(b.x, b.y);
        __half2 h3 = __floats2half2_rn(b.z, b.w);
        uint4 o;
        o.x = *(uint32_t*)&h0; o.y = *(uint32_t*)&h1;
        o.z = *(uint32_t*)&h2; o.w = *(uint32_t*)&h3;
        *(uint4*)(out + i) = o;
    }
}

// ---------------------------------------------------------------------------
// Embedding + sinusoidal positional encoding (residual stream, fp32)
// ---------------------------------------------------------------------------
__global__ void embed_kernel(const int* __restrict__ tok,
                             const float* __restrict__ emb,
                             float* __restrict__ y) {
    int row = blockIdx.x;
    int s   = row % SEQ;
    int t   = tok[row];
    const float scale = 22.62741699796952f;
    const float c0 = -9.210340371976184f / (float)DMODEL;
    int tid = threadIdx.x;
    #pragma unroll
    for (int i = 0; i < 4; i++) {
        int d = tid + i*128;
        float e = (t == 0) ? 0.f : emb[(size_t)t*DMODEL + d];
        int half = d >> 1;
        float div = expf((float)(2*half) * c0);
        float ang = (float)s * div;
        float pe = (d & 1) ? cosf(ang) : sinf(ang);
        y[(size_t)row*DMODEL + d] = e*scale + pe;
    }
}

// ---------------------------------------------------------------------------
// LayerNorm, warp-per-row (8 rows / 256-thread block).
// ---------------------------------------------------------------------------
__global__ __launch_bounds__(256)
void ln_kernel(const float* __restrict__ x,
               const float* __restrict__ g,
               const float* __restrict__ b,
               __half* __restrict__ y) {
    int row  = blockIdx.x*8 + (threadIdx.x >> 5);
    int lane = threadIdx.x & 31;
    const float* xr = x + (size_t)row*DMODEL;
    float4 v[4];
    float s = 0.f;
    #pragma unroll
    for (int c = 0; c < 4; c++) {
        v[c] = *(const float4*)(xr + lane*4 + c*128);
        s += (v[c].x + v[c].y) + (v[c].z + v[c].w);
    }
    #pragma unroll
    for (int o = 16; o > 0; o >>= 1) s += __shfl_xor_sync(0xffffffffu, s, o);
    float mean = s * (1.f/(float)DMODEL);
    float vs = 0.f;
    #pragma unroll
    for (int c = 0; c < 4; c++) {
        float d0 = v[c].x-mean, d1 = v[c].y-mean, d2 = v[c].z-mean, d3 = v[c].w-mean;
        vs += d0*d0 + d1*d1 + d2*d2 + d3*d3;
    }
    #pragma unroll
    for (int o = 16; o > 0; o >>= 1) vs += __shfl_xor_sync(0xffffffffu, vs, o);
    float inv = rsqrtf(vs * (1.f/(float)DMODEL) + 1e-5f);
    #pragma unroll
    for (int c = 0; c < 4; c++) {
        int d = lane*4 + c*128;
        float4 gv = *(const float4*)(g + d);
        float4 bv = *(const float4*)(b + d);
        float r0 = (v[c].x-mean)*inv*gv.x + bv.x;
        float r1 = (v[c].y-mean)*inv*gv.y + bv.y;
        float r2 = (v[c].z-mean)*inv*gv.z + bv.z;
        float r3 = (v[c].w-mean)*inv*gv.w + bv.w;
        __half2 h0 = __floats2half2_rn(r0, r1);
        __half2 h1 = __floats2half2_rn(r2, r3);
        uint2 o; o.x = *(uint32_t*)&h0; o.y = *(uint32_t*)&h1;
        *(uint2*)(y + (size_t)row*DMODEL + d) = o;
    }
}

// ---------------------------------------------------------------------------
// fp16 mma.sync GEMM, CTA 128x128x32 (wide-N shapes).
// ---------------------------------------------------------------------------
#define TSTR 40
#define TILE_HALFS (128*TSTR)
#define STAGE_HALFS (2*TILE_HALFS)
#define GEMM_SMEM (3*STAGE_HALFS*2)

template<bool RELU, bool RES, bool BIAS, bool OHALF>
__global__ __launch_bounds__(256, 2)
void gemm_mma(const __half* __restrict__ A, const __half* __restrict__ W,
              const float* __restrict__ bias, const float* __restrict__ res,
              void* __restrict__ Cv, int M, int N, int K) {
    extern __shared__ __half smh[];
    int t = threadIdx.x, lane = t & 31, wid = t >> 5;
    int wm = (wid & 1) * 64;
    int wn = (wid >> 1) * 32;
    int r4 = lane >> 2, l4 = lane & 3;

    const __half* Ab = A + (size_t)blockIdx.y*128*K;
    const __half* Wb = W + (size_t)blockIdx.x*128*K;
    uint32_t sbase = smem_u32(smh);

    float acc[4][4][4];
    #pragma unroll
    for (int i = 0; i < 4; i++)
        #pragma unroll
        for (int j = 0; j < 4; j++)
            #pragma unroll
            for (int c = 0; c < 4; c++) acc[i][j][c] = 0.f;

    int NK = K >> 5;

    auto issue = [&](int it, int buf) {
        uint32_t base = sbase + (uint32_t)buf*STAGE_HALFS*2;
        int k0 = it*32;
        #pragma unroll
        for (int i = 0; i < 2; i++) {
            int idx = t + i*256, r = idx >> 2, ch = idx & 3;
            uint32_t off = (uint32_t)(r*TSTR + ch*8)*2;
            cp16(base + off,                  Ab + (size_t)r*K + k0 + ch*8);
            cp16(base + TILE_HALFS*2 + off,   Wb + (size_t)r*K + k0 + ch*8);
        }
        CP_COMMIT();
    };

    issue(0, 0);
    issue(1, 1);

    int a_row = (lane & 15);
    int a_kh8 = (lane >> 4) * 8;
    int b_row = (lane & 7) + ((lane >> 4) & 1) * 8;
    int b_kh8 = ((lane >> 3) & 1) * 8;

    for (int it = 0; it < NK; it++) {
        if (it + 1 < NK) cp_wait<1>(); else cp_wait<0>();
        __syncthreads();
        if (it + 2 < NK) issue(it + 2, (it + 2) % 3);
        uint32_t sA = sbase + (uint32_t)(it % 3)*STAGE_HALFS*2;
        uint32_t sB = sA + TILE_HALFS*2;
        #pragma unroll
        for (int kh = 0; kh < 2; kh++) {
            uint32_t af[4][4], bf[2][4];
            #pragma unroll
            for (int mi = 0; mi < 4; mi++)
                ldm_x4(af[mi], sA + (uint32_t)((wm + mi*16 + a_row)*TSTR + kh*16 + a_kh8)*2);
            #pragma unroll
            for (int nb = 0; nb < 2; nb++)
                ldm_x4(bf[nb], sB + (uint32_t)((wn + nb*16 + b_row)*TSTR + kh*16 + b_kh8)*2);
            #pragma unroll
            for (int mi = 0; mi < 4; mi++) {
                #pragma unroll
                for (int ni = 0; ni < 4; ni++)
                    mma_f16(acc[mi][ni], af[mi], bf[ni >> 1] + (ni & 1)*2);
            }
        }
    }

    int gm = blockIdx.y*128 + wm;
    int gn = blockIdx.x*128 + wn;
    #pragma unroll
    for (int mi = 0; mi < 4; mi++) {
        #pragma unroll
        for (int ni = 0; ni < 4; ni++) {
            int row = gm + mi*16 + r4;
            int col = gn + ni*8 + l4*2;
            float2 v0 = make_float2(acc[mi][ni][0], acc[mi][ni][1]);
            float2 v1 = make_float2(acc[mi][ni][2], acc[mi][ni][3]);
            if (BIAS) {
                float2 bv = *(const float2*)(bias + col);
                v0.x += bv.x; v0.y += bv.y; v1.x += bv.x; v1.y += bv.y;
            }
            if (RELU) {
                v0.x = fmaxf(v0.x, 0.f); v0.y = fmaxf(v0.y, 0.f);
                v1.x = fmaxf(v1.x, 0.f); v1.y = fmaxf(v1.y, 0.f);
            }
            if (RES) {
                float2 r0 = *(const float2*)(res + (size_t)row*N + col);
                float2 r1 = *(const float2*)(res + (size_t)(row+8)*N + col);
                v0.x += r0.x; v0.y += r0.y; v1.x += r1.x; v1.y += r1.y;
            }
            if (OHALF) {
                __half* C = (__half*)Cv;
                *(__half2*)(C + (size_t)row*N + col)     = __floats2half2_rn(v0.x, v0.y);
                *(__half2*)(C + (size_t)(row+8)*N + col) = __floats2half2_rn(v1.x, v1.y);
            } else {
                float* C = (float*)Cv;
                *(float2*)(C + (size_t)row*N + col)     = v0;
                *(float2*)(C + (size_t)(row+8)*N + col) = v1;
            }
        }
    }
}

// ---------------------------------------------------------------------------
// fp16 mma.sync GEMM, CTA 64x128x32 (narrow-N shapes).
// ---------------------------------------------------------------------------
#define A64_HALFS (64*TSTR)
#define S64_HALFS (A64_HALFS + TILE_HALFS)
#define GEMM64_SMEM (3*S64_HALFS*2)

template<bool RELU, bool RES, bool BIAS, bool OHALF>
__global__ __launch_bounds__(256)
void gemm_mma64(const __half* __restrict__ A, const __half* __restrict__ W,
                const float* __restrict__ bias, const float* __restrict__ res,
                void* __restrict__ Cv, int M, int N, int K) {
    extern __shared__ __half smh[];
    int t = threadIdx.x, lane = t & 31, wid = t >> 5;
    int wm = (wid & 1) * 32;
    int wn = (wid >> 1) * 32;
    int r4 = lane >> 2, l4 = lane & 3;

    const __half* Ab = A + (size_t)blockIdx.y*64*K;
    const __half* Wb = W + (size_t)blockIdx.x*128*K;
    uint32_t sbase = smem_u32(smh);

    float acc[2][4][4];
    #pragma unroll
    for (int i = 0; i < 2; i++)
        #pragma unroll
        for (int j = 0; j < 4; j++)
            #pragma unroll
            for (int c = 0; c < 4; c++) acc[i][j][c] = 0.f;

    int NK = K >> 5;

    auto issue = [&](int it, int buf) {
        uint32_t base = sbase + (uint32_t)buf*S64_HALFS*2;
        int k0 = it*32;
        {
            int r = t >> 2, ch = t & 3;
            cp16(base + (uint32_t)(r*TSTR + ch*8)*2, Ab + (size_t)r*K + k0 + ch*8);
        }
        #pragma unroll
        for (int i = 0; i < 2; i++) {
            int idx = t + i*256, r = idx >> 2, ch = idx & 3;
            cp16(base + A64_HALFS*2 + (uint32_t)(r*TSTR + ch*8)*2,
                 Wb + (size_t)r*K + k0 + ch*8);
        }
        CP_COMMIT();
    };

    issue(0, 0);
    issue(1, 1);

    int a_row = (lane & 15);
    int a_kh8 = (lane >> 4) * 8;
    int b_row = (lane & 7) + ((lane >> 4) & 1) * 8;
    int b_kh8 = ((lane >> 3) & 1) * 8;

    for (int it = 0; it < NK; it++) {
        if (it + 1 < NK) cp_wait<1>(); else cp_wait<0>();
        __syncthreads();
        if (it + 2 < NK) issue(it + 2, (it + 2) % 3);
        uint32_t sA = sbase + (uint32_t)(it % 3)*S64_HALFS*2;
        uint32_t sB = sA + A64_HALFS*2;
        #pragma unroll
        for (int kh = 0; kh < 2; kh++) {
            uint32_t af[2][4], bf[2][4];
            #pragma unroll
            for (int mi = 0; mi < 2; mi++)
                ldm_x4(af[mi], sA + (uint32_t)((wm + mi*16 + a_row)*TSTR + kh*16 + a_kh8)*2);
            #pragma unroll
            for (int nb = 0; nb < 2; nb++)
                ldm_x4(bf[nb], sB + (uint32_t)((wn + nb*16 + b_row)*TSTR + kh*16 + b_kh8)*2);
            #pragma unroll
            for (int mi = 0; mi < 2; mi++) {
                #pragma unroll
                for (int ni = 0; ni < 4; ni++)
                    mma_f16(acc[mi][ni], af[mi], bf[ni >> 1] + (ni & 1)*2);
            }
        }
    }

    int gm = blockIdx.y*64 + wm;
    int gn = blockIdx.x*128 + wn;
    #pragma unroll
    for (int mi = 0; mi < 2; mi++) {
        #pragma unroll
        for (int ni = 0; ni < 4; ni++) {
            int row = gm + mi*16 + r4;
            int col = gn + ni*8 + l4*2;
            float2 v0 = make_float2(acc[mi][ni][0], acc[mi][ni][1]);
            float2 v1 = make_float2(acc[mi][ni][2], acc[mi][ni][3]);
            if (BIAS) {
                float2 bv = *(const float2*)(bias + col);
                v0.x += bv.x; v0.y += bv.y; v1.x += bv.x; v1.y += bv.y;
            }
            if (RELU) {
                v0.x = fmaxf(v0.x, 0.f); v0.y = fmaxf(v0.y, 0.f);
                v1.x = fmaxf(v1.x, 0.f); v1.y = fmaxf(v1.y, 0.f);
            }
            if (RES) {
                float2 r0 = *(const float2*)(res + (size_t)row*N + col);
                float2 r1 = *(const float2*)(res + (size_t)(row+8)*N + col);
                v0.x += r0.x; v0.y += r0.y; v1.x += r1.x; v1.y += r1.y;
            }
            if (OHALF) {
                __half* C = (__half*)Cv;
                *(__half2*)(C + (size_t)row*N + col)     = __floats2half2_rn(v0.x, v0.y);
                *(__half2*)(C + (size_t)(row+8)*N + col) = __floats2half2_rn(v1.x, v1.y);
            } else {
                float* C = (float*)Cv;
                *(float2*)(C + (size_t)row*N + col)     = v0;
                *(float2*)(C + (size_t)(row+8)*N + col) = v1;
            }
        }
    }
}

// ---------------------------------------------------------------------------
// Flash attention, fp16 inputs, cp.async double-buffered K/V.
// ---------------------------------------------------------------------------
#define ASS 72
#define ATILE (64*ASS)
#define FH_TOT (6*ATILE)
#define ATTN_SMEM (FH_TOT*2 + 2816)

__global__ __launch_bounds__(128)
void attn_mma(const __half* __restrict__ Qp, int qstride,
              const __half* __restrict__ Kp, const __half* __restrict__ Vp, int kvstride,
              __half* __restrict__ Op,
              const int* __restrict__ mtok, int causal) {
    extern __shared__ __half smh[];
    __half* Ps = smh + 5*ATILE;
    float* alphas = (float*)(smh + FH_TOT);
    float* linv   = alphas + 64;
    uint32_t* maskv = (uint32_t*)(linv + 64);

    int t = threadIdx.x, lane = t & 31, w = t >> 5;
    int r4 = lane >> 2, l4 = lane & 3;
    int q0 = blockIdx.x * 64, h = blockIdx.y, b = blockIdx.z;
    const __half* Qb = Qp + (size_t)b*SEQ*qstride  + h*DHEAD;
    const __half* Kb = Kp + (size_t)b*SEQ*kvstride + h*DHEAD;
    const __half* Vb = Vp + (size_t)b*SEQ*kvstride + h*DHEAD;

    uint32_t qs_b = smem_u32(smh);
    uint32_t ps_b = smem_u32(Ps);

    int a_row = (lane & 15);
    int a_k8  = (lane >> 4) * 8;
    int b_row = (lane & 7) + ((lane >> 4) & 1) * 8;
    int b_k8  = ((lane >> 3) & 1) * 8;
    int v_s   = (lane & 7) + ((lane >> 4) & 1) * 8;
    int v_d8  = ((lane >> 3) & 1) * 8;

    int qcnk = q0 >> 6;
    int nchunks = causal ? (qcnk + 1) : (SEQ/64);

    auto issue_kv = [&](int kt, int buf) {
        uint32_t kbase = qs_b + (uint32_t)(1 + buf)*ATILE*2;
        uint32_t vbase = qs_b + (uint32_t)(3 + buf)*ATILE*2;
        const __half* Kc = Kb + (size_t)kt*64*kvstride;
        const __half* Vc = Vb + (size_t)kt*64*kvstride;
        #pragma unroll
        for (int i = 0; i < 4; i++) {
            int idx = t + i*128, s = idx >> 3, ch = idx & 7;
            uint32_t off = (uint32_t)(s*ASS + ch*8)*2;
            cp16(kbase + off, Kc + (size_t)s*kvstride + ch*8);
            cp16(vbase + off, Vc + (size_t)s*kvstride + ch*8);
        }
        CP_COMMIT();
    };

    #pragma unroll
    for (int i = 0; i < 4; i++) {
        int idx = t + i*128, s = idx >> 3, ch = idx & 7;
        cp16(qs_b + (uint32_t)(s*ASS + ch*8)*2, Qb + (size_t)(q0+s)*qstride + ch*8);
    }
    CP_COMMIT();
    #pragma unroll
    for (int i = 0; i < 4; i++) {
        int idx = t + i*128;
        maskv[idx] = (mtok[b*SEQ + idx] != 0);
    }
    issue_kv(0, 0);
    cp_wait<1>();
    __syncthreads();

    int m0 = w*16;
    uint32_t qf[4][4];
    #pragma unroll
    for (int kh = 0; kh < 4; kh++)
        ldm_x4(qf[kh], qs_b + (uint32_t)((m0 + a_row)*ASS + kh*16 + a_k8)*2);

    float oacc[8][4];
    #pragma unroll
    for (int j = 0; j < 8; j++)
        #pragma unroll
        for (int c = 0; c < 4; c++) oacc[j][c] = 0.f;
    float mrA = -1e30f, mrB = -1e30f, lrA = 0.f, lrB = 0.f;
    int qA = q0 + m0 + r4, qB = qA + 8;

    for (int kt = 0; kt < nchunks; kt++) {
        cp_wait<0>();
        __syncthreads();
        if (kt + 1 < nchunks) issue_kv(kt + 1, (kt + 1) & 1);
        uint32_t ks_b = qs_b + (uint32_t)(1 + (kt & 1))*ATILE*2;
        uint32_t vs_b = qs_b + (uint32_t)(3 + (kt & 1))*ATILE*2;

        float sacc[8][4];
        #pragma unroll
        for (int j = 0; j < 8; j++)
            #pragma unroll
            for (int c = 0; c < 4; c++) sacc[j][c] = 0.f;
        #pragma unroll
        for (int kh = 0; kh < 4; kh++) {
            uint32_t bf[4][4];
            #pragma unroll
            for (int nb = 0; nb < 4; nb++)
                ldm_x4(bf[nb], ks_b + (uint32_t)((nb*16 + b_row)*ASS + kh*16 + b_k8)*2);
            #pragma unroll
            for (int nb = 0; nb < 4; nb++) {
                mma_f16(sacc[nb*2],     qf[kh], bf[nb]);
                mma_f16(sacc[nb*2 + 1], qf[kh], bf[nb] + 2);
            }
        }
        bool diag = causal && (kt == qcnk);
        float mA = -1e30f, mB = -1e30f;
        #pragma unroll
        for (int j = 0; j < 8; j++) {
            int kl = j*8 + 2*l4;
            int kg = kt*64 + kl;
            bool pv0 = maskv[kg] != 0, pv1 = maskv[kg+1] != 0;
            bool a0 = pv0 && (!diag || kg   <= qA);
            bool a1 = pv1 && (!diag || kg+1 <= qA);
            bool b0 = pv0 && (!diag || kg   <= qB);
            bool b1 = pv1 && (!diag || kg+1 <= qB);
            sacc[j][0] = a0 ? sacc[j][0]*0.125f : -1e9f;
            sacc[j][1] = a1 ? sacc[j][1]*0.125f : -1e9f;
            sacc[j][2] = b0 ? sacc[j][2]*0.125f : -1e9f;
            sacc[j][3] = b1 ? sacc[j][3]*0.125f : -1e9f;
            mA = fmaxf(mA, fmaxf(sacc[j][0], sacc[j][1]));
            mB = fmaxf(mB, fmaxf(sacc[j][2], sacc[j][3]));
        }
        mA = fmaxf(mA, __shfl_xor_sync(0xffffffffu, mA, 1));
        mA = fmaxf(mA, __shfl_xor_sync(0xffffffffu, mA, 2));
        mB = fmaxf(mB, __shfl_xor_sync(0xffffffffu, mB, 1));
        mB = fmaxf(mB, __shfl_xor_sync(0xffffffffu, mB, 2));
        float mnA = fmaxf(mrA, mA), mnB = fmaxf(mrB, mB);
        float aA = __expf(mrA - mnA), aB = __expf(mrB - mnB);
        mrA = mnA; mrB = mnB;
        float lA = 0.f, lB = 0.f;
        #pragma unroll
        for (int j = 0; j < 8; j++) {
            float p0 = __expf(sacc[j][0] - mnA);
            float p1 = __expf(sacc[j][1] - mnA);
            float p2 = __expf(sacc[j][2] - mnB);
            float p3 = __expf(sacc[j][3] - mnB);
            lA += p0 + p1; lB += p2 + p3;
            *(__half2*)(Ps + (m0 + r4)*ASS     + j*8 + 2*l4) = __floats2half2_rn(p0, p1);
            *(__half2*)(Ps + (m0 + r4 + 8)*ASS + j*8 + 2*l4) = __floats2half2_rn(p2, p3);
        }
        lA += __shfl_xor_sync(0xffffffffu, lA, 1);
        lA += __shfl_xor_sync(0xffffffffu, lA, 2);
        lB += __shfl_xor_sync(0xffffffffu, lB, 1);
        lB += __shfl_xor_sync(0xffffffffu, lB, 2);
        lrA = lrA*aA + lA;
        lrB = lrB*aB + lB;
        if (l4 == 0) {
            alphas[m0 + r4]     = aA;
            alphas[m0 + r4 + 8] = aB;
            if (kt == nchunks - 1) {
                linv[m0 + r4]     = 1.f / lrA;
                linv[m0 + r4 + 8] = 1.f / lrB;
            }
        }
        __syncthreads();

        #pragma unroll
        for (int j = 0; j < 8; j++) {
            float a0 = alphas[j*8 + 2*l4];
            float a1 = alphas[j*8 + 2*l4 + 1];
            oacc[j][0] *= a0; oacc[j][1] *= a1;
            oacc[j][2] *= a0; oacc[j][3] *= a1;
        }
        #pragma unroll
        for (int kh = 0; kh < 4; kh++) {
            uint32_t af[4];
            ldm_x4_t(af, vs_b + (uint32_t)((kh*16 + v_s)*ASS + m0 + v_d8)*2);
            #pragma unroll
            for (int jb = 0; jb < 4; jb++) {
                uint32_t bf[4];
                ldm_x4(bf, ps_b + (uint32_t)((jb*16 + b_row)*ASS + kh*16 + b_k8)*2);
                mma_f16(oacc[jb*2],     af, bf);
                mma_f16(oacc[jb*2 + 1], af, bf + 2);
            }
        }
    }

    #pragma unroll
    for (int j = 0; j < 8; j++) {
        int qc2 = j*8 + 2*l4;
        float i0 = linv[qc2], i1 = linv[qc2 + 1];
        int d0 = m0 + r4;
        size_t ro0 = ((size_t)b*SEQ + q0 + qc2)*DMODEL + h*DHEAD;
        size_t ro1 = ro0 + DMODEL;
        Op[ro0 + d0]     = __float2half_rn(oacc[j][0]*i0);
        Op[ro1 + d0]     = __float2half_rn(oacc[j][1]*i1);
        Op[ro0 + d0 + 8] = __float2half_rn(oacc[j][2]*i0);
        Op[ro1 + d0 + 8] = __float2half_rn(oacc[j][3]*i1);
    }
}

// ---------------------------------------------------------------------------
// Host-side stream/event resources, created at static-init (pre-checkpoint).
// Fallback to serial single-stream if creation fails.
// ---------------------------------------------------------------------------
struct StreamCtx {
    cudaStream_t s1 = nullptr;
    cudaEvent_t root = nullptr, enc = nullptr, dec0 = nullptr, kv[NLAYER] = {};
    bool ok = false;
    StreamCtx() {
        if (cudaStreamCreateWithFlags(&s1, cudaStreamNonBlocking) != cudaSuccess) return;
        if (cudaEventCreateWithFlags(&root, cudaEventDisableTiming) != cudaSuccess) return;
        if (cudaEventCreateWithFlags(&enc,  cudaEventDisableTiming) != cudaSuccess) return;
        if (cudaEventCreateWithFlags(&dec0, cudaEventDisableTiming) != cudaSuccess) return;
        for (int i = 0; i < NLAYER; i++)
            if (cudaEventCreateWithFlags(&kv[i], cudaEventDisableTiming) != cudaSuccess) return;
        ok = true;
    }
};
static StreamCtx g_sc;

// ---------------------------------------------------------------------------
// Orchestration
// ---------------------------------------------------------------------------
static inline void launch_gemm(const __half* A, const __half* W, const float* bias,
                               const float* res, void* C, int M, int N, int K,
                               bool relu, cudaStream_t st) {
    if (N <= 1024) {
        dim3 grid(N/128, M/64), block(256);
        if (res)        gemm_mma64<false,true ,true ,false><<<grid, block, GEMM64_SMEM, st>>>(A, W, bias, res, C, M, N, K);
        else if (relu)  gemm_mma64<true ,false,true ,true ><<<grid, block, GEMM64_SMEM, st>>>(A, W, bias, nullptr, C, M, N, K);
        else if (bias)  gemm_mma64<false,false,true ,true ><<<grid, block, GEMM64_SMEM, st>>>(A, W, bias, nullptr, C, M, N, K);
        else            gemm_mma64<false,false,false,false><<<grid, block, GEMM64_SMEM, st>>>(A, W, nullptr, nullptr, C, M, N, K);
        return;
    }
    dim3 grid(N/128, M/128), block(256);
    if (res)        gemm_mma<false,true ,true ,false><<<grid, block, GEMM_SMEM, st>>>(A, W, bias, res, C, M, N, K);
    else if (relu)  gemm_mma<true ,false,true ,true ><<<grid, block, GEMM_SMEM, st>>>(A, W, bias, nullptr, C, M, N, K);
    else if (bias)  gemm_mma<false,false,true ,true ><<<grid, block, GEMM_SMEM, st>>>(A, W, bias, nullptr, C, M, N, K);
    else            gemm_mma<false,false,false,false><<<grid, block, GEMM_SMEM, st>>>(A, W, nullptr, nullptr, C, M, N, K);
}

extern "C" void kernel_launch(void* const* d_in, const int* in_sizes, int n_in,
                              void* d_out, int out_size) {
    const int*   src        = (const int*)  d_in[0];
    const int*   tgt        = (const int*)  d_in[1];
    const float* emb        = (const float*)d_in[2];
    const float* enc_attn_w = (const float*)d_in[3];
    const float* enc_attn_b = (const float*)d_in[4];
    const float* enc_ln_g   = (const float*)d_in[5];
    const float* enc_ln_b   = (const float*)d_in[6];
    const float* enc_w1     = (const float*)d_in[7];
    const float* enc_b1     = (const float*)d_in[8];
    const float* enc_w2     = (const float*)d_in[9];
    const float* enc_b2     = (const float*)d_in[10];
    const float* dec_attn_w = (const float*)d_in[11];
    const float* dec_attn_b = (const float*)d_in[12];
    const float* dec_ln_g   = (const float*)d_in[13];
    const float* dec_ln_b   = (const float*)d_in[14];
    const float* dec_w1     = (const float*)d_in[15];
    const float* dec_b1     = (const float*)d_in[16];
    const float* dec_w2     = (const float*)d_in[17];
    const float* dec_b2     = (const float*)d_in[18];
    const float* enc_norm_g = (const float*)d_in[19];
    const float* enc_norm_b = (const float*)d_in[20];
    const float* dec_norm_g = (const float*)d_in[21];
    const float* dec_norm_b = (const float*)d_in[22];

    float *x, *xd;
    __half *x2, *x2d, *qb, *ctx, *ctxd, *enc, *hbuf, *qkv, *qkvd, *wv;
    __half *kvb[NLAYER];
    cudaGetSymbolAddress((void**)&x,    g_x);
    cudaGetSymbolAddress((void**)&xd,   g_xd);
    cudaGetSymbolAddress((void**)&x2,   g_x2);
    cudaGetSymbolAddress((void**)&x2d,  g_x2d);
    cudaGetSymbolAddress((void**)&qb,   g_qb);
    cudaGetSymbolAddress((void**)&ctx,  g_ctx);
    cudaGetSymbolAddress((void**)&ctxd, g_ctxd);
    cudaGetSymbolAddress((void**)&enc,  g_enc);
    cudaGetSymbolAddress((void**)&hbuf, g_h);
    cudaGetSymbolAddress((void**)&qkv,  g_qkv);
    cudaGetSymbolAddress((void**)&qkvd, g_qkvd);
    cudaGetSymbolAddress((void**)&wv,   g_w);
    {
        __half* kvb0;
        cudaGetSymbolAddress((void**)&kvb0, g_kvb);
        for (int l = 0; l < NLAYER; l++) kvb[l] = kvb0 + (size_t)l*MROWS*2*DMODEL;
    }

    // smem attributes (idempotent host calls)
    cudaFuncSetAttribute(attn_mma, cudaFuncAttributeMaxDynamicSharedMemorySize, ATTN_SMEM);
    cudaFuncSetAttribute(gemm_mma<false,true ,true ,false>, cudaFuncAttributeMaxDynamicSharedMemorySize, GEMM_SMEM);
    cudaFuncSetAttribute(gemm_mma<true ,false,true ,true >, cudaFuncAttributeMaxDynamicSharedMemorySize, GEMM_SMEM);
    cudaFuncSetAttribute(gemm_mma<false,false,true ,true >, cudaFuncAttributeMaxDynamicSharedMemorySize, GEMM_SMEM);
    cudaFuncSetAttribute(gemm_mma<false,false,false,false>, cudaFuncAttributeMaxDynamicSharedMemorySize, GEMM_SMEM);
    cudaFuncSetAttribute(gemm_mma64<false,true ,true ,false>, cudaFuncAttributeMaxDynamicSharedMemorySize, GEMM64_SMEM);
    cudaFuncSetAttribute(gemm_mma64<true ,false,true ,true >, cudaFuncAttributeMaxDynamicSharedMemorySize, GEMM64_SMEM);
    cudaFuncSetAttribute(gemm_mma64<false,false,true ,true >, cudaFuncAttributeMaxDynamicSharedMemorySize, GEMM64_SMEM);
    cudaFuncSetAttribute(gemm_mma64<false,false,false,false>, cudaFuncAttributeMaxDynamicSharedMemorySize, GEMM64_SMEM);

    const int D = DMODEL, M = MROWS;
    const size_t WSZ = (size_t)D*D;
    dim3 attnGrid(SEQ/64, NHEAD, BATCH);
    const __half* ew = wv + OFF_ENC_ATTN;
    const __half* dw = wv + OFF_DEC_ATTN;

    const bool par = g_sc.ok;
    cudaStream_t s0 = 0;
    cudaStream_t s1 = par ? g_sc.s1 : (cudaStream_t)0;

    // fork
    if (par) {
        cudaEventRecord(g_sc.root, s0);
        cudaStreamWaitEvent(s1, g_sc.root, 0);
    }

    // ----- s1: decoder-side cvt + embed + layer-0 self-attn block -----
    cvt_kernel<<<(NLAYER*8*DMODEL*DMODEL)/2048, 256, 0, s1>>>(dec_attn_w, wv + OFF_DEC_ATTN, NLAYER*8*DMODEL*DMODEL);
    cvt_kernel<<<(NLAYER*DFF*DMODEL)/2048,      256, 0, s1>>>(dec_w1,     wv + OFF_DEC_W1,   NLAYER*DFF*DMODEL);
    cvt_kernel<<<(NLAYER*DMODEL*DFF)/2048,      256, 0, s1>>>(dec_w2,     wv + OFF_DEC_W2,   NLAYER*DMODEL*DFF);
    cvt_kernel<<<(VOCAB*DMODEL)/2048,           256, 0, s1>>>(emb,        wv + OFF_EMB,      VOCAB*DMODEL);
    embed_kernel<<<M, 128, 0, s1>>>(tgt, emb, xd);
    {
        const __half* w  = dw;                       // layer 0
        const float*  bb = dec_attn_b;
        ln_kernel<<<M/8, 256, 0, s1>>>(xd, dec_ln_g, dec_ln_b, x2d);
        launch_gemm(x2d, w, bb, nullptr, qkvd, M, 3*D, D, false, s1);
        attn_mma<<<attnGrid, 128, ATTN_SMEM, s1>>>(qkvd, 3*D, qkvd + D, qkvd + 2*D, 3*D, ctxd, tgt, 1);
        launch_gemm(ctxd, w + 3*WSZ, bb + 3*D, xd, xd, M, D, D, false, s1);
        ln_kernel<<<M/8, 256, 0, s1>>>(xd, dec_ln_g + (size_t)1*D, dec_ln_b + (size_t)1*D, x2d);
    }
    if (par) cudaEventRecord(g_sc.dec0, s1);

    // ----- s0: encoder-side cvt + embed + encoder -----
    cvt_kernel<<<(NLAYER*4*DMODEL*DMODEL)/2048, 256, 0, s0>>>(enc_attn_w, wv + OFF_ENC_ATTN, NLAYER*4*DMODEL*DMODEL);
    cvt_kernel<<<(NLAYER*DFF*DMODEL)/2048,      256, 0, s0>>>(enc_w1,     wv + OFF_ENC_W1,   NLAYER*DFF*DMODEL);
    cvt_kernel<<<(NLAYER*DMODEL*DFF)/2048,      256, 0, s0>>>(enc_w2,     wv + OFF_ENC_W2,   NLAYER*DMODEL*DFF);
    embed_kernel<<<M, 128, 0, s0>>>(src, emb, x);
    for (int l = 0; l < NLAYER; l++) {
        const __half* w  = ew + (size_t)l*4*WSZ;
        const float*  bb = enc_attn_b + (size_t)l*4*D;
        ln_kernel<<<M/8, 256, 0, s0>>>(x, enc_ln_g + (size_t)(l*2+0)*D, enc_ln_b + (size_t)(l*2+0)*D, x2);
        launch_gemm(x2, w, bb, nullptr, qkv, M, 3*D, D, false, s0);
        attn_mma<<<attnGrid, 128, ATTN_SMEM, s0>>>(qkv, 3*D, qkv + D, qkv + 2*D, 3*D, ctx, src, 0);
        launch_gemm(ctx, w + 3*WSZ, bb + 3*D, x, x, M, D, D, false, s0);
        ln_kernel<<<M/8, 256, 0, s0>>>(x, enc_ln_g + (size_t)(l*2+1)*D, enc_ln_b + (size_t)(l*2+1)*D, x2);
        launch_gemm(x2, wv + OFF_ENC_W1 + (size_t)l*DFF*D, enc_b1 + (size_t)l*DFF, nullptr, hbuf, M, DFF, D, true, s0);
        launch_gemm(hbuf, wv + OFF_ENC_W2 + (size_t)l*D*DFF, enc_b2 + (size_t)l*D, x, x, M, D, DFF, false, s0);
    }
    ln_kernel<<<M/8, 256, 0, s0>>>(x, enc_norm_g, enc_norm_b, enc);
    if (par) cudaEventRecord(g_sc.enc, s0);

    // ----- s1: cross-KV projections for all layers (need enc) -----
    if (par) cudaStreamWaitEvent(s1, g_sc.enc, 0);
    for (int l = 0; l < NLAYER; l++) {
        const __half* w  = dw + (size_t)l*8*WSZ;
        const float*  bb = dec_attn_b + (size_t)l*8*D;
        launch_gemm(enc, w + 5*WSZ, bb + 5*D, nullptr, kvb[l], M, 2*D, D, false, s1);
        if (par) cudaEventRecord(g_sc.kv[l], s1);
    }

    // ----- s0: decoder -----
    if (par) cudaStreamWaitEvent(s0, g_sc.dec0, 0);
    for (int l = 0; l < NLAYER; l++) {
        const __half* w  = dw + (size_t)l*8*WSZ;
        const float*  bb = dec_attn_b + (size_t)l*8*D;
        if (l > 0) {
            // self-attention block (layer 0's was done on s1)
            ln_kernel<<<M/8, 256, 0, s0>>>(xd, dec_ln_g + (size_t)(l*3+0)*D, dec_ln_b + (size_t)(l*3+0)*D, x2d);
            launch_gemm(x2d, w, bb, nullptr, qkvd, M, 3*D, D, false, s0);
            attn_mma<<<attnGrid, 128, ATTN_SMEM, s0>>>(qkvd, 3*D, qkvd + D, qkvd + 2*D, 3*D, ctxd, tgt, 1);
            launch_gemm(ctxd, w + 3*WSZ, bb + 3*D, xd, xd, M, D, D, false, s0);
            ln_kernel<<<M/8, 256, 0, s0>>>(xd, dec_ln_g + (size_t)(l*3+1)*D, dec_ln_b + (size_t)(l*3+1)*D, x2d);
        }
        // cross-attention
        launch_gemm(x2d, w + 4*WSZ, bb + 4*D, nullptr, qb, M, D, D, false, s0);
        if (par) cudaStreamWaitEvent(s0, g_sc.kv[l], 0);
        attn_mma<<<attnGrid, 128, ATTN_SMEM, s0>>>(qb, D, kvb[l], kvb[l] + D, 2*D, ctxd, src, 0);
        launch_gemm(ctxd, w + 7*WSZ, bb + 7*D, xd, xd, M, D, D, false, s0);
        // FFN
        ln_kernel<<<M/8, 256, 0, s0>>>(xd, dec_ln_g + (size_t)(l*3+2)*D, dec_ln_b + (size_t)(l*3+2)*D, x2d);
        launch_gemm(x2d, wv + OFF_DEC_W1 + (size_t)l*DFF*D, dec_b1 + (size_t)l*DFF, nullptr, hbuf, M, DFF, D, true, s0);
        launch_gemm(hbuf, wv + OFF_DEC_W2 + (size_t)l*D*DFF, dec_b2 + (size_t)l*D, xd, xd, M, D, DFF, false, s0);
    }
    ln_kernel<<<M/8, 256, 0, s0>>>(xd, dec_norm_g, dec_norm_b, x2d);

    // ----- tied output projection -----
    launch_gemm(x2d, wv + OFF_EMB, nullptr, nullptr, (float*)d_out, M, VOCAB, D, false, s0);
}